// round 1
// baseline (speedup 1.0000x reference)
#include <cuda_runtime.h>
#include <math.h>

// Problem constants
#define CL   12
#define CD   768
#define CH   12
#define CF   3072
#define CB   8
#define CS   784
#define CHD  64
#define CBS  (CB*CS)          // 6272 rows
#define CEPS 1e-6f

// ---------------------------------------------------------------------------
// Scratch (device globals; no allocations allowed)
// ---------------------------------------------------------------------------
__device__ float g_h  [CBS*CD];
__device__ float g_y  [CBS*CD];
__device__ float g_q  [CBS*CD];
__device__ float g_k  [CBS*CD];
__device__ float g_v  [CBS*CD];
__device__ float g_ctx[CBS*CD];
__device__ float g_mlp[CBS*CF];
__device__ float g_sc [(size_t)CB*CH*CS*CS];   // 59M floats, 236 MB

// ---------------------------------------------------------------------------
// Block reductions (256 threads)
// ---------------------------------------------------------------------------
__device__ __forceinline__ float bsum(float v) {
    __shared__ float red[32];
    #pragma unroll
    for (int o = 16; o; o >>= 1) v += __shfl_xor_sync(0xffffffffu, v, o);
    if ((threadIdx.x & 31) == 0) red[threadIdx.x >> 5] = v;
    __syncthreads();
    float t = (threadIdx.x < (blockDim.x >> 5)) ? red[threadIdx.x] : 0.0f;
    if (threadIdx.x < 32) {
        #pragma unroll
        for (int o = 16; o; o >>= 1) t += __shfl_xor_sync(0xffffffffu, t, o);
        if (threadIdx.x == 0) red[0] = t;
    }
    __syncthreads();
    float r = red[0];
    __syncthreads();
    return r;
}

__device__ __forceinline__ float bmax(float v) {
    __shared__ float red[32];
    #pragma unroll
    for (int o = 16; o; o >>= 1) v = fmaxf(v, __shfl_xor_sync(0xffffffffu, v, o));
    if ((threadIdx.x & 31) == 0) red[threadIdx.x >> 5] = v;
    __syncthreads();
    float t = (threadIdx.x < (blockDim.x >> 5)) ? red[threadIdx.x] : -1e30f;
    if (threadIdx.x < 32) {
        #pragma unroll
        for (int o = 16; o; o >>= 1) t = fmaxf(t, __shfl_xor_sync(0xffffffffu, t, o));
        if (threadIdx.x == 0) red[0] = t;
    }
    __syncthreads();
    float r = red[0];
    __syncthreads();
    return r;
}

// ---------------------------------------------------------------------------
// LayerNorm: one block per row of 768 (3 elems/thread at 256 threads)
// ---------------------------------------------------------------------------
__global__ void __launch_bounds__(256) ln_kernel(
    const float* __restrict__ in, float* __restrict__ out,
    const float* __restrict__ gs, const float* __restrict__ gb)
{
    int tid = threadIdx.x;
    const float* x = in  + (size_t)blockIdx.x * CD;
    float*       o = out + (size_t)blockIdx.x * CD;
    float v0 = x[tid], v1 = x[tid + 256], v2 = x[tid + 512];
    float mean = bsum(v0 + v1 + v2) * (1.0f / CD);
    float c0 = v0 - mean, c1 = v1 - mean, c2 = v2 - mean;
    float var = bsum(c0*c0 + c1*c1 + c2*c2) * (1.0f / CD);
    float r = rsqrtf(var + CEPS);
    o[tid]       = c0 * r * gs[tid]       + gb[tid];
    o[tid + 256] = c1 * r * gs[tid + 256] + gb[tid + 256];
    o[tid + 512] = c2 * r * gs[tid + 512] + gb[tid + 512];
}

// ---------------------------------------------------------------------------
// Generic projection GEMM: C[M,N] = A[M,K] @ W[K,N] + bias (+gelu) (+residual)
// Tiles: 128x128x8, 256 threads, 8x8 per thread. M,N,K all multiples required
// (M=6272=49*128, N in {768,3072}, K in {768,3072}) -> no bounds checks.
// ---------------------------------------------------------------------------
template<bool GELU, bool RES>
__global__ void __launch_bounds__(256) gemm_kernel(
    const float* __restrict__ A, const float* __restrict__ W,
    const float* __restrict__ bias, const float* __restrict__ R,
    float* __restrict__ C, int N, int K)
{
    __shared__ float As[8][128];
    __shared__ float Bs[8][128];

    int tid = threadIdx.x;
    int bm = blockIdx.y * 128;
    int bn = blockIdx.x * 128;

    int arow = tid >> 1;            // 0..127
    int acol = (tid & 1) << 2;      // 0 or 4
    int brow = tid >> 5;            // 0..7
    int bcol = (tid & 31) << 2;     // 0..124

    const float* Aptr = A + (size_t)(bm + arow) * K + acol;
    const float* Wptr = W + (size_t)brow * N + bn + bcol;

    float acc[8][8];
    #pragma unroll
    for (int i = 0; i < 8; i++)
        #pragma unroll
        for (int j = 0; j < 8; j++) acc[i][j] = 0.0f;

    int tx = tid & 15, ty = tid >> 4;

    for (int k0 = 0; k0 < K; k0 += 8) {
        float4 a4 = *(const float4*)(Aptr + k0);
        As[acol + 0][arow] = a4.x;
        As[acol + 1][arow] = a4.y;
        As[acol + 2][arow] = a4.z;
        As[acol + 3][arow] = a4.w;
        float4 b4 = *(const float4*)(Wptr + (size_t)k0 * N);
        *(float4*)&Bs[brow][bcol] = b4;
        __syncthreads();

        #pragma unroll
        for (int kk = 0; kk < 8; kk++) {
            float ar[8], br[8];
            *(float4*)&ar[0] = *(const float4*)&As[kk][ty * 8];
            *(float4*)&ar[4] = *(const float4*)&As[kk][ty * 8 + 4];
            *(float4*)&br[0] = *(const float4*)&Bs[kk][tx * 8];
            *(float4*)&br[4] = *(const float4*)&Bs[kk][tx * 8 + 4];
            #pragma unroll
            for (int i = 0; i < 8; i++)
                #pragma unroll
                for (int j = 0; j < 8; j++)
                    acc[i][j] = fmaf(ar[i], br[j], acc[i][j]);
        }
        __syncthreads();
    }

    #pragma unroll
    for (int i = 0; i < 8; i++) {
        int gm = bm + ty * 8 + i;
        #pragma unroll
        for (int j = 0; j < 8; j++) {
            int gn = bn + tx * 8 + j;
            float c = acc[i][j] + bias[gn];
            if (GELU) c = 0.5f * c * (1.0f + erff(c * 0.70710678118654752f));
            if (RES)  c += R[(size_t)gm * N + gn];
            C[(size_t)gm * N + gn] = c;
        }
    }
}

// ---------------------------------------------------------------------------
// Attention scores: sc[b,h,s,t] = scale * sum_d q[b,s,h,d] * k[b,t,h,d]
// Block = 64x64 output tile; K dim (64) fully in smem. 4x4 per thread,
// lane-stride-16 mapping for conflict-free LDS.
// ---------------------------------------------------------------------------
__global__ void __launch_bounds__(256) attn_scores(
    const float* __restrict__ q, const float* __restrict__ k,
    float* __restrict__ sc)
{
    __shared__ float Qs[64][65];
    __shared__ float Ks[64][65];

    int bh = blockIdx.z;
    int b = bh / CH, h = bh % CH;
    int s0 = blockIdx.y * 64, t0 = blockIdx.x * 64;
    int tid = threadIdx.x;
    int lrow = tid >> 4;            // 0..15
    int ld4  = (tid & 15) << 2;     // 0..60

    const float* qb = q + (size_t)b * CS * CD + h * CHD;
    const float* kb = k + (size_t)b * CS * CD + h * CHD;

    #pragma unroll
    for (int it = 0; it < 4; it++) {
        int row = lrow + it * 16;
        float4 qa = (s0 + row < CS)
            ? *(const float4*)(qb + (size_t)(s0 + row) * CD + ld4)
            : make_float4(0.f, 0.f, 0.f, 0.f);
        Qs[row][ld4 + 0] = qa.x; Qs[row][ld4 + 1] = qa.y;
        Qs[row][ld4 + 2] = qa.z; Qs[row][ld4 + 3] = qa.w;
        float4 ka = (t0 + row < CS)
            ? *(const float4*)(kb + (size_t)(t0 + row) * CD + ld4)
            : make_float4(0.f, 0.f, 0.f, 0.f);
        Ks[row][ld4 + 0] = ka.x; Ks[row][ld4 + 1] = ka.y;
        Ks[row][ld4 + 2] = ka.z; Ks[row][ld4 + 3] = ka.w;
    }
    __syncthreads();

    int tx = tid & 15, ty = tid >> 4;
    float acc[4][4];
    #pragma unroll
    for (int i = 0; i < 4; i++)
        #pragma unroll
        for (int j = 0; j < 4; j++) acc[i][j] = 0.0f;

    #pragma unroll 8
    for (int d = 0; d < 64; d++) {
        float ar[4], br[4];
        #pragma unroll
        for (int i = 0; i < 4; i++) ar[i] = Qs[ty + 16 * i][d];
        #pragma unroll
        for (int j = 0; j < 4; j++) br[j] = Ks[tx + 16 * j][d];
        #pragma unroll
        for (int i = 0; i < 4; i++)
            #pragma unroll
            for (int j = 0; j < 4; j++)
                acc[i][j] = fmaf(ar[i], br[j], acc[i][j]);
    }

    const float scale = 0.125f;   // 1/sqrt(64)
    #pragma unroll
    for (int i = 0; i < 4; i++) {
        int s = s0 + ty + 16 * i;
        if (s >= CS) continue;
        #pragma unroll
        for (int j = 0; j < 4; j++) {
            int t = t0 + tx + 16 * j;
            if (t < CS)
                sc[((size_t)bh * CS + s) * CS + t] = acc[i][j] * scale;
        }
    }
}

// ---------------------------------------------------------------------------
// Row softmax over length 784 (one block of 256 per row), in place
// ---------------------------------------------------------------------------
__global__ void __launch_bounds__(256) softmax_rows(float* __restrict__ sc)
{
    float* row = sc + (size_t)blockIdx.x * CS;
    int tid = threadIdx.x;
    float m = -1e30f;
    for (int i = tid; i < CS; i += 256) m = fmaxf(m, row[i]);
    m = bmax(m);
    float sum = 0.0f;
    for (int i = tid; i < CS; i += 256) {
        float e = __expf(row[i] - m);
        row[i] = e;
        sum += e;
    }
    sum = bsum(sum);
    float inv = 1.0f / sum;
    for (int i = tid; i < CS; i += 256) row[i] *= inv;
}

// ---------------------------------------------------------------------------
// Context: ctx[b,s,h,d] = sum_t P[b,h,s,t] * v[b,t,h,d]
// Block = 64 rows x 64 (=HD) cols; K (t) tiles of 64 with zero-fill padding.
// ---------------------------------------------------------------------------
__global__ void __launch_bounds__(256) attn_ctx(
    const float* __restrict__ p, const float* __restrict__ v,
    float* __restrict__ ctx)
{
    __shared__ float Ps[64][65];
    __shared__ float Vs[64][65];

    int bh = blockIdx.y;
    int b = bh / CH, h = bh % CH;
    int s0 = blockIdx.x * 64;
    int tid = threadIdx.x;
    int lrow = tid >> 4;
    int lc4  = (tid & 15) << 2;
    int tx = tid & 15, ty = tid >> 4;

    const float* pb = p + (size_t)bh * CS * CS;
    const float* vb = v + (size_t)b * CS * CD + h * CHD;

    float acc[4][4];
    #pragma unroll
    for (int i = 0; i < 4; i++)
        #pragma unroll
        for (int j = 0; j < 4; j++) acc[i][j] = 0.0f;

    for (int t0 = 0; t0 < CS; t0 += 64) {
        #pragma unroll
        for (int it = 0; it < 4; it++) {
            int row = lrow + it * 16;
            float4 pa = (s0 + row < CS && t0 + lc4 < CS)
                ? *(const float4*)(pb + (size_t)(s0 + row) * CS + t0 + lc4)
                : make_float4(0.f, 0.f, 0.f, 0.f);
            Ps[row][lc4 + 0] = pa.x; Ps[row][lc4 + 1] = pa.y;
            Ps[row][lc4 + 2] = pa.z; Ps[row][lc4 + 3] = pa.w;
            float4 va = (t0 + row < CS)
                ? *(const float4*)(vb + (size_t)(t0 + row) * CD + lc4)
                : make_float4(0.f, 0.f, 0.f, 0.f);
            Vs[row][lc4 + 0] = va.x; Vs[row][lc4 + 1] = va.y;
            Vs[row][lc4 + 2] = va.z; Vs[row][lc4 + 3] = va.w;
        }
        __syncthreads();

        #pragma unroll 8
        for (int t = 0; t < 64; t++) {
            float ar[4], br[4];
            #pragma unroll
            for (int i = 0; i < 4; i++) ar[i] = Ps[ty + 16 * i][t];
            #pragma unroll
            for (int j = 0; j < 4; j++) br[j] = Vs[t][tx + 16 * j];
            #pragma unroll
            for (int i = 0; i < 4; i++)
                #pragma unroll
                for (int j = 0; j < 4; j++)
                    acc[i][j] = fmaf(ar[i], br[j], acc[i][j]);
        }
        __syncthreads();
    }

    #pragma unroll
    for (int i = 0; i < 4; i++) {
        int s = s0 + ty + 16 * i;
        if (s >= CS) continue;
        #pragma unroll
        for (int j = 0; j < 4; j++)
            ctx[((size_t)b * CS + s) * CD + h * CHD + tx + 16 * j] = acc[i][j];
    }
}

// ---------------------------------------------------------------------------
// Orchestration
// ---------------------------------------------------------------------------
extern "C" void kernel_launch(void* const* d_in, const int* in_sizes, int n_in,
                              void* d_out, int out_size)
{
    (void)in_sizes; (void)n_in; (void)out_size;

    const float* x     = (const float*)d_in[0];
    const float* ln1_s = (const float*)d_in[1];
    const float* ln1_b = (const float*)d_in[2];
    const float* wq    = (const float*)d_in[3];
    const float* bq    = (const float*)d_in[4];
    const float* wk    = (const float*)d_in[5];
    const float* bk    = (const float*)d_in[6];
    const float* wv    = (const float*)d_in[7];
    const float* bv    = (const float*)d_in[8];
    const float* wo    = (const float*)d_in[9];
    const float* bo    = (const float*)d_in[10];
    const float* ln2_s = (const float*)d_in[11];
    const float* ln2_b = (const float*)d_in[12];
    const float* w1    = (const float*)d_in[13];
    const float* b1    = (const float*)d_in[14];
    const float* w2    = (const float*)d_in[15];
    const float* b2    = (const float*)d_in[16];
    const float* lnf_s = (const float*)d_in[17];
    const float* lnf_b = (const float*)d_in[18];

    float *h, *y, *q, *k, *v, *ctx, *mlp, *sc;
    cudaGetSymbolAddress((void**)&h,   g_h);
    cudaGetSymbolAddress((void**)&y,   g_y);
    cudaGetSymbolAddress((void**)&q,   g_q);
    cudaGetSymbolAddress((void**)&k,   g_k);
    cudaGetSymbolAddress((void**)&v,   g_v);
    cudaGetSymbolAddress((void**)&ctx, g_ctx);
    cudaGetSymbolAddress((void**)&mlp, g_mlp);
    cudaGetSymbolAddress((void**)&sc,  g_sc);

    cudaMemcpyAsync(h, x, (size_t)CBS * CD * sizeof(float),
                    cudaMemcpyDeviceToDevice);

    dim3 blk(256);
    dim3 gp768(CD / 128, CBS / 128);    // (6, 49)
    dim3 gp3072(CF / 128, CBS / 128);   // (24, 49)
    dim3 gsc((CS + 63) / 64, (CS + 63) / 64, CB * CH);  // (13,13,96)
    dim3 gctx((CS + 63) / 64, CB * CH);                 // (13,96)

    for (int l = 0; l < CL; l++) {
        ln_kernel<<<CBS, blk>>>(h, y, ln1_s + l * CD, ln1_b + l * CD);
        gemm_kernel<false, false><<<gp768, blk>>>(
            y, wq + (size_t)l * CD * CD, bq + l * CD, nullptr, q, CD, CD);
        gemm_kernel<false, false><<<gp768, blk>>>(
            y, wk + (size_t)l * CD * CD, bk + l * CD, nullptr, k, CD, CD);
        gemm_kernel<false, false><<<gp768, blk>>>(
            y, wv + (size_t)l * CD * CD, bv + l * CD, nullptr, v, CD, CD);
        attn_scores<<<gsc, blk>>>(q, k, sc);
        softmax_rows<<<CB * CH * CS, blk>>>(sc);
        attn_ctx<<<gctx, blk>>>(sc, v, ctx);
        gemm_kernel<false, true><<<gp768, blk>>>(
            ctx, wo + (size_t)l * CD * CD, bo + l * CD, h, h, CD, CD);
        ln_kernel<<<CBS, blk>>>(h, y, ln2_s + l * CD, ln2_b + l * CD);
        gemm_kernel<true, false><<<gp3072, blk>>>(
            y, w1 + (size_t)l * CD * CF, b1 + l * CF, nullptr, mlp, CF, CD);
        gemm_kernel<false, true><<<gp768, blk>>>(
            mlp, w2 + (size_t)l * CF * CD, b2 + l * CD, h, h, CD, CF);
    }
    ln_kernel<<<CBS, blk>>>(h, (float*)d_out, lnf_s, lnf_b);
}

// round 4
// speedup vs baseline: 1.2056x; 1.2056x over previous
#include <cuda_runtime.h>
#include <math.h>
#include <stdint.h>

// Problem constants
#define CL   12
#define CD   768
#define CH   12
#define CF   3072
#define CB   8
#define CS   784
#define CHD  64
#define CBS  (CB*CS)          // 6272 rows
#define CEPS 1e-6f

// ---------------------------------------------------------------------------
// Scratch (device globals; no allocations allowed)
// ---------------------------------------------------------------------------
__device__ float g_h  [CBS*CD];
__device__ float g_y  [CBS*CD];
__device__ float g_q  [CBS*CD];
__device__ float g_k  [CBS*CD];
__device__ float g_v  [CBS*CD];
__device__ float g_ctx[CBS*CD];
__device__ float g_mlp[(size_t)CBS*CF];
__device__ float g_sc [(size_t)CB*CH*CS*CS];   // 236 MB

// ---------------------------------------------------------------------------
// TF32 helpers: 2-term split x = hi + lo (exact residual in fp32)
// ---------------------------------------------------------------------------
__device__ __forceinline__ uint32_t f2tf(float f) {
    uint32_t u;
    asm("cvt.rna.tf32.f32 %0, %1;" : "=r"(u) : "f"(f));
    return u;
}

__device__ __forceinline__ void split4(float4 v, uint4& h, uint4& l) {
    h.x = f2tf(v.x); l.x = f2tf(v.x - __uint_as_float(h.x));
    h.y = f2tf(v.y); l.y = f2tf(v.y - __uint_as_float(h.y));
    h.z = f2tf(v.z); l.z = f2tf(v.z - __uint_as_float(h.z));
    h.w = f2tf(v.w); l.w = f2tf(v.w - __uint_as_float(h.w));
}

__device__ __forceinline__ void mma8(float* c, const uint32_t* a, const uint32_t* b) {
    asm("mma.sync.aligned.m16n8k8.row.col.f32.tf32.tf32.f32 "
        "{%0,%1,%2,%3},{%4,%5,%6,%7},{%8,%9},{%0,%1,%2,%3};"
        : "+f"(c[0]), "+f"(c[1]), "+f"(c[2]), "+f"(c[3])
        : "r"(a[0]), "r"(a[1]), "r"(a[2]), "r"(a[3]), "r"(b[0]), "r"(b[1]));
}

// ---------------------------------------------------------------------------
// Block reductions (256 threads)
// ---------------------------------------------------------------------------
__device__ __forceinline__ float bsum(float v) {
    __shared__ float red[32];
    #pragma unroll
    for (int o = 16; o; o >>= 1) v += __shfl_xor_sync(0xffffffffu, v, o);
    if ((threadIdx.x & 31) == 0) red[threadIdx.x >> 5] = v;
    __syncthreads();
    float t = (threadIdx.x < (blockDim.x >> 5)) ? red[threadIdx.x] : 0.0f;
    if (threadIdx.x < 32) {
        #pragma unroll
        for (int o = 16; o; o >>= 1) t += __shfl_xor_sync(0xffffffffu, t, o);
        if (threadIdx.x == 0) red[0] = t;
    }
    __syncthreads();
    float r = red[0];
    __syncthreads();
    return r;
}

__device__ __forceinline__ float bmax(float v) {
    __shared__ float red[32];
    #pragma unroll
    for (int o = 16; o; o >>= 1) v = fmaxf(v, __shfl_xor_sync(0xffffffffu, v, o));
    if ((threadIdx.x & 31) == 0) red[threadIdx.x >> 5] = v;
    __syncthreads();
    float t = (threadIdx.x < (blockDim.x >> 5)) ? red[threadIdx.x] : -1e30f;
    if (threadIdx.x < 32) {
        #pragma unroll
        for (int o = 16; o; o >>= 1) t = fmaxf(t, __shfl_xor_sync(0xffffffffu, t, o));
        if (threadIdx.x == 0) red[0] = t;
    }
    __syncthreads();
    float r = red[0];
    __syncthreads();
    return r;
}

// ---------------------------------------------------------------------------
// LayerNorm: one block per row of 768
// ---------------------------------------------------------------------------
__global__ void __launch_bounds__(256) ln_kernel(
    const float* __restrict__ in, float* __restrict__ out,
    const float* __restrict__ gs, const float* __restrict__ gb)
{
    int tid = threadIdx.x;
    const float* x = in  + (size_t)blockIdx.x * CD;
    float*       o = out + (size_t)blockIdx.x * CD;
    float v0 = x[tid], v1 = x[tid + 256], v2 = x[tid + 512];
    float mean = bsum(v0 + v1 + v2) * (1.0f / CD);
    float c0 = v0 - mean, c1 = v1 - mean, c2 = v2 - mean;
    float var = bsum(c0*c0 + c1*c1 + c2*c2) * (1.0f / CD);
    float r = rsqrtf(var + CEPS);
    o[tid]       = c0 * r * gs[tid]       + gb[tid];
    o[tid + 256] = c1 * r * gs[tid + 256] + gb[tid + 256];
    o[tid + 512] = c2 * r * gs[tid + 512] + gb[tid + 512];
}

// ---------------------------------------------------------------------------
// 2xTF32 projection GEMM: C = A[M,K] @ W[K,N] + bias (+gelu) (+residual)
// 128x128x16 block tile, 256 threads = 8 warps (2x4), warp tile 64x32.
// hi/lo tiles both in smem; 3 MMAs per fragment pair (hh, lh, hl).
// ---------------------------------------------------------------------------
#define KT  16
#define AST 20
#define BST 136

template<bool GELU, bool RES>
__global__ void __launch_bounds__(256) gemm_tf32x2(
    const float* __restrict__ A, const float* __restrict__ W,
    const float* __restrict__ bias, const float* __restrict__ R,
    float* __restrict__ C, int N, int K)
{
    __shared__ uint32_t AsH[128 * AST];
    __shared__ uint32_t AsL[128 * AST];
    __shared__ uint32_t BsH[KT * BST];
    __shared__ uint32_t BsL[KT * BST];

    int tid  = threadIdx.x;
    int bm   = blockIdx.y * 128, bn = blockIdx.x * 128;
    int lane = tid & 31, wid = tid >> 5;
    int wm = (wid >> 2) * 64;     // 0 or 64
    int wn = (wid & 3) * 32;      // 0,32,64,96
    int lr = lane >> 2;           // 0..7
    int lc = lane & 3;            // 0..3

    const float* Ab = A + (size_t)bm * K;
    const float* Wb = W + bn;

    float4 pa[2], pb[2];
    #pragma unroll
    for (int i = 0; i < 2; i++) {
        int idx = tid + 256 * i;
        pa[i] = *(const float4*)(Ab + (size_t)(idx >> 2) * K + ((idx & 3) << 2));
        pb[i] = *(const float4*)(Wb + (size_t)(idx >> 5) * N + ((idx & 31) << 2));
    }

    float acc[4][4][4];
    #pragma unroll
    for (int mi = 0; mi < 4; mi++)
        #pragma unroll
        for (int ni = 0; ni < 4; ni++)
            #pragma unroll
            for (int e = 0; e < 4; e++) acc[mi][ni][e] = 0.0f;

    for (int k0 = 0;;) {
        #pragma unroll
        for (int i = 0; i < 2; i++) {
            int idx = tid + 256 * i;
            uint4 h, l;
            split4(pa[i], h, l);
            *(uint4*)&AsH[(idx >> 2) * AST + ((idx & 3) << 2)] = h;
            *(uint4*)&AsL[(idx >> 2) * AST + ((idx & 3) << 2)] = l;
            split4(pb[i], h, l);
            *(uint4*)&BsH[(idx >> 5) * BST + ((idx & 31) << 2)] = h;
            *(uint4*)&BsL[(idx >> 5) * BST + ((idx & 31) << 2)] = l;
        }
        __syncthreads();

        int kn = k0 + KT;
        if (kn < K) {
            #pragma unroll
            for (int i = 0; i < 2; i++) {
                int idx = tid + 256 * i;
                pa[i] = *(const float4*)(Ab + (size_t)(idx >> 2) * K + kn + ((idx & 3) << 2));
                pb[i] = *(const float4*)(Wb + (size_t)(kn + (idx >> 5)) * N + ((idx & 31) << 2));
            }
        }

        #pragma unroll
        for (int ks = 0; ks < KT / 8; ks++) {
            int kk = ks * 8;
            uint32_t aH[4][4], aL[4][4], bH[4][2], bL[4][2];
            #pragma unroll
            for (int mi = 0; mi < 4; mi++) {
                int row = wm + mi * 16 + lr;
                aH[mi][0] = AsH[row * AST + kk + lc];
                aH[mi][1] = AsH[(row + 8) * AST + kk + lc];
                aH[mi][2] = AsH[row * AST + kk + lc + 4];
                aH[mi][3] = AsH[(row + 8) * AST + kk + lc + 4];
                aL[mi][0] = AsL[row * AST + kk + lc];
                aL[mi][1] = AsL[(row + 8) * AST + kk + lc];
                aL[mi][2] = AsL[row * AST + kk + lc + 4];
                aL[mi][3] = AsL[(row + 8) * AST + kk + lc + 4];
            }
            #pragma unroll
            for (int ni = 0; ni < 4; ni++) {
                int col = wn + ni * 8 + lr;
                bH[ni][0] = BsH[(kk + lc) * BST + col];
                bH[ni][1] = BsH[(kk + lc + 4) * BST + col];
                bL[ni][0] = BsL[(kk + lc) * BST + col];
                bL[ni][1] = BsL[(kk + lc + 4) * BST + col];
            }
            #pragma unroll
            for (int mi = 0; mi < 4; mi++)
                #pragma unroll
                for (int ni = 0; ni < 4; ni++) {
                    mma8(acc[mi][ni], aH[mi], bH[ni]);
                    mma8(acc[mi][ni], aL[mi], bH[ni]);
                    mma8(acc[mi][ni], aH[mi], bL[ni]);
                }
        }

        k0 = kn;
        if (k0 >= K) break;
        __syncthreads();
    }

    #pragma unroll
    for (int mi = 0; mi < 4; mi++) {
        int row0 = bm + wm + mi * 16 + lr;
        #pragma unroll
        for (int ni = 0; ni < 4; ni++) {
            int col0 = bn + wn + ni * 8 + (lc << 1);
            #pragma unroll
            for (int e = 0; e < 4; e++) {
                int row = row0 + (e >> 1) * 8;
                int col = col0 + (e & 1);
                float cv = acc[mi][ni][e] + bias[col];
                if (GELU) cv = 0.5f * cv * (1.0f + erff(cv * 0.70710678118654752f));
                if (RES)  cv += R[(size_t)row * N + col];
                C[(size_t)row * N + col] = cv;
            }
        }
    }
}

// ---------------------------------------------------------------------------
// 2xTF32 attention scores: sc[b,h,s,t] = 0.125 * sum_d q.k
// 64x64 tile, 128 threads = 4 warps (2x2), warp tile 32x32, d tiled at 32.
// ---------------------------------------------------------------------------
#define SQT 36

__global__ void __launch_bounds__(128) attn_scores_x2(
    const float* __restrict__ q, const float* __restrict__ k,
    float* __restrict__ sc)
{
    __shared__ uint32_t QsH[64 * SQT];
    __shared__ uint32_t QsL[64 * SQT];
    __shared__ uint32_t KsH[64 * SQT];
    __shared__ uint32_t KsL[64 * SQT];

    int bh = blockIdx.z, b = bh / CH, h = bh % CH;
    int s0 = blockIdx.y * 64, t0 = blockIdx.x * 64;
    int tid = threadIdx.x, lane = tid & 31, wid = tid >> 5;
    int wm = (wid >> 1) * 32, wn = (wid & 1) * 32;
    int lr = lane >> 2, lc = lane & 3;

    const float* qb = q + (size_t)b * CS * CD + h * CHD;
    const float* kb = k + (size_t)b * CS * CD + h * CHD;

    float acc[2][4][4];
    #pragma unroll
    for (int mi = 0; mi < 2; mi++)
        #pragma unroll
        for (int ni = 0; ni < 4; ni++)
            #pragma unroll
            for (int e = 0; e < 4; e++) acc[mi][ni][e] = 0.0f;

    for (int d0 = 0; d0 < CHD; d0 += 32) {
        #pragma unroll
        for (int i = 0; i < 4; i++) {
            int idx = tid + 128 * i;      // 0..511
            int row = idx >> 3;           // 0..63
            int c4  = (idx & 7) << 2;     // 0..28
            float4 qa = (s0 + row < CS)
                ? *(const float4*)(qb + (size_t)(s0 + row) * CD + d0 + c4)
                : make_float4(0.f, 0.f, 0.f, 0.f);
            uint4 hh, ll;
            split4(qa, hh, ll);
            *(uint4*)&QsH[row * SQT + c4] = hh;
            *(uint4*)&QsL[row * SQT + c4] = ll;
            float4 ka = (t0 + row < CS)
                ? *(const float4*)(kb + (size_t)(t0 + row) * CD + d0 + c4)
                : make_float4(0.f, 0.f, 0.f, 0.f);
            split4(ka, hh, ll);
            *(uint4*)&KsH[row * SQT + c4] = hh;
            *(uint4*)&KsL[row * SQT + c4] = ll;
        }
        __syncthreads();

        #pragma unroll
        for (int ks = 0; ks < 4; ks++) {
            int kk = ks * 8;
            uint32_t aH[2][4], aL[2][4], bH[4][2], bL[4][2];
            #pragma unroll
            for (int mi = 0; mi < 2; mi++) {
                int row = wm + mi * 16 + lr;
                aH[mi][0] = QsH[row * SQT + kk + lc];
                aH[mi][1] = QsH[(row + 8) * SQT + kk + lc];
                aH[mi][2] = QsH[row * SQT + kk + lc + 4];
                aH[mi][3] = QsH[(row + 8) * SQT + kk + lc + 4];
                aL[mi][0] = QsL[row * SQT + kk + lc];
                aL[mi][1] = QsL[(row + 8) * SQT + kk + lc];
                aL[mi][2] = QsL[row * SQT + kk + lc + 4];
                aL[mi][3] = QsL[(row + 8) * SQT + kk + lc + 4];
            }
            #pragma unroll
            for (int ni = 0; ni < 4; ni++) {
                int col = wn + ni * 8 + lr;
                bH[ni][0] = KsH[col * SQT + kk + lc];
                bH[ni][1] = KsH[col * SQT + kk + lc + 4];
                bL[ni][0] = KsL[col * SQT + kk + lc];
                bL[ni][1] = KsL[col * SQT + kk + lc + 4];
            }
            #pragma unroll
            for (int mi = 0; mi < 2; mi++)
                #pragma unroll
                for (int ni = 0; ni < 4; ni++) {
                    mma8(acc[mi][ni], aH[mi], bH[ni]);
                    mma8(acc[mi][ni], aL[mi], bH[ni]);
                    mma8(acc[mi][ni], aH[mi], bL[ni]);
                }
        }
        __syncthreads();
    }

    float* scb = sc + (size_t)bh * CS * CS;
    #pragma unroll
    for (int mi = 0; mi < 2; mi++) {
        #pragma unroll
        for (int ni = 0; ni < 4; ni++) {
            #pragma unroll
            for (int e = 0; e < 4; e++) {
                int s = s0 + wm + mi * 16 + lr + (e >> 1) * 8;
                int t = t0 + wn + ni * 8 + (lc << 1) + (e & 1);
                if (s < CS && t < CS)
                    scb[(size_t)s * CS + t] = acc[mi][ni][e] * 0.125f;
            }
        }
    }
}

// ---------------------------------------------------------------------------
// 2xTF32 context: ctx[b,s,h,d] = sum_t P[b,h,s,t] * v[b,t,h,d]
// 64(s) x 64(d) tile, 128 threads = 4 warps (2x2), warp tile 32x32,
// t tiled at 32. FIX vs R2/R3: 4 n-fragments (full 32 cols per warp).
// ---------------------------------------------------------------------------
#define PST 36
#define VSTR 72

__global__ void __launch_bounds__(128) attn_ctx_x2(
    const float* __restrict__ p, const float* __restrict__ v,
    float* __restrict__ ctx)
{
    __shared__ uint32_t PsH[64 * PST];
    __shared__ uint32_t PsL[64 * PST];
    __shared__ uint32_t VsH[32 * VSTR];
    __shared__ uint32_t VsL[32 * VSTR];

    int bh = blockIdx.y, b = bh / CH, h = bh % CH;
    int s0 = blockIdx.x * 64;
    int tid = threadIdx.x, lane = tid & 31, wid = tid >> 5;
    int wm = (wid >> 1) * 32, wn = (wid & 1) * 32;
    int lr = lane >> 2, lc = lane & 3;

    const float* pb = p + (size_t)bh * CS * CS;
    const float* vb = v + (size_t)b * CS * CD + h * CHD;

    float acc[2][4][4];
    #pragma unroll
    for (int mi = 0; mi < 2; mi++)
        #pragma unroll
        for (int ni = 0; ni < 4; ni++)
            #pragma unroll
            for (int e = 0; e < 4; e++) acc[mi][ni][e] = 0.0f;

    for (int t0 = 0; t0 < CS; t0 += 32) {
        #pragma unroll
        for (int i = 0; i < 4; i++) {
            int idx = tid + 128 * i;      // 0..511
            int prow = idx >> 3;          // 0..63
            int pc4  = (idx & 7) << 2;    // 0..28
            float4 pa = (s0 + prow < CS && t0 + pc4 < CS)
                ? *(const float4*)(pb + (size_t)(s0 + prow) * CS + t0 + pc4)
                : make_float4(0.f, 0.f, 0.f, 0.f);
            uint4 hh, ll;
            split4(pa, hh, ll);
            *(uint4*)&PsH[prow * PST + pc4] = hh;
            *(uint4*)&PsL[prow * PST + pc4] = ll;

            int vrow = idx >> 4;          // 0..31
            int vc4  = (idx & 15) << 2;   // 0..60
            float4 va = (t0 + vrow < CS)
                ? *(const float4*)(vb + (size_t)(t0 + vrow) * CD + vc4)
                : make_float4(0.f, 0.f, 0.f, 0.f);
            split4(va, hh, ll);
            *(uint4*)&VsH[vrow * VSTR + vc4] = hh;
            *(uint4*)&VsL[vrow * VSTR + vc4] = ll;
        }
        __syncthreads();

        #pragma unroll
        for (int ks = 0; ks < 4; ks++) {
            int kk = ks * 8;
            uint32_t aH[2][4], aL[2][4], bH[4][2], bL[4][2];
            #pragma unroll
            for (int mi = 0; mi < 2; mi++) {
                int row = wm + mi * 16 + lr;
                aH[mi][0] = PsH[row * PST + kk + lc];
                aH[mi][1] = PsH[(row + 8) * PST + kk + lc];
                aH[mi][2] = PsH[row * PST + kk + lc + 4];
                aH[mi][3] = PsH[(row + 8) * PST + kk + lc + 4];
                aL[mi][0] = PsL[row * PST + kk + lc];
                aL[mi][1] = PsL[(row + 8) * PST + kk + lc];
                aL[mi][2] = PsL[row * PST + kk + lc + 4];
                aL[mi][3] = PsL[(row + 8) * PST + kk + lc + 4];
            }
            #pragma unroll
            for (int ni = 0; ni < 4; ni++) {
                int col = wn + ni * 8 + lr;
                bH[ni][0] = VsH[(kk + lc) * VSTR + col];
                bH[ni][1] = VsH[(kk + lc + 4) * VSTR + col];
                bL[ni][0] = VsL[(kk + lc) * VSTR + col];
                bL[ni][1] = VsL[(kk + lc + 4) * VSTR + col];
            }
            #pragma unroll
            for (int mi = 0; mi < 2; mi++)
                #pragma unroll
                for (int ni = 0; ni < 4; ni++) {
                    mma8(acc[mi][ni], aH[mi], bH[ni]);
                    mma8(acc[mi][ni], aL[mi], bH[ni]);
                    mma8(acc[mi][ni], aH[mi], bL[ni]);
                }
        }
        __syncthreads();
    }

    #pragma unroll
    for (int mi = 0; mi < 2; mi++) {
        #pragma unroll
        for (int ni = 0; ni < 4; ni++) {
            #pragma unroll
            for (int e = 0; e < 4; e++) {
                int s = s0 + wm + mi * 16 + lr + (e >> 1) * 8;
                int d = wn + ni * 8 + (lc << 1) + (e & 1);
                if (s < CS)
                    ctx[((size_t)b * CS + s) * CD + h * CHD + d] = acc[mi][ni][e];
            }
        }
    }
}

// ---------------------------------------------------------------------------
// Row softmax over length 784 (one block of 256 per row), in place
// ---------------------------------------------------------------------------
__global__ void __launch_bounds__(256) softmax_rows(float* __restrict__ sc)
{
    float* row = sc + (size_t)blockIdx.x * CS;
    int tid = threadIdx.x;
    float m = -1e30f;
    for (int i = tid; i < CS; i += 256) m = fmaxf(m, row[i]);
    m = bmax(m);
    float sum = 0.0f;
    for (int i = tid; i < CS; i += 256) {
        float e = __expf(row[i] - m);
        row[i] = e;
        sum += e;
    }
    sum = bsum(sum);
    float inv = 1.0f / sum;
    for (int i = tid; i < CS; i += 256) row[i] *= inv;
}

// ---------------------------------------------------------------------------
// Orchestration
// ---------------------------------------------------------------------------
extern "C" void kernel_launch(void* const* d_in, const int* in_sizes, int n_in,
                              void* d_out, int out_size)
{
    (void)in_sizes; (void)n_in; (void)out_size;

    const float* x     = (const float*)d_in[0];
    const float* ln1_s = (const float*)d_in[1];
    const float* ln1_b = (const float*)d_in[2];
    const float* wq    = (const float*)d_in[3];
    const float* bq    = (const float*)d_in[4];
    const float* wk    = (const float*)d_in[5];
    const float* bk    = (const float*)d_in[6];
    const float* wv    = (const float*)d_in[7];
    const float* bv    = (const float*)d_in[8];
    const float* wo    = (const float*)d_in[9];
    const float* bo    = (const float*)d_in[10];
    const float* ln2_s = (const float*)d_in[11];
    const float* ln2_b = (const float*)d_in[12];
    const float* w1    = (const float*)d_in[13];
    const float* b1    = (const float*)d_in[14];
    const float* w2    = (const float*)d_in[15];
    const float* b2    = (const float*)d_in[16];
    const float* lnf_s = (const float*)d_in[17];
    const float* lnf_b = (const float*)d_in[18];

    float *h, *y, *q, *k, *v, *ctx, *mlp, *sc;
    cudaGetSymbolAddress((void**)&h,   g_h);
    cudaGetSymbolAddress((void**)&y,   g_y);
    cudaGetSymbolAddress((void**)&q,   g_q);
    cudaGetSymbolAddress((void**)&k,   g_k);
    cudaGetSymbolAddress((void**)&v,   g_v);
    cudaGetSymbolAddress((void**)&ctx, g_ctx);
    cudaGetSymbolAddress((void**)&mlp, g_mlp);
    cudaGetSymbolAddress((void**)&sc,  g_sc);

    cudaMemcpyAsync(h, x, (size_t)CBS * CD * sizeof(float),
                    cudaMemcpyDeviceToDevice);

    dim3 blk(256);
    dim3 blk128(128);
    dim3 gp768(CD / 128, CBS / 128);    // (6, 49)
    dim3 gp3072(CF / 128, CBS / 128);   // (24, 49)
    dim3 gsc((CS + 63) / 64, (CS + 63) / 64, CB * CH);  // (13,13,96)
    dim3 gctx((CS + 63) / 64, CB * CH);                 // (13,96)

    for (int l = 0; l < CL; l++) {
        ln_kernel<<<CBS, blk>>>(h, y, ln1_s + l * CD, ln1_b + l * CD);
        gemm_tf32x2<false, false><<<gp768, blk>>>(
            y, wq + (size_t)l * CD * CD, bq + l * CD, nullptr, q, CD, CD);
        gemm_tf32x2<false, false><<<gp768, blk>>>(
            y, wk + (size_t)l * CD * CD, bk + l * CD, nullptr, k, CD, CD);
        gemm_tf32x2<false, false><<<gp768, blk>>>(
            y, wv + (size_t)l * CD * CD, bv + l * CD, nullptr, v, CD, CD);
        attn_scores_x2<<<gsc, blk128>>>(q, k, sc);
        softmax_rows<<<CB * CH * CS, blk>>>(sc);
        attn_ctx_x2<<<gctx, blk128>>>(sc, v, ctx);
        gemm_tf32x2<false, true><<<gp768, blk>>>(
            ctx, wo + (size_t)l * CD * CD, bo + l * CD, h, h, CD, CD);
        ln_kernel<<<CBS, blk>>>(h, y, ln2_s + l * CD, ln2_b + l * CD);
        gemm_tf32x2<true, false><<<gp3072, blk>>>(
            y, w1 + (size_t)l * CD * CF, b1 + l * CF, nullptr, mlp, CF, CD);
        gemm_tf32x2<false, true><<<gp768, blk>>>(
            mlp, w2 + (size_t)l * CF * CD, b2 + l * CD, h, h, CD, CF);
    }
    ln_kernel<<<CBS, blk>>>(h, (float*)d_out, lnf_s, lnf_b);
}

// round 5
// speedup vs baseline: 1.4535x; 1.2056x over previous
#include <cuda_runtime.h>
#include <cuda_bf16.h>
#include <math.h>
#include <stdint.h>

// Problem constants
#define CL   12
#define CD   768
#define CH   12
#define CF   3072
#define CB   8
#define CS   784
#define CHD  64
#define CBS  (CB*CS)          // 6272 rows
#define CEPS 1e-6f

// ---------------------------------------------------------------------------
// Scratch (device globals; no allocations allowed)
// ---------------------------------------------------------------------------
__device__ float g_h  [CBS*CD];
__device__ float g_y  [CBS*CD];
__device__ float g_q  [CBS*CD];
__device__ float g_k  [CBS*CD];
__device__ float g_v  [CBS*CD];
__device__ float g_ctx[CBS*CD];
__device__ float g_mlp[(size_t)CBS*CF];
__device__ float g_sc [(size_t)CB*CH*CS*CS];   // 236 MB

// ---------------------------------------------------------------------------
// bf16 helpers
// ---------------------------------------------------------------------------
__device__ __forceinline__ uint32_t pack2(float a, float b) {
    __nv_bfloat162 t = __floats2bfloat162_rn(a, b);   // low = a, high = b
    return *reinterpret_cast<uint32_t*>(&t);
}
__device__ __forceinline__ float bf16f(float a) {
    return __bfloat162float(__float2bfloat16(a));
}

__device__ __forceinline__ void mma16(float* c, const uint32_t* a, const uint32_t* b) {
    asm("mma.sync.aligned.m16n8k16.row.col.f32.bf16.bf16.f32 "
        "{%0,%1,%2,%3},{%4,%5,%6,%7},{%8,%9},{%0,%1,%2,%3};"
        : "+f"(c[0]), "+f"(c[1]), "+f"(c[2]), "+f"(c[3])
        : "r"(a[0]), "r"(a[1]), "r"(a[2]), "r"(a[3]), "r"(b[0]), "r"(b[1]));
}

// ---------------------------------------------------------------------------
// TF32 helpers (attention path, unchanged from R4 — proven correct)
// ---------------------------------------------------------------------------
__device__ __forceinline__ uint32_t f2tf(float f) {
    uint32_t u;
    asm("cvt.rna.tf32.f32 %0, %1;" : "=r"(u) : "f"(f));
    return u;
}

__device__ __forceinline__ void split4(float4 v, uint4& h, uint4& l) {
    h.x = f2tf(v.x); l.x = f2tf(v.x - __uint_as_float(h.x));
    h.y = f2tf(v.y); l.y = f2tf(v.y - __uint_as_float(h.y));
    h.z = f2tf(v.z); l.z = f2tf(v.z - __uint_as_float(h.z));
    h.w = f2tf(v.w); l.w = f2tf(v.w - __uint_as_float(h.w));
}

__device__ __forceinline__ void mma8(float* c, const uint32_t* a, const uint32_t* b) {
    asm("mma.sync.aligned.m16n8k8.row.col.f32.tf32.tf32.f32 "
        "{%0,%1,%2,%3},{%4,%5,%6,%7},{%8,%9},{%0,%1,%2,%3};"
        : "+f"(c[0]), "+f"(c[1]), "+f"(c[2]), "+f"(c[3])
        : "r"(a[0]), "r"(a[1]), "r"(a[2]), "r"(a[3]), "r"(b[0]), "r"(b[1]));
}

// ---------------------------------------------------------------------------
// Block reductions (256 threads)
// ---------------------------------------------------------------------------
__device__ __forceinline__ float bsum(float v) {
    __shared__ float red[32];
    #pragma unroll
    for (int o = 16; o; o >>= 1) v += __shfl_xor_sync(0xffffffffu, v, o);
    if ((threadIdx.x & 31) == 0) red[threadIdx.x >> 5] = v;
    __syncthreads();
    float t = (threadIdx.x < (blockDim.x >> 5)) ? red[threadIdx.x] : 0.0f;
    if (threadIdx.x < 32) {
        #pragma unroll
        for (int o = 16; o; o >>= 1) t += __shfl_xor_sync(0xffffffffu, t, o);
        if (threadIdx.x == 0) red[0] = t;
    }
    __syncthreads();
    float r = red[0];
    __syncthreads();
    return r;
}

__device__ __forceinline__ float bmax(float v) {
    __shared__ float red[32];
    #pragma unroll
    for (int o = 16; o; o >>= 1) v = fmaxf(v, __shfl_xor_sync(0xffffffffu, v, o));
    if ((threadIdx.x & 31) == 0) red[threadIdx.x >> 5] = v;
    __syncthreads();
    float t = (threadIdx.x < (blockDim.x >> 5)) ? red[threadIdx.x] : -1e30f;
    if (threadIdx.x < 32) {
        #pragma unroll
        for (int o = 16; o; o >>= 1) t = fmaxf(t, __shfl_xor_sync(0xffffffffu, t, o));
        if (threadIdx.x == 0) red[0] = t;
    }
    __syncthreads();
    float r = red[0];
    __syncthreads();
    return r;
}

// ---------------------------------------------------------------------------
// LayerNorm: one block per row of 768
// ---------------------------------------------------------------------------
__global__ void __launch_bounds__(256) ln_kernel(
    const float* __restrict__ in, float* __restrict__ out,
    const float* __restrict__ gs, const float* __restrict__ gb)
{
    int tid = threadIdx.x;
    const float* x = in  + (size_t)blockIdx.x * CD;
    float*       o = out + (size_t)blockIdx.x * CD;
    float v0 = x[tid], v1 = x[tid + 256], v2 = x[tid + 512];
    float mean = bsum(v0 + v1 + v2) * (1.0f / CD);
    float c0 = v0 - mean, c1 = v1 - mean, c2 = v2 - mean;
    float var = bsum(c0*c0 + c1*c1 + c2*c2) * (1.0f / CD);
    float r = rsqrtf(var + CEPS);
    o[tid]       = c0 * r * gs[tid]       + gb[tid];
    o[tid + 256] = c1 * r * gs[tid + 256] + gb[tid + 256];
    o[tid + 512] = c2 * r * gs[tid + 512] + gb[tid + 512];
}

// ---------------------------------------------------------------------------
// 3-MMA bf16 projection GEMM: C = A[M,K] @ W[K,N] + bias (+gelu) (+residual)
// 128x128x32 block tile, 256 threads = 8 warps (2x4), warp tile 64x32.
// m16n8k16 bf16 MMA; hi/lo split tiles in smem (2 bf16 packed per word,
// pair along k). acc += hh + lh + hl (lo*lo dropped, ~2^-18 relative).
// Smem word layout: Xs[row_or_col][kpair], stride 20 (mod32=20) ->
// fragment loads conflict-free (verified: 20*lr + lc distinct banks).
// ---------------------------------------------------------------------------
#define KT   32
#define PST20 20

template<bool GELU, bool RES>
__global__ void __launch_bounds__(256) gemm_bf16x3(
    const float* __restrict__ A, const float* __restrict__ W,
    const float* __restrict__ bias, const float* __restrict__ R,
    float* __restrict__ C, int N, int K)
{
    __shared__ uint32_t AsH[128 * PST20];
    __shared__ uint32_t AsL[128 * PST20];
    __shared__ uint32_t BsH[128 * PST20];
    __shared__ uint32_t BsL[128 * PST20];

    int tid  = threadIdx.x;
    int bm   = blockIdx.y * 128, bn = blockIdx.x * 128;
    int lane = tid & 31, wid = tid >> 5;
    int wm = (wid >> 2) * 64;     // 0 or 64
    int wn = (wid & 3) * 32;      // 0,32,64,96
    int lr = lane >> 2;           // 0..7
    int lc = lane & 3;            // 0..3

    const float* Ab = A + (size_t)bm * K;
    const float* Wb = W + bn;

    // A fill mapping: row = tid>>1 (0..127), khalf = tid&1 (16 k each)
    int arow = tid >> 1, akh = tid & 1;
    // B fill mapping (2 units): kp = u&15, n0 = ((u>>4)&31)*4  -> STS conflict-free
    int bkp[2], bn0[2];
    #pragma unroll
    for (int i = 0; i < 2; i++) {
        int u = tid + 256 * i;
        bkp[i] = u & 15;
        bn0[i] = ((u >> 4) & 31) << 2;
    }

    float4 pa[4], pb[4];
    #pragma unroll
    for (int j = 0; j < 4; j++)
        pa[j] = *(const float4*)(Ab + (size_t)arow * K + akh * 16 + j * 4);
    #pragma unroll
    for (int i = 0; i < 2; i++) {
        pb[2*i]   = *(const float4*)(Wb + (size_t)(2*bkp[i])     * N + bn0[i]);
        pb[2*i+1] = *(const float4*)(Wb + (size_t)(2*bkp[i] + 1) * N + bn0[i]);
    }

    float acc[4][4][4];
    #pragma unroll
    for (int mi = 0; mi < 4; mi++)
        #pragma unroll
        for (int ni = 0; ni < 4; ni++)
            #pragma unroll
            for (int e = 0; e < 4; e++) acc[mi][ni][e] = 0.0f;

    for (int k0 = 0;;) {
        // --- commit prefetched tile (split + pack) ---
        {
            float fa[16];
            *(float4*)&fa[0]  = pa[0]; *(float4*)&fa[4]  = pa[1];
            *(float4*)&fa[8]  = pa[2]; *(float4*)&fa[12] = pa[3];
            uint32_t hw[8], lw[8];
            #pragma unroll
            for (int p = 0; p < 8; p++) {
                float x = fa[2*p], y = fa[2*p+1];
                float hx = bf16f(x), hy = bf16f(y);
                hw[p] = pack2(hx, hy);
                lw[p] = pack2(x - hx, y - hy);
            }
            int base = arow * PST20 + akh * 8;
            *(uint4*)&AsH[base]     = *(uint4*)&hw[0];
            *(uint4*)&AsH[base + 4] = *(uint4*)&hw[4];
            *(uint4*)&AsL[base]     = *(uint4*)&lw[0];
            *(uint4*)&AsL[base + 4] = *(uint4*)&lw[4];
        }
        #pragma unroll
        for (int i = 0; i < 2; i++) {
            float f0[4], f1[4];
            *(float4*)f0 = pb[2*i];
            *(float4*)f1 = pb[2*i+1];
            #pragma unroll
            for (int j = 0; j < 4; j++) {
                float h0 = bf16f(f0[j]), h1 = bf16f(f1[j]);
                int addr = (bn0[i] + j) * PST20 + bkp[i];
                BsH[addr] = pack2(h0, h1);                     // (k even, k odd)
                BsL[addr] = pack2(f0[j] - h0, f1[j] - h1);
            }
        }
        __syncthreads();

        int kn = k0 + KT;
        if (kn < K) {
            #pragma unroll
            for (int j = 0; j < 4; j++)
                pa[j] = *(const float4*)(Ab + (size_t)arow * K + kn + akh * 16 + j * 4);
            #pragma unroll
            for (int i = 0; i < 2; i++) {
                pb[2*i]   = *(const float4*)(Wb + (size_t)(kn + 2*bkp[i])     * N + bn0[i]);
                pb[2*i+1] = *(const float4*)(Wb + (size_t)(kn + 2*bkp[i] + 1) * N + bn0[i]);
            }
        }

        #pragma unroll
        for (int ks = 0; ks < 2; ks++) {        // two k16 steps per tile
            int kp0 = ks * 8;                   // k-pair offset
            uint32_t aH[4][4], aL[4][4], bH[4][2], bL[4][2];
            #pragma unroll
            for (int mi = 0; mi < 4; mi++) {
                int row = wm + mi * 16 + lr;
                aH[mi][0] = AsH[row * PST20 + kp0 + lc];
                aH[mi][1] = AsH[(row + 8) * PST20 + kp0 + lc];
                aH[mi][2] = AsH[row * PST20 + kp0 + lc + 4];
                aH[mi][3] = AsH[(row + 8) * PST20 + kp0 + lc + 4];
                aL[mi][0] = AsL[row * PST20 + kp0 + lc];
                aL[mi][1] = AsL[(row + 8) * PST20 + kp0 + lc];
                aL[mi][2] = AsL[row * PST20 + kp0 + lc + 4];
                aL[mi][3] = AsL[(row + 8) * PST20 + kp0 + lc + 4];
            }
            #pragma unroll
            for (int ni = 0; ni < 4; ni++) {
                int col = wn + ni * 8 + lr;
                bH[ni][0] = BsH[col * PST20 + kp0 + lc];
                bH[ni][1] = BsH[col * PST20 + kp0 + lc + 4];
                bL[ni][0] = BsL[col * PST20 + kp0 + lc];
                bL[ni][1] = BsL[col * PST20 + kp0 + lc + 4];
            }
            #pragma unroll
            for (int mi = 0; mi < 4; mi++)
                #pragma unroll
                for (int ni = 0; ni < 4; ni++) {
                    mma16(acc[mi][ni], aH[mi], bH[ni]);
                    mma16(acc[mi][ni], aL[mi], bH[ni]);
                    mma16(acc[mi][ni], aH[mi], bL[ni]);
                }
        }

        k0 = kn;
        if (k0 >= K) break;
        __syncthreads();
    }

    #pragma unroll
    for (int mi = 0; mi < 4; mi++) {
        int row0 = bm + wm + mi * 16 + lr;
        #pragma unroll
        for (int ni = 0; ni < 4; ni++) {
            int col0 = bn + wn + ni * 8 + (lc << 1);
            #pragma unroll
            for (int e = 0; e < 4; e++) {
                int row = row0 + (e >> 1) * 8;
                int col = col0 + (e & 1);
                float cv = acc[mi][ni][e] + bias[col];
                if (GELU) cv = 0.5f * cv * (1.0f + erff(cv * 0.70710678118654752f));
                if (RES)  cv += R[(size_t)row * N + col];
                C[(size_t)row * N + col] = cv;
            }
        }
    }
}

// ---------------------------------------------------------------------------
// 2xTF32 attention scores (unchanged, proven)
// ---------------------------------------------------------------------------
#define SQT 36

__global__ void __launch_bounds__(128) attn_scores_x2(
    const float* __restrict__ q, const float* __restrict__ k,
    float* __restrict__ sc)
{
    __shared__ uint32_t QsH[64 * SQT];
    __shared__ uint32_t QsL[64 * SQT];
    __shared__ uint32_t KsH[64 * SQT];
    __shared__ uint32_t KsL[64 * SQT];

    int bh = blockIdx.z, b = bh / CH, h = bh % CH;
    int s0 = blockIdx.y * 64, t0 = blockIdx.x * 64;
    int tid = threadIdx.x, lane = tid & 31, wid = tid >> 5;
    int wm = (wid >> 1) * 32, wn = (wid & 1) * 32;
    int lr = lane >> 2, lc = lane & 3;

    const float* qb = q + (size_t)b * CS * CD + h * CHD;
    const float* kb = k + (size_t)b * CS * CD + h * CHD;

    float acc[2][4][4];
    #pragma unroll
    for (int mi = 0; mi < 2; mi++)
        #pragma unroll
        for (int ni = 0; ni < 4; ni++)
            #pragma unroll
            for (int e = 0; e < 4; e++) acc[mi][ni][e] = 0.0f;

    for (int d0 = 0; d0 < CHD; d0 += 32) {
        #pragma unroll
        for (int i = 0; i < 4; i++) {
            int idx = tid + 128 * i;
            int row = idx >> 3;
            int c4  = (idx & 7) << 2;
            float4 qa = (s0 + row < CS)
                ? *(const float4*)(qb + (size_t)(s0 + row) * CD + d0 + c4)
                : make_float4(0.f, 0.f, 0.f, 0.f);
            uint4 hh, ll;
            split4(qa, hh, ll);
            *(uint4*)&QsH[row * SQT + c4] = hh;
            *(uint4*)&QsL[row * SQT + c4] = ll;
            float4 ka = (t0 + row < CS)
                ? *(const float4*)(kb + (size_t)(t0 + row) * CD + d0 + c4)
                : make_float4(0.f, 0.f, 0.f, 0.f);
            split4(ka, hh, ll);
            *(uint4*)&KsH[row * SQT + c4] = hh;
            *(uint4*)&KsL[row * SQT + c4] = ll;
        }
        __syncthreads();

        #pragma unroll
        for (int ks = 0; ks < 4; ks++) {
            int kk = ks * 8;
            uint32_t aH[2][4], aL[2][4], bH[4][2], bL[4][2];
            #pragma unroll
            for (int mi = 0; mi < 2; mi++) {
                int row = wm + mi * 16 + lr;
                aH[mi][0] = QsH[row * SQT + kk + lc];
                aH[mi][1] = QsH[(row + 8) * SQT + kk + lc];
                aH[mi][2] = QsH[row * SQT + kk + lc + 4];
                aH[mi][3] = QsH[(row + 8) * SQT + kk + lc + 4];
                aL[mi][0] = QsL[row * SQT + kk + lc];
                aL[mi][1] = QsL[(row + 8) * SQT + kk + lc];
                aL[mi][2] = QsL[row * SQT + kk + lc + 4];
                aL[mi][3] = QsL[(row + 8) * SQT + kk + lc + 4];
            }
            #pragma unroll
            for (int ni = 0; ni < 4; ni++) {
                int col = wn + ni * 8 + lr;
                bH[ni][0] = KsH[col * SQT + kk + lc];
                bH[ni][1] = KsH[col * SQT + kk + lc + 4];
                bL[ni][0] = KsL[col * SQT + kk + lc];
                bL[ni][1] = KsL[col * SQT + kk + lc + 4];
            }
            #pragma unroll
            for (int mi = 0; mi < 2; mi++)
                #pragma unroll
                for (int ni = 0; ni < 4; ni++) {
                    mma8(acc[mi][ni], aH[mi], bH[ni]);
                    mma8(acc[mi][ni], aL[mi], bH[ni]);
                    mma8(acc[mi][ni], aH[mi], bL[ni]);
                }
        }
        __syncthreads();
    }

    float* scb = sc + (size_t)bh * CS * CS;
    #pragma unroll
    for (int mi = 0; mi < 2; mi++) {
        #pragma unroll
        for (int ni = 0; ni < 4; ni++) {
            #pragma unroll
            for (int e = 0; e < 4; e++) {
                int s = s0 + wm + mi * 16 + lr + (e >> 1) * 8;
                int t = t0 + wn + ni * 8 + (lc << 1) + (e & 1);
                if (s < CS && t < CS)
                    scb[(size_t)s * CS + t] = acc[mi][ni][e] * 0.125f;
            }
        }
    }
}

// ---------------------------------------------------------------------------
// 2xTF32 context (unchanged, fixed in R4)
// ---------------------------------------------------------------------------
#define PST 36
#define VSTR 72

__global__ void __launch_bounds__(128) attn_ctx_x2(
    const float* __restrict__ p, const float* __restrict__ v,
    float* __restrict__ ctx)
{
    __shared__ uint32_t PsH[64 * PST];
    __shared__ uint32_t PsL[64 * PST];
    __shared__ uint32_t VsH[32 * VSTR];
    __shared__ uint32_t VsL[32 * VSTR];

    int bh = blockIdx.y, b = bh / CH, h = bh % CH;
    int s0 = blockIdx.x * 64;
    int tid = threadIdx.x, lane = tid & 31, wid = tid >> 5;
    int wm = (wid >> 1) * 32, wn = (wid & 1) * 32;
    int lr = lane >> 2, lc = lane & 3;

    const float* pb = p + (size_t)bh * CS * CS;
    const float* vb = v + (size_t)b * CS * CD + h * CHD;

    float acc[2][4][4];
    #pragma unroll
    for (int mi = 0; mi < 2; mi++)
        #pragma unroll
        for (int ni = 0; ni < 4; ni++)
            #pragma unroll
            for (int e = 0; e < 4; e++) acc[mi][ni][e] = 0.0f;

    for (int t0 = 0; t0 < CS; t0 += 32) {
        #pragma unroll
        for (int i = 0; i < 4; i++) {
            int idx = tid + 128 * i;
            int prow = idx >> 3;
            int pc4  = (idx & 7) << 2;
            float4 pa = (s0 + prow < CS && t0 + pc4 < CS)
                ? *(const float4*)(pb + (size_t)(s0 + prow) * CS + t0 + pc4)
                : make_float4(0.f, 0.f, 0.f, 0.f);
            uint4 hh, ll;
            split4(pa, hh, ll);
            *(uint4*)&PsH[prow * PST + pc4] = hh;
            *(uint4*)&PsL[prow * PST + pc4] = ll;

            int vrow = idx >> 4;
            int vc4  = (idx & 15) << 2;
            float4 va = (t0 + vrow < CS)
                ? *(const float4*)(vb + (size_t)(t0 + vrow) * CD + vc4)
                : make_float4(0.f, 0.f, 0.f, 0.f);
            split4(va, hh, ll);
            *(uint4*)&VsH[vrow * VSTR + vc4] = hh;
            *(uint4*)&VsL[vrow * VSTR + vc4] = ll;
        }
        __syncthreads();

        #pragma unroll
        for (int ks = 0; ks < 4; ks++) {
            int kk = ks * 8;
            uint32_t aH[2][4], aL[2][4], bH[4][2], bL[4][2];
            #pragma unroll
            for (int mi = 0; mi < 2; mi++) {
                int row = wm + mi * 16 + lr;
                aH[mi][0] = PsH[row * PST + kk + lc];
                aH[mi][1] = PsH[(row + 8) * PST + kk + lc];
                aH[mi][2] = PsH[row * PST + kk + lc + 4];
                aH[mi][3] = PsH[(row + 8) * PST + kk + lc + 4];
                aL[mi][0] = PsL[row * PST + kk + lc];
                aL[mi][1] = PsL[(row + 8) * PST + kk + lc];
                aL[mi][2] = PsL[row * PST + kk + lc + 4];
                aL[mi][3] = PsL[(row + 8) * PST + kk + lc + 4];
            }
            #pragma unroll
            for (int ni = 0; ni < 4; ni++) {
                int col = wn + ni * 8 + lr;
                bH[ni][0] = VsH[(kk + lc) * VSTR + col];
                bH[ni][1] = VsH[(kk + lc + 4) * VSTR + col];
                bL[ni][0] = VsL[(kk + lc) * VSTR + col];
                bL[ni][1] = VsL[(kk + lc + 4) * VSTR + col];
            }
            #pragma unroll
            for (int mi = 0; mi < 2; mi++)
                #pragma unroll
                for (int ni = 0; ni < 4; ni++) {
                    mma8(acc[mi][ni], aH[mi], bH[ni]);
                    mma8(acc[mi][ni], aL[mi], bH[ni]);
                    mma8(acc[mi][ni], aH[mi], bL[ni]);
                }
        }
        __syncthreads();
    }

    #pragma unroll
    for (int mi = 0; mi < 2; mi++) {
        #pragma unroll
        for (int ni = 0; ni < 4; ni++) {
            #pragma unroll
            for (int e = 0; e < 4; e++) {
                int s = s0 + wm + mi * 16 + lr + (e >> 1) * 8;
                int d = wn + ni * 8 + (lc << 1) + (e & 1);
                if (s < CS)
                    ctx[((size_t)b * CS + s) * CD + h * CHD + d] = acc[mi][ni][e];
            }
        }
    }
}

// ---------------------------------------------------------------------------
// Row softmax over length 784 (one block of 256 per row), in place
// ---------------------------------------------------------------------------
__global__ void __launch_bounds__(256) softmax_rows(float* __restrict__ sc)
{
    float* row = sc + (size_t)blockIdx.x * CS;
    int tid = threadIdx.x;
    float m = -1e30f;
    for (int i = tid; i < CS; i += 256) m = fmaxf(m, row[i]);
    m = bmax(m);
    float sum = 0.0f;
    for (int i = tid; i < CS; i += 256) {
        float e = __expf(row[i] - m);
        row[i] = e;
        sum += e;
    }
    sum = bsum(sum);
    float inv = 1.0f / sum;
    for (int i = tid; i < CS; i += 256) row[i] *= inv;
}

// ---------------------------------------------------------------------------
// Orchestration
// ---------------------------------------------------------------------------
extern "C" void kernel_launch(void* const* d_in, const int* in_sizes, int n_in,
                              void* d_out, int out_size)
{
    (void)in_sizes; (void)n_in; (void)out_size;

    const float* x     = (const float*)d_in[0];
    const float* ln1_s = (const float*)d_in[1];
    const float* ln1_b = (const float*)d_in[2];
    const float* wq    = (const float*)d_in[3];
    const float* bq    = (const float*)d_in[4];
    const float* wk    = (const float*)d_in[5];
    const float* bk    = (const float*)d_in[6];
    const float* wv    = (const float*)d_in[7];
    const float* bv    = (const float*)d_in[8];
    const float* wo    = (const float*)d_in[9];
    const float* bo    = (const float*)d_in[10];
    const float* ln2_s = (const float*)d_in[11];
    const float* ln2_b = (const float*)d_in[12];
    const float* w1    = (const float*)d_in[13];
    const float* b1    = (const float*)d_in[14];
    const float* w2    = (const float*)d_in[15];
    const float* b2    = (const float*)d_in[16];
    const float* lnf_s = (const float*)d_in[17];
    const float* lnf_b = (const float*)d_in[18];

    float *h, *y, *q, *k, *v, *ctx, *mlp, *sc;
    cudaGetSymbolAddress((void**)&h,   g_h);
    cudaGetSymbolAddress((void**)&y,   g_y);
    cudaGetSymbolAddress((void**)&q,   g_q);
    cudaGetSymbolAddress((void**)&k,   g_k);
    cudaGetSymbolAddress((void**)&v,   g_v);
    cudaGetSymbolAddress((void**)&ctx, g_ctx);
    cudaGetSymbolAddress((void**)&mlp, g_mlp);
    cudaGetSymbolAddress((void**)&sc,  g_sc);

    cudaMemcpyAsync(h, x, (size_t)CBS * CD * sizeof(float),
                    cudaMemcpyDeviceToDevice);

    dim3 blk(256);
    dim3 blk128(128);
    dim3 gp768(CD / 128, CBS / 128);    // (6, 49)
    dim3 gp3072(CF / 128, CBS / 128);   // (24, 49)
    dim3 gsc((CS + 63) / 64, (CS + 63) / 64, CB * CH);  // (13,13,96)
    dim3 gctx((CS + 63) / 64, CB * CH);                 // (13,96)

    for (int l = 0; l < CL; l++) {
        ln_kernel<<<CBS, blk>>>(h, y, ln1_s + l * CD, ln1_b + l * CD);
        gemm_bf16x3<false, false><<<gp768, blk>>>(
            y, wq + (size_t)l * CD * CD, bq + l * CD, nullptr, q, CD, CD);
        gemm_bf16x3<false, false><<<gp768, blk>>>(
            y, wk + (size_t)l * CD * CD, bk + l * CD, nullptr, k, CD, CD);
        gemm_bf16x3<false, false><<<gp768, blk>>>(
            y, wv + (size_t)l * CD * CD, bv + l * CD, nullptr, v, CD, CD);
        attn_scores_x2<<<gsc, blk128>>>(q, k, sc);
        softmax_rows<<<CB * CH * CS, blk>>>(sc);
        attn_ctx_x2<<<gctx, blk128>>>(sc, v, ctx);
        gemm_bf16x3<false, true><<<gp768, blk>>>(
            ctx, wo + (size_t)l * CD * CD, bo + l * CD, h, h, CD, CD);
        ln_kernel<<<CBS, blk>>>(h, y, ln2_s + l * CD, ln2_b + l * CD);
        gemm_bf16x3<true, false><<<gp3072, blk>>>(
            y, w1 + (size_t)l * CD * CF, b1 + l * CF, nullptr, mlp, CF, CD);
        gemm_bf16x3<false, true><<<gp768, blk>>>(
            mlp, w2 + (size_t)l * CF * CD, b2 + l * CD, h, h, CD, CF);
    }
    ln_kernel<<<CBS, blk>>>(h, (float*)d_out, lnf_s, lnf_b);
}

// round 7
// speedup vs baseline: 1.8552x; 1.2764x over previous
#include <cuda_runtime.h>
#include <cuda_bf16.h>
#include <math.h>
#include <stdint.h>

// Problem constants
#define CL   12
#define CD   768
#define CH   12
#define CF   3072
#define CB   8
#define CS   784
#define CHD  64
#define CBS  (CB*CS)          // 6272 rows
#define CEPS 1e-6f

// ---------------------------------------------------------------------------
// Scratch (device globals; no allocations allowed)
// ---------------------------------------------------------------------------
__device__ float g_h  [CBS*CD];
__device__ float g_q  [CBS*CD];
__device__ float g_k  [CBS*CD];
__device__ float g_v  [CBS*CD];
__device__ float g_sc [(size_t)CB*CH*CS*CS];   // 236 MB

__device__ __nv_bfloat16 g_yh  [CBS*CD];
__device__ __nv_bfloat16 g_yl  [CBS*CD];
__device__ __nv_bfloat16 g_ctxh[CBS*CD];
__device__ __nv_bfloat16 g_ctxl[CBS*CD];
__device__ __nv_bfloat16 g_mlph[(size_t)CBS*CF];
__device__ __nv_bfloat16 g_mlpl[(size_t)CBS*CF];

// split+transposed weights: [L][N][K] bf16 hi/lo
__device__ __nv_bfloat16 g_wqth[CL*CD*CD], g_wqtl[CL*CD*CD];
__device__ __nv_bfloat16 g_wkth[CL*CD*CD], g_wktl[CL*CD*CD];
__device__ __nv_bfloat16 g_wvth[CL*CD*CD], g_wvtl[CL*CD*CD];
__device__ __nv_bfloat16 g_woth[CL*CD*CD], g_wotl[CL*CD*CD];
__device__ __nv_bfloat16 g_w1th[(size_t)CL*CD*CF], g_w1tl[(size_t)CL*CD*CF];
__device__ __nv_bfloat16 g_w2th[(size_t)CL*CD*CF], g_w2tl[(size_t)CL*CD*CF];

// ---------------------------------------------------------------------------
// helpers
// ---------------------------------------------------------------------------
__device__ __forceinline__ uint32_t smem_u32(const void* p) {
    return (uint32_t)__cvta_generic_to_shared(p);
}
__device__ __forceinline__ uint32_t pack2(float a, float b) {
    __nv_bfloat162 t = __floats2bfloat162_rn(a, b);
    return *reinterpret_cast<uint32_t*>(&t);
}
__device__ __forceinline__ float bf16f(float a) {
    return __bfloat162float(__float2bfloat16(a));
}

__device__ __forceinline__ void mma16(float* c, const uint32_t* a, const uint32_t* b) {
    asm("mma.sync.aligned.m16n8k16.row.col.f32.bf16.bf16.f32 "
        "{%0,%1,%2,%3},{%4,%5,%6,%7},{%8,%9},{%0,%1,%2,%3};"
        : "+f"(c[0]), "+f"(c[1]), "+f"(c[2]), "+f"(c[3])
        : "r"(a[0]), "r"(a[1]), "r"(a[2]), "r"(a[3]), "r"(b[0]), "r"(b[1]));
}

#define CP16(dst, src) \
    asm volatile("cp.async.cg.shared.global [%0], [%1], 16;" \
                 :: "r"(dst), "l"(src) : "memory")

// TF32 helpers (attention path — proven)
__device__ __forceinline__ uint32_t f2tf(float f) {
    uint32_t u;
    asm("cvt.rna.tf32.f32 %0, %1;" : "=r"(u) : "f"(f));
    return u;
}
__device__ __forceinline__ void split4(float4 v, uint4& h, uint4& l) {
    h.x = f2tf(v.x); l.x = f2tf(v.x - __uint_as_float(h.x));
    h.y = f2tf(v.y); l.y = f2tf(v.y - __uint_as_float(h.y));
    h.z = f2tf(v.z); l.z = f2tf(v.z - __uint_as_float(h.z));
    h.w = f2tf(v.w); l.w = f2tf(v.w - __uint_as_float(h.w));
}
__device__ __forceinline__ void mma8(float* c, const uint32_t* a, const uint32_t* b) {
    asm("mma.sync.aligned.m16n8k8.row.col.f32.tf32.tf32.f32 "
        "{%0,%1,%2,%3},{%4,%5,%6,%7},{%8,%9},{%0,%1,%2,%3};"
        : "+f"(c[0]), "+f"(c[1]), "+f"(c[2]), "+f"(c[3])
        : "r"(a[0]), "r"(a[1]), "r"(a[2]), "r"(a[3]), "r"(b[0]), "r"(b[1]));
}

// ---------------------------------------------------------------------------
// Block reductions
// ---------------------------------------------------------------------------
__device__ __forceinline__ float bsum(float v) {
    __shared__ float red[32];
    #pragma unroll
    for (int o = 16; o; o >>= 1) v += __shfl_xor_sync(0xffffffffu, v, o);
    if ((threadIdx.x & 31) == 0) red[threadIdx.x >> 5] = v;
    __syncthreads();
    float t = (threadIdx.x < (blockDim.x >> 5)) ? red[threadIdx.x] : 0.0f;
    if (threadIdx.x < 32) {
        #pragma unroll
        for (int o = 16; o; o >>= 1) t += __shfl_xor_sync(0xffffffffu, t, o);
        if (threadIdx.x == 0) red[0] = t;
    }
    __syncthreads();
    float r = red[0];
    __syncthreads();
    return r;
}
__device__ __forceinline__ float bmax(float v) {
    __shared__ float red[32];
    #pragma unroll
    for (int o = 16; o; o >>= 1) v = fmaxf(v, __shfl_xor_sync(0xffffffffu, v, o));
    if ((threadIdx.x & 31) == 0) red[threadIdx.x >> 5] = v;
    __syncthreads();
    float t = (threadIdx.x < (blockDim.x >> 5)) ? red[threadIdx.x] : -1e30f;
    if (threadIdx.x < 32) {
        #pragma unroll
        for (int o = 16; o; o >>= 1) t = fmaxf(t, __shfl_xor_sync(0xffffffffu, t, o));
        if (threadIdx.x == 0) red[0] = t;
    }
    __syncthreads();
    float r = red[0];
    __syncthreads();
    return r;
}

// ---------------------------------------------------------------------------
// Weight prep: transpose + bf16 hi/lo split. W:[L][K][N] -> T{h,l}:[L][N][K]
// ---------------------------------------------------------------------------
__global__ void __launch_bounds__(256) splitT_kernel(
    const float* __restrict__ W, __nv_bfloat16* __restrict__ Th,
    __nv_bfloat16* __restrict__ Tl, int K, int N)
{
    __shared__ float t[32][33];
    size_t lb = (size_t)blockIdx.z * K * N;
    const float* Wl = W + lb;
    __nv_bfloat16* Thl = Th + lb;
    __nv_bfloat16* Tll = Tl + lb;
    int n0 = blockIdx.x * 32, k0 = blockIdx.y * 32;
    int tx = threadIdx.x & 31, ty = threadIdx.x >> 5;
    #pragma unroll
    for (int r = 0; r < 32; r += 8)
        t[ty + r][tx] = Wl[(size_t)(k0 + ty + r) * N + n0 + tx];
    __syncthreads();
    #pragma unroll
    for (int r = 0; r < 32; r += 8) {
        float v = t[tx][ty + r];
        float hv = bf16f(v);
        size_t o = (size_t)(n0 + ty + r) * K + k0 + tx;
        Thl[o] = __float2bfloat16(hv);
        Tll[o] = __float2bfloat16(v - hv);
    }
}

// ---------------------------------------------------------------------------
// LayerNorm -> fp32 out (final)
// ---------------------------------------------------------------------------
__global__ void __launch_bounds__(256) ln_kernel(
    const float* __restrict__ in, float* __restrict__ out,
    const float* __restrict__ gs, const float* __restrict__ gb)
{
    int tid = threadIdx.x;
    const float* x = in  + (size_t)blockIdx.x * CD;
    float*       o = out + (size_t)blockIdx.x * CD;
    float v0 = x[tid], v1 = x[tid + 256], v2 = x[tid + 512];
    float mean = bsum(v0 + v1 + v2) * (1.0f / CD);
    float c0 = v0 - mean, c1 = v1 - mean, c2 = v2 - mean;
    float var = bsum(c0*c0 + c1*c1 + c2*c2) * (1.0f / CD);
    float r = rsqrtf(var + CEPS);
    o[tid]       = c0 * r * gs[tid]       + gb[tid];
    o[tid + 256] = c1 * r * gs[tid + 256] + gb[tid + 256];
    o[tid + 512] = c2 * r * gs[tid + 512] + gb[tid + 512];
}

// LayerNorm -> bf16 hi/lo
__global__ void __launch_bounds__(256) ln_split_kernel(
    const float* __restrict__ in,
    __nv_bfloat16* __restrict__ oh, __nv_bfloat16* __restrict__ ol,
    const float* __restrict__ gs, const float* __restrict__ gb)
{
    int tid = threadIdx.x;
    const float* x = in + (size_t)blockIdx.x * CD;
    size_t ob = (size_t)blockIdx.x * CD;
    float v0 = x[tid], v1 = x[tid + 256], v2 = x[tid + 512];
    float mean = bsum(v0 + v1 + v2) * (1.0f / CD);
    float c0 = v0 - mean, c1 = v1 - mean, c2 = v2 - mean;
    float var = bsum(c0*c0 + c1*c1 + c2*c2) * (1.0f / CD);
    float r = rsqrtf(var + CEPS);
    float y0 = c0 * r * gs[tid]       + gb[tid];
    float y1 = c1 * r * gs[tid + 256] + gb[tid + 256];
    float y2 = c2 * r * gs[tid + 512] + gb[tid + 512];
    float h0 = bf16f(y0), h1 = bf16f(y1), h2 = bf16f(y2);
    oh[ob + tid]       = __float2bfloat16(h0);
    oh[ob + tid + 256] = __float2bfloat16(h1);
    oh[ob + tid + 512] = __float2bfloat16(h2);
    ol[ob + tid]       = __float2bfloat16(y0 - h0);
    ol[ob + tid + 256] = __float2bfloat16(y1 - h1);
    ol[ob + tid + 512] = __float2bfloat16(y2 - h2);
}

// ---------------------------------------------------------------------------
// bf16x3 GEMM, pre-split inputs, cp.async pipeline: C = A @ B^T (+bias/gelu/res)
// A{h,l}: [M][K] bf16; B{h,l}: [N][K] bf16. Block 128x128, KT=32, 8 warps,
// warp tile 64x32, 2-stage cp.async double buffer, 2 CTAs/SM.
// smem/stage: 4 arrays x 128 rows x 20 words (80B; 64B data + 16B pad).
// ---------------------------------------------------------------------------
#define GSTAGE 40960
#define GSMEM  (2*GSTAGE)

template<int GELU_, int RES_, int SPLITOUT_>
__global__ void __launch_bounds__(256, 2) gemm_bf16p(
    const __nv_bfloat16* __restrict__ Ah, const __nv_bfloat16* __restrict__ Al,
    const __nv_bfloat16* __restrict__ Bh, const __nv_bfloat16* __restrict__ Bl,
    const float* __restrict__ bias, const float* __restrict__ R,
    float* __restrict__ C,
    __nv_bfloat16* __restrict__ Ch, __nv_bfloat16* __restrict__ Cl,
    int N, int K)
{
    extern __shared__ char smem[];
    const int tid = threadIdx.x, lane = tid & 31, wid = tid >> 5;
    const int bm = blockIdx.y * 128, bn = blockIdx.x * 128;
    const int wm = (wid >> 2) * 64, wn = (wid & 3) * 32;
    const int lr = lane >> 2, lc = lane & 3;
    const uint32_t sbase = smem_u32(smem);

    auto fill = [&](int kt, int s) {
        int k0 = kt << 5;
        uint32_t stg = sbase + s * GSTAGE;
        #pragma unroll
        for (int i = 0; i < 8; i++) {
            int idx = tid + 256 * i;
            int arr = idx >> 9;             // 0..3
            int c = idx & 511;
            int row = c >> 2, ch = c & 3;
            const __nv_bfloat16* g = (arr == 0) ? Ah : (arr == 1) ? Al
                                   : (arr == 2) ? Bh : Bl;
            int rb = (arr < 2) ? bm : bn;
            const __nv_bfloat16* src = g + (size_t)(rb + row) * K + k0 + ch * 8;
            uint32_t dst = stg + arr * 10240 + row * 80 + ch * 16;
            CP16(dst, src);
        }
        asm volatile("cp.async.commit_group;" ::: "memory");
    };

    float acc[4][4][4];
    #pragma unroll
    for (int mi = 0; mi < 4; mi++)
        #pragma unroll
        for (int ni = 0; ni < 4; ni++)
            #pragma unroll
            for (int e = 0; e < 4; e++) acc[mi][ni][e] = 0.0f;

    int NT = K >> 5;
    fill(0, 0);
    fill(1, 1);

    for (int kt = 0; kt < NT; kt++) {
        int s = kt & 1;
        asm volatile("cp.async.wait_group 1;" ::: "memory");
        __syncthreads();

        const uint32_t* AH = (const uint32_t*)(smem + s * GSTAGE);
        const uint32_t* AL = AH + 2560;
        const uint32_t* BH = AH + 5120;
        const uint32_t* BL = AH + 7680;

        #pragma unroll
        for (int ks = 0; ks < 2; ks++) {
            int kp0 = ks * 8;
            uint32_t aH[4][4], aL[4][4];
            #pragma unroll
            for (int mi = 0; mi < 4; mi++) {
                int r0 = (wm + mi * 16 + lr) * 20 + kp0 + lc;
                int r1 = r0 + 160;
                aH[mi][0] = AH[r0]; aH[mi][1] = AH[r1];
                aH[mi][2] = AH[r0 + 4]; aH[mi][3] = AH[r1 + 4];
                aL[mi][0] = AL[r0]; aL[mi][1] = AL[r1];
                aL[mi][2] = AL[r0 + 4]; aL[mi][3] = AL[r1 + 4];
            }
            #pragma unroll
            for (int ni = 0; ni < 4; ni++) {
                int cb = (wn + ni * 8 + lr) * 20 + kp0 + lc;
                uint32_t bH[2] = { BH[cb], BH[cb + 4] };
                uint32_t bL[2] = { BL[cb], BL[cb + 4] };
                #pragma unroll
                for (int mi = 0; mi < 4; mi++) {
                    mma16(acc[mi][ni], aH[mi], bH);
                    mma16(acc[mi][ni], aL[mi], bH);
                    mma16(acc[mi][ni], aH[mi], bL);
                }
            }
        }
        __syncthreads();
        if (kt + 2 < NT) fill(kt + 2, s);
    }

    // epilogue
    #pragma unroll
    for (int mi = 0; mi < 4; mi++) {
        int row0 = bm + wm + mi * 16 + lr;
        #pragma unroll
        for (int ni = 0; ni < 4; ni++) {
            int col0 = bn + wn + ni * 8 + (lc << 1);
            float b0 = bias[col0], b1 = bias[col0 + 1];
            #pragma unroll
            for (int half = 0; half < 2; half++) {
                int row = row0 + half * 8;
                float v0 = acc[mi][ni][half * 2 + 0] + b0;
                float v1 = acc[mi][ni][half * 2 + 1] + b1;
                if (GELU_) {
                    v0 = 0.5f * v0 * (1.0f + erff(v0 * 0.70710678118654752f));
                    v1 = 0.5f * v1 * (1.0f + erff(v1 * 0.70710678118654752f));
                }
                if (RES_) {
                    float2 r2 = *(const float2*)(R + (size_t)row * N + col0);
                    v0 += r2.x; v1 += r2.y;
                }
                if (SPLITOUT_) {
                    float h0 = bf16f(v0), h1 = bf16f(v1);
                    size_t off = (size_t)row * N + col0;
                    *(uint32_t*)(Ch + off) = pack2(h0, h1);
                    *(uint32_t*)(Cl + off) = pack2(v0 - h0, v1 - h1);
                } else {
                    *(float2*)(C + (size_t)row * N + col0) = make_float2(v0, v1);
                }
            }
        }
    }
}

// ---------------------------------------------------------------------------
// 2xTF32 attention scores (proven, unchanged)
// ---------------------------------------------------------------------------
#define SQT 36

__global__ void __launch_bounds__(128) attn_scores_x2(
    const float* __restrict__ q, const float* __restrict__ k,
    float* __restrict__ sc)
{
    __shared__ uint32_t QsH[64 * SQT];
    __shared__ uint32_t QsL[64 * SQT];
    __shared__ uint32_t KsH[64 * SQT];
    __shared__ uint32_t KsL[64 * SQT];

    int bh = blockIdx.z, b = bh / CH, h = bh % CH;
    int s0 = blockIdx.y * 64, t0 = blockIdx.x * 64;
    int tid = threadIdx.x, lane = tid & 31, wid = tid >> 5;
    int wm = (wid >> 1) * 32, wn = (wid & 1) * 32;
    int lr = lane >> 2, lc = lane & 3;

    const float* qb = q + (size_t)b * CS * CD + h * CHD;
    const float* kb = k + (size_t)b * CS * CD + h * CHD;

    float acc[2][4][4];
    #pragma unroll
    for (int mi = 0; mi < 2; mi++)
        #pragma unroll
        for (int ni = 0; ni < 4; ni++)
            #pragma unroll
            for (int e = 0; e < 4; e++) acc[mi][ni][e] = 0.0f;

    for (int d0 = 0; d0 < CHD; d0 += 32) {
        #pragma unroll
        for (int i = 0; i < 4; i++) {
            int idx = tid + 128 * i;
            int row = idx >> 3;
            int c4  = (idx & 7) << 2;
            float4 qa = (s0 + row < CS)
                ? *(const float4*)(qb + (size_t)(s0 + row) * CD + d0 + c4)
                : make_float4(0.f, 0.f, 0.f, 0.f);
            uint4 hh, ll;
            split4(qa, hh, ll);
            *(uint4*)&QsH[row * SQT + c4] = hh;
            *(uint4*)&QsL[row * SQT + c4] = ll;
            float4 ka = (t0 + row < CS)
                ? *(const float4*)(kb + (size_t)(t0 + row) * CD + d0 + c4)
                : make_float4(0.f, 0.f, 0.f, 0.f);
            split4(ka, hh, ll);
            *(uint4*)&KsH[row * SQT + c4] = hh;
            *(uint4*)&KsL[row * SQT + c4] = ll;
        }
        __syncthreads();

        #pragma unroll
        for (int ks = 0; ks < 4; ks++) {
            int kk = ks * 8;
            uint32_t aH[2][4], aL[2][4], bH[4][2], bL[4][2];
            #pragma unroll
            for (int mi = 0; mi < 2; mi++) {
                int row = wm + mi * 16 + lr;
                aH[mi][0] = QsH[row * SQT + kk + lc];
                aH[mi][1] = QsH[(row + 8) * SQT + kk + lc];
                aH[mi][2] = QsH[row * SQT + kk + lc + 4];
                aH[mi][3] = QsH[(row + 8) * SQT + kk + lc + 4];
                aL[mi][0] = QsL[row * SQT + kk + lc];
                aL[mi][1] = QsL[(row + 8) * SQT + kk + lc];
                aL[mi][2] = QsL[row * SQT + kk + lc + 4];
                aL[mi][3] = QsL[(row + 8) * SQT + kk + lc + 4];
            }
            #pragma unroll
            for (int ni = 0; ni < 4; ni++) {
                int col = wn + ni * 8 + lr;
                bH[ni][0] = KsH[col * SQT + kk + lc];
                bH[ni][1] = KsH[col * SQT + kk + lc + 4];
                bL[ni][0] = KsL[col * SQT + kk + lc];
                bL[ni][1] = KsL[col * SQT + kk + lc + 4];
            }
            #pragma unroll
            for (int mi = 0; mi < 2; mi++)
                #pragma unroll
                for (int ni = 0; ni < 4; ni++) {
                    mma8(acc[mi][ni], aH[mi], bH[ni]);
                    mma8(acc[mi][ni], aL[mi], bH[ni]);
                    mma8(acc[mi][ni], aH[mi], bL[ni]);
                }
        }
        __syncthreads();
    }

    float* scb = sc + (size_t)bh * CS * CS;
    #pragma unroll
    for (int mi = 0; mi < 2; mi++) {
        #pragma unroll
        for (int ni = 0; ni < 4; ni++) {
            #pragma unroll
            for (int e = 0; e < 4; e++) {
                int s = s0 + wm + mi * 16 + lr + (e >> 1) * 8;
                int t = t0 + wn + ni * 8 + (lc << 1) + (e & 1);
                if (s < CS && t < CS)
                    scb[(size_t)s * CS + t] = acc[mi][ni][e] * 0.125f;
            }
        }
    }
}

// ---------------------------------------------------------------------------
// 2xTF32 context -> bf16 hi/lo output
// ---------------------------------------------------------------------------
#define PST 36
#define VSTR 72

__global__ void __launch_bounds__(128) attn_ctx_x2(
    const float* __restrict__ p, const float* __restrict__ v,
    __nv_bfloat16* __restrict__ ctxh, __nv_bfloat16* __restrict__ ctxl)
{
    __shared__ uint32_t PsH[64 * PST];
    __shared__ uint32_t PsL[64 * PST];
    __shared__ uint32_t VsH[32 * VSTR];
    __shared__ uint32_t VsL[32 * VSTR];

    int bh = blockIdx.y, b = bh / CH, h = bh % CH;
    int s0 = blockIdx.x * 64;
    int tid = threadIdx.x, lane = tid & 31, wid = tid >> 5;
    int wm = (wid >> 1) * 32, wn = (wid & 1) * 32;
    int lr = lane >> 2, lc = lane & 3;

    const float* pb = p + (size_t)bh * CS * CS;
    const float* vb = v + (size_t)b * CS * CD + h * CHD;

    float acc[2][4][4];
    #pragma unroll
    for (int mi = 0; mi < 2; mi++)
        #pragma unroll
        for (int ni = 0; ni < 4; ni++)
            #pragma unroll
            for (int e = 0; e < 4; e++) acc[mi][ni][e] = 0.0f;

    for (int t0 = 0; t0 < CS; t0 += 32) {
        #pragma unroll
        for (int i = 0; i < 4; i++) {
            int idx = tid + 128 * i;
            int prow = idx >> 3;
            int pc4  = (idx & 7) << 2;
            float4 pa = (s0 + prow < CS && t0 + pc4 < CS)
                ? *(const float4*)(pb + (size_t)(s0 + prow) * CS + t0 + pc4)
                : make_float4(0.f, 0.f, 0.f, 0.f);
            uint4 hh, ll;
            split4(pa, hh, ll);
            *(uint4*)&PsH[prow * PST + pc4] = hh;
            *(uint4*)&PsL[prow * PST + pc4] = ll;

            int vrow = idx >> 4;
            int vc4  = (idx & 15) << 2;
            float4 va = (t0 + vrow < CS)
                ? *(const float4*)(vb + (size_t)(t0 + vrow) * CD + vc4)
                : make_float4(0.f, 0.f, 0.f, 0.f);
            split4(va, hh, ll);
            *(uint4*)&VsH[vrow * VSTR + vc4] = hh;
            *(uint4*)&VsL[vrow * VSTR + vc4] = ll;
        }
        __syncthreads();

        #pragma unroll
        for (int ks = 0; ks < 4; ks++) {
            int kk = ks * 8;
            uint32_t aH[2][4], aL[2][4], bH[4][2], bL[4][2];
            #pragma unroll
            for (int mi = 0; mi < 2; mi++) {
                int row = wm + mi * 16 + lr;
                aH[mi][0] = PsH[row * PST + kk + lc];
                aH[mi][1] = PsH[(row + 8) * PST + kk + lc];
                aH[mi][2] = PsH[row * PST + kk + lc + 4];
                aH[mi][3] = PsH[(row + 8) * PST + kk + lc + 4];
                aL[mi][0] = PsL[row * PST + kk + lc];
                aL[mi][1] = PsL[(row + 8) * PST + kk + lc];
                aL[mi][2] = PsL[row * PST + kk + lc + 4];
                aL[mi][3] = PsL[(row + 8) * PST + kk + lc + 4];
            }
            #pragma unroll
            for (int ni = 0; ni < 4; ni++) {
                int col = wn + ni * 8 + lr;
                bH[ni][0] = VsH[(kk + lc) * VSTR + col];
                bH[ni][1] = VsH[(kk + lc + 4) * VSTR + col];
                bL[ni][0] = VsL[(kk + lc) * VSTR + col];
                bL[ni][1] = VsL[(kk + lc + 4) * VSTR + col];
            }
            #pragma unroll
            for (int mi = 0; mi < 2; mi++)
                #pragma unroll
                for (int ni = 0; ni < 4; ni++) {
                    mma8(acc[mi][ni], aH[mi], bH[ni]);
                    mma8(acc[mi][ni], aL[mi], bH[ni]);
                    mma8(acc[mi][ni], aH[mi], bL[ni]);
                }
        }
        __syncthreads();
    }

    #pragma unroll
    for (int mi = 0; mi < 2; mi++) {
        #pragma unroll
        for (int ni = 0; ni < 4; ni++) {
            #pragma unroll
            for (int half = 0; half < 2; half++) {
                int s = s0 + wm + mi * 16 + lr + half * 8;
                if (s >= CS) continue;
                int d = wn + ni * 8 + (lc << 1);
                float a0 = acc[mi][ni][half * 2 + 0];
                float a1 = acc[mi][ni][half * 2 + 1];
                float h0 = bf16f(a0), h1 = bf16f(a1);
                size_t off = ((size_t)b * CS + s) * CD + h * CHD + d;
                *(uint32_t*)(ctxh + off) = pack2(h0, h1);
                *(uint32_t*)(ctxl + off) = pack2(a0 - h0, a1 - h1);
            }
        }
    }
}

// ---------------------------------------------------------------------------
// Row softmax (unchanged)
// ---------------------------------------------------------------------------
__global__ void __launch_bounds__(256) softmax_rows(float* __restrict__ sc)
{
    float* row = sc + (size_t)blockIdx.x * CS;
    int tid = threadIdx.x;
    float m = -1e30f;
    for (int i = tid; i < CS; i += 256) m = fmaxf(m, row[i]);
    m = bmax(m);
    float sum = 0.0f;
    for (int i = tid; i < CS; i += 256) {
        float e = __expf(row[i] - m);
        row[i] = e;
        sum += e;
    }
    sum = bsum(sum);
    float inv = 1.0f / sum;
    for (int i = tid; i < CS; i += 256) row[i] *= inv;
}

// ---------------------------------------------------------------------------
// Orchestration
// ---------------------------------------------------------------------------
extern "C" void kernel_launch(void* const* d_in, const int* in_sizes, int n_in,
                              void* d_out, int out_size)
{
    (void)in_sizes; (void)n_in; (void)out_size;

    const float* x     = (const float*)d_in[0];
    const float* ln1_s = (const float*)d_in[1];
    const float* ln1_b = (const float*)d_in[2];
    const float* wq    = (const float*)d_in[3];
    const float* bq    = (const float*)d_in[4];
    const float* wk    = (const float*)d_in[5];
    const float* bk    = (const float*)d_in[6];
    const float* wv    = (const float*)d_in[7];
    const float* bv    = (const float*)d_in[8];
    const float* wo    = (const float*)d_in[9];
    const float* bo    = (const float*)d_in[10];
    const float* ln2_s = (const float*)d_in[11];
    const float* ln2_b = (const float*)d_in[12];
    const float* w1    = (const float*)d_in[13];
    const float* b1    = (const float*)d_in[14];
    const float* w2    = (const float*)d_in[15];
    const float* b2    = (const float*)d_in[16];
    const float* lnf_s = (const float*)d_in[17];
    const float* lnf_b = (const float*)d_in[18];

    float *h, *q, *k, *v, *sc;
    cudaGetSymbolAddress((void**)&h,  g_h);
    cudaGetSymbolAddress((void**)&q,  g_q);
    cudaGetSymbolAddress((void**)&k,  g_k);
    cudaGetSymbolAddress((void**)&v,  g_v);
    cudaGetSymbolAddress((void**)&sc, g_sc);

    __nv_bfloat16 *yh, *yl, *ctxh, *ctxl, *mlph, *mlpl;
    cudaGetSymbolAddress((void**)&yh,   g_yh);
    cudaGetSymbolAddress((void**)&yl,   g_yl);
    cudaGetSymbolAddress((void**)&ctxh, g_ctxh);
    cudaGetSymbolAddress((void**)&ctxl, g_ctxl);
    cudaGetSymbolAddress((void**)&mlph, g_mlph);
    cudaGetSymbolAddress((void**)&mlpl, g_mlpl);

    __nv_bfloat16 *wqth, *wqtl, *wkth, *wktl, *wvth, *wvtl, *woth, *wotl;
    __nv_bfloat16 *w1th, *w1tl, *w2th, *w2tl;
    cudaGetSymbolAddress((void**)&wqth, g_wqth);
    cudaGetSymbolAddress((void**)&wqtl, g_wqtl);
    cudaGetSymbolAddress((void**)&wkth, g_wkth);
    cudaGetSymbolAddress((void**)&wktl, g_wktl);
    cudaGetSymbolAddress((void**)&wvth, g_wvth);
    cudaGetSymbolAddress((void**)&wvtl, g_wvtl);
    cudaGetSymbolAddress((void**)&woth, g_woth);
    cudaGetSymbolAddress((void**)&wotl, g_wotl);
    cudaGetSymbolAddress((void**)&w1th, g_w1th);
    cudaGetSymbolAddress((void**)&w1tl, g_w1tl);
    cudaGetSymbolAddress((void**)&w2th, g_w2th);
    cudaGetSymbolAddress((void**)&w2tl, g_w2tl);

    cudaFuncSetAttribute(gemm_bf16p<0,0,0>, cudaFuncAttributeMaxDynamicSharedMemorySize, GSMEM);
    cudaFuncSetAttribute(gemm_bf16p<0,1,0>, cudaFuncAttributeMaxDynamicSharedMemorySize, GSMEM);
    cudaFuncSetAttribute(gemm_bf16p<1,0,1>, cudaFuncAttributeMaxDynamicSharedMemorySize, GSMEM);

    dim3 blk(256), blk128(128);

    // weight prep (~140us per replay)
    splitT_kernel<<<dim3(CD/32, CD/32, CL), blk>>>(wq, wqth, wqtl, CD, CD);
    splitT_kernel<<<dim3(CD/32, CD/32, CL), blk>>>(wk, wkth, wktl, CD, CD);
    splitT_kernel<<<dim3(CD/32, CD/32, CL), blk>>>(wv, wvth, wvtl, CD, CD);
    splitT_kernel<<<dim3(CD/32, CD/32, CL), blk>>>(wo, woth, wotl, CD, CD);
    splitT_kernel<<<dim3(CF/32, CD/32, CL), blk>>>(w1, w1th, w1tl, CD, CF);
    splitT_kernel<<<dim3(CD/32, CF/32, CL), blk>>>(w2, w2th, w2tl, CF, CD);

    cudaMemcpyAsync(h, x, (size_t)CBS * CD * sizeof(float),
                    cudaMemcpyDeviceToDevice);

    dim3 gp768(CD / 128, CBS / 128);    // (6, 49)
    dim3 gp3072(CF / 128, CBS / 128);   // (24, 49)
    dim3 gsc((CS + 63) / 64, (CS + 63) / 64, CB * CH);
    dim3 gctx((CS + 63) / 64, CB * CH);

    for (int l = 0; l < CL; l++) {
        size_t wo768 = (size_t)l * CD * CD;
        size_t woF   = (size_t)l * CD * CF;
        ln_split_kernel<<<CBS, blk>>>(h, yh, yl, ln1_s + l * CD, ln1_b + l * CD);
        gemm_bf16p<0,0,0><<<gp768, blk, GSMEM>>>(
            yh, yl, wqth + wo768, wqtl + wo768, bq + l * CD, nullptr,
            q, nullptr, nullptr, CD, CD);
        gemm_bf16p<0,0,0><<<gp768, blk, GSMEM>>>(
            yh, yl, wkth + wo768, wktl + wo768, bk + l * CD, nullptr,
            k, nullptr, nullptr, CD, CD);
        gemm_bf16p<0,0,0><<<gp768, blk, GSMEM>>>(
            yh, yl, wvth + wo768, wvtl + wo768, bv + l * CD, nullptr,
            v, nullptr, nullptr, CD, CD);
        attn_scores_x2<<<gsc, blk128>>>(q, k, sc);
        softmax_rows<<<CB * CH * CS, blk>>>(sc);
        attn_ctx_x2<<<gctx, blk128>>>(sc, v, ctxh, ctxl);
        gemm_bf16p<0,1,0><<<gp768, blk, GSMEM>>>(
            ctxh, ctxl, woth + wo768, wotl + wo768, bo + l * CD, h,
            h, nullptr, nullptr, CD, CD);
        ln_split_kernel<<<CBS, blk>>>(h, yh, yl, ln2_s + l * CD, ln2_b + l * CD);
        gemm_bf16p<1,0,1><<<gp3072, blk, GSMEM>>>(
            yh, yl, w1th + woF, w1tl + woF, b1 + l * CF, nullptr,
            nullptr, mlph, mlpl, CF, CD);
        gemm_bf16p<0,1,0><<<gp768, blk, GSMEM>>>(
            mlph, mlpl, w2th + woF, w2tl + woF, b2 + l * CD, h,
            h, nullptr, nullptr, CD, CF);
    }
    ln_kernel<<<CBS, blk>>>(h, (float*)d_out, lnf_s, lnf_b);
}

// round 8
// speedup vs baseline: 2.6904x; 1.4501x over previous
#include <cuda_runtime.h>
#include <cuda_bf16.h>
#include <math.h>
#include <stdint.h>

// Problem constants
#define CL   12
#define CD   768
#define CH   12
#define CF   3072
#define CB   8
#define CS   784
#define CHD  64
#define CBS  (CB*CS)          // 6272 rows
#define CEPS 1e-6f
#define TPAD 832              // t-dim padded to 13*64

// ---------------------------------------------------------------------------
// Scratch (device globals; no allocations allowed)
// ---------------------------------------------------------------------------
__device__ float g_h  [CBS*CD];
__device__ float g_v  [CBS*CD];

__device__ __nv_bfloat16 g_yh  [CBS*CD];
__device__ __nv_bfloat16 g_yl  [CBS*CD];
__device__ __nv_bfloat16 g_qh  [CBS*CD];
__device__ __nv_bfloat16 g_ql  [CBS*CD];
__device__ __nv_bfloat16 g_kh  [CBS*CD];
__device__ __nv_bfloat16 g_kl  [CBS*CD];
__device__ __nv_bfloat16 g_vth [CB*CH*CHD*TPAD];
__device__ __nv_bfloat16 g_vtl [CB*CH*CHD*TPAD];
__device__ __nv_bfloat16 g_ctxh[CBS*CD];
__device__ __nv_bfloat16 g_ctxl[CBS*CD];
__device__ __nv_bfloat16 g_mlph[(size_t)CBS*CF];
__device__ __nv_bfloat16 g_mlpl[(size_t)CBS*CF];

// split+transposed weights: [L][N][K] bf16 hi/lo
__device__ __nv_bfloat16 g_wqth[CL*CD*CD], g_wqtl[CL*CD*CD];
__device__ __nv_bfloat16 g_wkth[CL*CD*CD], g_wktl[CL*CD*CD];
__device__ __nv_bfloat16 g_wvth[CL*CD*CD], g_wvtl[CL*CD*CD];
__device__ __nv_bfloat16 g_woth[CL*CD*CD], g_wotl[CL*CD*CD];
__device__ __nv_bfloat16 g_w1th[(size_t)CL*CD*CF], g_w1tl[(size_t)CL*CD*CF];
__device__ __nv_bfloat16 g_w2th[(size_t)CL*CD*CF], g_w2tl[(size_t)CL*CD*CF];

// ---------------------------------------------------------------------------
// helpers
// ---------------------------------------------------------------------------
__device__ __forceinline__ uint32_t smem_u32(const void* p) {
    return (uint32_t)__cvta_generic_to_shared(p);
}
__device__ __forceinline__ uint32_t pack2(float a, float b) {
    __nv_bfloat162 t = __floats2bfloat162_rn(a, b);
    return *reinterpret_cast<uint32_t*>(&t);
}
__device__ __forceinline__ float bf16f(float a) {
    return __bfloat162float(__float2bfloat16(a));
}

__device__ __forceinline__ void mma16(float* c, const uint32_t* a, const uint32_t* b) {
    asm("mma.sync.aligned.m16n8k16.row.col.f32.bf16.bf16.f32 "
        "{%0,%1,%2,%3},{%4,%5,%6,%7},{%8,%9},{%0,%1,%2,%3};"
        : "+f"(c[0]), "+f"(c[1]), "+f"(c[2]), "+f"(c[3])
        : "r"(a[0]), "r"(a[1]), "r"(a[2]), "r"(a[3]), "r"(b[0]), "r"(b[1]));
}

#define CP16(dst, src) \
    asm volatile("cp.async.cg.shared.global [%0], [%1], 16;" \
                 :: "r"(dst), "l"(src) : "memory")

// ---------------------------------------------------------------------------
// Block reduction (256 threads)
// ---------------------------------------------------------------------------
__device__ __forceinline__ float bsum(float v) {
    __shared__ float red[32];
    #pragma unroll
    for (int o = 16; o; o >>= 1) v += __shfl_xor_sync(0xffffffffu, v, o);
    if ((threadIdx.x & 31) == 0) red[threadIdx.x >> 5] = v;
    __syncthreads();
    float t = (threadIdx.x < (blockDim.x >> 5)) ? red[threadIdx.x] : 0.0f;
    if (threadIdx.x < 32) {
        #pragma unroll
        for (int o = 16; o; o >>= 1) t += __shfl_xor_sync(0xffffffffu, t, o);
        if (threadIdx.x == 0) red[0] = t;
    }
    __syncthreads();
    float r = red[0];
    __syncthreads();
    return r;
}

// ---------------------------------------------------------------------------
// Weight prep: transpose + bf16 hi/lo split. W:[L][K][N] -> T{h,l}:[L][N][K]
// ---------------------------------------------------------------------------
__global__ void __launch_bounds__(256) splitT_kernel(
    const float* __restrict__ W, __nv_bfloat16* __restrict__ Th,
    __nv_bfloat16* __restrict__ Tl, int K, int N)
{
    __shared__ float t[32][33];
    size_t lb = (size_t)blockIdx.z * K * N;
    const float* Wl = W + lb;
    __nv_bfloat16* Thl = Th + lb;
    __nv_bfloat16* Tll = Tl + lb;
    int n0 = blockIdx.x * 32, k0 = blockIdx.y * 32;
    int tx = threadIdx.x & 31, ty = threadIdx.x >> 5;
    #pragma unroll
    for (int r = 0; r < 32; r += 8)
        t[ty + r][tx] = Wl[(size_t)(k0 + ty + r) * N + n0 + tx];
    __syncthreads();
    #pragma unroll
    for (int r = 0; r < 32; r += 8) {
        float v = t[tx][ty + r];
        float hv = bf16f(v);
        size_t o = (size_t)(n0 + ty + r) * K + k0 + tx;
        Thl[o] = __float2bfloat16(hv);
        Tll[o] = __float2bfloat16(v - hv);
    }
}

// ---------------------------------------------------------------------------
// V transpose+split: v fp32 [b,t,h,d] -> vt{h,l} bf16 [b*h][d][TPAD]
// ---------------------------------------------------------------------------
__global__ void __launch_bounds__(256) vsplitT_kernel(
    const float* __restrict__ v,
    __nv_bfloat16* __restrict__ vth, __nv_bfloat16* __restrict__ vtl)
{
    __shared__ float t[64][65];
    int bh = blockIdx.y, b = bh / CH, h = bh % CH;
    int t0 = blockIdx.x * 64;
    int tid = threadIdx.x;
    #pragma unroll
    for (int i = 0; i < 16; i++) {
        int idx = tid + 256 * i;
        int row = idx >> 6, d = idx & 63;
        int tr = t0 + row;
        t[row][d] = (tr < CS)
            ? v[((size_t)b * CS + tr) * CD + h * CHD + d] : 0.0f;
    }
    __syncthreads();
    // write: 4 d-rows per pass; warp covers 128B contiguous t-span per d
    #pragma unroll
    for (int pass = 0; pass < 4; pass++) {
        int d = (tid >> 4) + pass * 16;
        int tw = (tid & 15) * 4;          // 4 t-elems per thread
        size_t ob = ((size_t)bh * CHD + d) * TPAD + t0 + tw;
        float v0 = t[tw + 0][d], v1 = t[tw + 1][d];
        float v2 = t[tw + 2][d], v3 = t[tw + 3][d];
        float h0 = bf16f(v0), h1 = bf16f(v1), h2 = bf16f(v2), h3 = bf16f(v3);
        *(uint32_t*)(vth + ob)     = pack2(h0, h1);
        *(uint32_t*)(vth + ob + 2) = pack2(h2, h3);
        *(uint32_t*)(vtl + ob)     = pack2(v0 - h0, v1 - h1);
        *(uint32_t*)(vtl + ob + 2) = pack2(v2 - h2, v3 - h3);
    }
}

// ---------------------------------------------------------------------------
// LayerNorm -> fp32 out (final)
// ---------------------------------------------------------------------------
__global__ void __launch_bounds__(256) ln_kernel(
    const float* __restrict__ in, float* __restrict__ out,
    const float* __restrict__ gs, const float* __restrict__ gb)
{
    int tid = threadIdx.x;
    const float* x = in  + (size_t)blockIdx.x * CD;
    float*       o = out + (size_t)blockIdx.x * CD;
    float v0 = x[tid], v1 = x[tid + 256], v2 = x[tid + 512];
    float mean = bsum(v0 + v1 + v2) * (1.0f / CD);
    float c0 = v0 - mean, c1 = v1 - mean, c2 = v2 - mean;
    float var = bsum(c0*c0 + c1*c1 + c2*c2) * (1.0f / CD);
    float r = rsqrtf(var + CEPS);
    o[tid]       = c0 * r * gs[tid]       + gb[tid];
    o[tid + 256] = c1 * r * gs[tid + 256] + gb[tid + 256];
    o[tid + 512] = c2 * r * gs[tid + 512] + gb[tid + 512];
}

// LayerNorm -> bf16 hi/lo
__global__ void __launch_bounds__(256) ln_split_kernel(
    const float* __restrict__ in,
    __nv_bfloat16* __restrict__ oh, __nv_bfloat16* __restrict__ ol,
    const float* __restrict__ gs, const float* __restrict__ gb)
{
    int tid = threadIdx.x;
    const float* x = in + (size_t)blockIdx.x * CD;
    size_t ob = (size_t)blockIdx.x * CD;
    float v0 = x[tid], v1 = x[tid + 256], v2 = x[tid + 512];
    float mean = bsum(v0 + v1 + v2) * (1.0f / CD);
    float c0 = v0 - mean, c1 = v1 - mean, c2 = v2 - mean;
    float var = bsum(c0*c0 + c1*c1 + c2*c2) * (1.0f / CD);
    float r = rsqrtf(var + CEPS);
    float y0 = c0 * r * gs[tid]       + gb[tid];
    float y1 = c1 * r * gs[tid + 256] + gb[tid + 256];
    float y2 = c2 * r * gs[tid + 512] + gb[tid + 512];
    float h0 = bf16f(y0), h1 = bf16f(y1), h2 = bf16f(y2);
    oh[ob + tid]       = __float2bfloat16(h0);
    oh[ob + tid + 256] = __float2bfloat16(h1);
    oh[ob + tid + 512] = __float2bfloat16(h2);
    ol[ob + tid]       = __float2bfloat16(y0 - h0);
    ol[ob + tid + 256] = __float2bfloat16(y1 - h1);
    ol[ob + tid + 512] = __float2bfloat16(y2 - h2);
}

// ---------------------------------------------------------------------------
// bf16x3 GEMM (unchanged from R7): C = A @ B^T (+bias/gelu/res)
// ---------------------------------------------------------------------------
#define GSTAGE 40960
#define GSMEM  (2*GSTAGE)

template<int GELU_, int RES_, int SPLITOUT_>
__global__ void __launch_bounds__(256, 2) gemm_bf16p(
    const __nv_bfloat16* __restrict__ Ah, const __nv_bfloat16* __restrict__ Al,
    const __nv_bfloat16* __restrict__ Bh, const __nv_bfloat16* __restrict__ Bl,
    const float* __restrict__ bias, const float* __restrict__ R,
    float* __restrict__ C,
    __nv_bfloat16* __restrict__ Ch, __nv_bfloat16* __restrict__ Cl,
    int N, int K)
{
    extern __shared__ char smem[];
    const int tid = threadIdx.x, lane = tid & 31, wid = tid >> 5;
    const int bm = blockIdx.y * 128, bn = blockIdx.x * 128;
    const int wm = (wid >> 2) * 64, wn = (wid & 3) * 32;
    const int lr = lane >> 2, lc = lane & 3;
    const uint32_t sbase = smem_u32(smem);

    auto fill = [&](int kt, int s) {
        int k0 = kt << 5;
        uint32_t stg = sbase + s * GSTAGE;
        #pragma unroll
        for (int i = 0; i < 8; i++) {
            int idx = tid + 256 * i;
            int arr = idx >> 9;
            int c = idx & 511;
            int row = c >> 2, ch = c & 3;
            const __nv_bfloat16* g = (arr == 0) ? Ah : (arr == 1) ? Al
                                   : (arr == 2) ? Bh : Bl;
            int rb = (arr < 2) ? bm : bn;
            const __nv_bfloat16* src = g + (size_t)(rb + row) * K + k0 + ch * 8;
            uint32_t dst = stg + arr * 10240 + row * 80 + ch * 16;
            CP16(dst, src);
        }
        asm volatile("cp.async.commit_group;" ::: "memory");
    };

    float acc[4][4][4];
    #pragma unroll
    for (int mi = 0; mi < 4; mi++)
        #pragma unroll
        for (int ni = 0; ni < 4; ni++)
            #pragma unroll
            for (int e = 0; e < 4; e++) acc[mi][ni][e] = 0.0f;

    int NT = K >> 5;
    fill(0, 0);
    fill(1, 1);

    for (int kt = 0; kt < NT; kt++) {
        int s = kt & 1;
        asm volatile("cp.async.wait_group 1;" ::: "memory");
        __syncthreads();

        const uint32_t* AH = (const uint32_t*)(smem + s * GSTAGE);
        const uint32_t* AL = AH + 2560;
        const uint32_t* BH = AH + 5120;
        const uint32_t* BL = AH + 7680;

        #pragma unroll
        for (int ks = 0; ks < 2; ks++) {
            int kp0 = ks * 8;
            uint32_t aH[4][4], aL[4][4];
            #pragma unroll
            for (int mi = 0; mi < 4; mi++) {
                int r0 = (wm + mi * 16 + lr) * 20 + kp0 + lc;
                int r1 = r0 + 160;
                aH[mi][0] = AH[r0]; aH[mi][1] = AH[r1];
                aH[mi][2] = AH[r0 + 4]; aH[mi][3] = AH[r1 + 4];
                aL[mi][0] = AL[r0]; aL[mi][1] = AL[r1];
                aL[mi][2] = AL[r0 + 4]; aL[mi][3] = AL[r1 + 4];
            }
            #pragma unroll
            for (int ni = 0; ni < 4; ni++) {
                int cb = (wn + ni * 8 + lr) * 20 + kp0 + lc;
                uint32_t bH[2] = { BH[cb], BH[cb + 4] };
                uint32_t bL[2] = { BL[cb], BL[cb + 4] };
                #pragma unroll
                for (int mi = 0; mi < 4; mi++) {
                    mma16(acc[mi][ni], aH[mi], bH);
                    mma16(acc[mi][ni], aL[mi], bH);
                    mma16(acc[mi][ni], aH[mi], bL);
                }
            }
        }
        __syncthreads();
        if (kt + 2 < NT) fill(kt + 2, s);
    }

    #pragma unroll
    for (int mi = 0; mi < 4; mi++) {
        int row0 = bm + wm + mi * 16 + lr;
        #pragma unroll
        for (int ni = 0; ni < 4; ni++) {
            int col0 = bn + wn + ni * 8 + (lc << 1);
            float b0 = bias[col0], b1 = bias[col0 + 1];
            #pragma unroll
            for (int half = 0; half < 2; half++) {
                int row = row0 + half * 8;
                float v0 = acc[mi][ni][half * 2 + 0] + b0;
                float v1 = acc[mi][ni][half * 2 + 1] + b1;
                if (GELU_) {
                    v0 = 0.5f * v0 * (1.0f + erff(v0 * 0.70710678118654752f));
                    v1 = 0.5f * v1 * (1.0f + erff(v1 * 0.70710678118654752f));
                }
                if (RES_) {
                    float2 r2 = *(const float2*)(R + (size_t)row * N + col0);
                    v0 += r2.x; v1 += r2.y;
                }
                if (SPLITOUT_) {
                    float h0 = bf16f(v0), h1 = bf16f(v1);
                    size_t off = (size_t)row * N + col0;
                    *(uint32_t*)(Ch + off) = pack2(h0, h1);
                    *(uint32_t*)(Cl + off) = pack2(v0 - h0, v1 - h1);
                } else {
                    *(float2*)(C + (size_t)row * N + col0) = make_float2(v0, v1);
                }
            }
        }
    }
}

// ---------------------------------------------------------------------------
// Fused flash attention (bf16x3 QK and PV, online softmax).
// Grid: (13 qblocks, 96 bh). 128 threads = 4 warps; warp w owns q-rows
// s0+16w..s0+16w+15. K/V tiles of 64 double-buffered via cp.async.
// smem per stage: 4 arrays (Kh,Kl,Vh,Vl) x 64 rows x 36 words.
// ---------------------------------------------------------------------------
#define FST    36
#define FARR   (64*FST)            // words per array
#define FSTAGE (4*FARR*4)          // bytes per stage = 36864
#define FSMEM  (2*FSTAGE)          // 73728
#define NTT    ((CS + 63) / 64)    // 13

__global__ void __launch_bounds__(128, 2) flash_attn(
    const __nv_bfloat16* __restrict__ qh, const __nv_bfloat16* __restrict__ ql,
    const __nv_bfloat16* __restrict__ kh, const __nv_bfloat16* __restrict__ kl,
    const __nv_bfloat16* __restrict__ vth, const __nv_bfloat16* __restrict__ vtl,
    __nv_bfloat16* __restrict__ ctxh, __nv_bfloat16* __restrict__ ctxl)
{
    extern __shared__ uint32_t fs[];
    int tid = threadIdx.x, lane = tid & 31, w = tid >> 5;
    int lr = lane >> 2, lc = lane & 3;
    int bh = blockIdx.y, b = bh / CH, h = bh % CH;
    int s0 = blockIdx.x * 64;
    uint32_t sb = smem_u32(fs);

    // Q A-fragments (held in registers)
    uint32_t qfh[4][4], qfl[4][4];
    {
        int r0 = min(s0 + w * 16 + lr, CS - 1);
        int r1 = min(s0 + w * 16 + lr + 8, CS - 1);
        const __nv_bfloat16* qh0 = qh + ((size_t)b * CS + r0) * CD + h * CHD + 2 * lc;
        const __nv_bfloat16* qh1 = qh + ((size_t)b * CS + r1) * CD + h * CHD + 2 * lc;
        const __nv_bfloat16* ql0 = ql + ((size_t)b * CS + r0) * CD + h * CHD + 2 * lc;
        const __nv_bfloat16* ql1 = ql + ((size_t)b * CS + r1) * CD + h * CHD + 2 * lc;
        #pragma unroll
        for (int kf = 0; kf < 4; kf++) {
            qfh[kf][0] = *(const uint32_t*)(qh0 + kf * 16);
            qfh[kf][1] = *(const uint32_t*)(qh1 + kf * 16);
            qfh[kf][2] = *(const uint32_t*)(qh0 + kf * 16 + 8);
            qfh[kf][3] = *(const uint32_t*)(qh1 + kf * 16 + 8);
            qfl[kf][0] = *(const uint32_t*)(ql0 + kf * 16);
            qfl[kf][1] = *(const uint32_t*)(ql1 + kf * 16);
            qfl[kf][2] = *(const uint32_t*)(ql0 + kf * 16 + 8);
            qfl[kf][3] = *(const uint32_t*)(ql1 + kf * 16 + 8);
        }
    }

    auto fill = [&](int tt, int st) {
        int t0 = tt * 64;
        uint32_t base = sb + st * FSTAGE;
        #pragma unroll
        for (int i = 0; i < 16; i++) {
            int idx = tid + 128 * i;          // 0..2047
            int arr = idx >> 9;               // 0:Kh 1:Kl 2:Vh 3:Vl
            int c = idx & 511;
            int row = c >> 3, ch = c & 7;
            const __nv_bfloat16* src;
            if (arr < 2) {
                int t = min(t0 + row, CS - 1);
                src = (arr == 0 ? kh : kl) + ((size_t)b * CS + t) * CD + h * CHD + ch * 8;
            } else {
                src = (arr == 2 ? vth : vtl) + ((size_t)bh * CHD + row) * TPAD + t0 + ch * 8;
            }
            uint32_t dst = base + arr * (FARR * 4) + row * (FST * 4) + ch * 16;
            CP16(dst, src);
        }
        asm volatile("cp.async.commit_group;" ::: "memory");
    };

    float m0 = -1e30f, m1 = -1e30f, l0 = 0.0f, l1 = 0.0f;
    float o[8][4];
    #pragma unroll
    for (int nj = 0; nj < 8; nj++)
        #pragma unroll
        for (int e = 0; e < 4; e++) o[nj][e] = 0.0f;

    fill(0, 0);
    fill(1, 1);

    for (int tt = 0; tt < NTT; tt++) {
        int st = tt & 1;
        asm volatile("cp.async.wait_group 1;" ::: "memory");
        __syncthreads();

        const uint32_t* KH = fs + st * (FSTAGE / 4);
        const uint32_t* KL = KH + FARR;
        const uint32_t* VH = KH + 2 * FARR;
        const uint32_t* VL = KH + 3 * FARR;

        // S = Q K^T (bf16x3)
        float s[8][4];
        #pragma unroll
        for (int nj = 0; nj < 8; nj++) {
            s[nj][0] = s[nj][1] = s[nj][2] = s[nj][3] = 0.0f;
            int cb = (nj * 8 + lr) * FST;
            #pragma unroll
            for (int kf = 0; kf < 4; kf++) {
                uint32_t bh_[2] = { KH[cb + kf * 8 + lc], KH[cb + kf * 8 + lc + 4] };
                uint32_t bl_[2] = { KL[cb + kf * 8 + lc], KL[cb + kf * 8 + lc + 4] };
                mma16(s[nj], qfh[kf], bh_);
                mma16(s[nj], qfl[kf], bh_);
                mma16(s[nj], qfh[kf], bl_);
            }
        }

        // scale + mask
        bool last = (tt == NTT - 1);
        #pragma unroll
        for (int nj = 0; nj < 8; nj++) {
            if (last && nj >= 2) {
                s[nj][0] = s[nj][1] = s[nj][2] = s[nj][3] = -1e30f;
            } else {
                s[nj][0] *= 0.125f; s[nj][1] *= 0.125f;
                s[nj][2] *= 0.125f; s[nj][3] *= 0.125f;
            }
        }

        // online softmax update
        float tm0 = -1e30f, tm1 = -1e30f;
        #pragma unroll
        for (int nj = 0; nj < 8; nj++) {
            tm0 = fmaxf(tm0, fmaxf(s[nj][0], s[nj][1]));
            tm1 = fmaxf(tm1, fmaxf(s[nj][2], s[nj][3]));
        }
        tm0 = fmaxf(tm0, __shfl_xor_sync(0xffffffffu, tm0, 1));
        tm0 = fmaxf(tm0, __shfl_xor_sync(0xffffffffu, tm0, 2));
        tm1 = fmaxf(tm1, __shfl_xor_sync(0xffffffffu, tm1, 1));
        tm1 = fmaxf(tm1, __shfl_xor_sync(0xffffffffu, tm1, 2));
        float mn0 = fmaxf(m0, tm0), mn1 = fmaxf(m1, tm1);
        float a0 = __expf(m0 - mn0), a1 = __expf(m1 - mn1);
        m0 = mn0; m1 = mn1;

        float rs0 = 0.0f, rs1 = 0.0f;
        #pragma unroll
        for (int nj = 0; nj < 8; nj++) {
            s[nj][0] = __expf(s[nj][0] - mn0);
            s[nj][1] = __expf(s[nj][1] - mn0);
            s[nj][2] = __expf(s[nj][2] - mn1);
            s[nj][3] = __expf(s[nj][3] - mn1);
            rs0 += s[nj][0] + s[nj][1];
            rs1 += s[nj][2] + s[nj][3];
        }
        rs0 += __shfl_xor_sync(0xffffffffu, rs0, 1);
        rs0 += __shfl_xor_sync(0xffffffffu, rs0, 2);
        rs1 += __shfl_xor_sync(0xffffffffu, rs1, 1);
        rs1 += __shfl_xor_sync(0xffffffffu, rs1, 2);
        l0 = l0 * a0 + rs0;
        l1 = l1 * a1 + rs1;

        #pragma unroll
        for (int nj = 0; nj < 8; nj++) {
            o[nj][0] *= a0; o[nj][1] *= a0;
            o[nj][2] *= a1; o[nj][3] *= a1;
        }

        // pack P -> bf16 hi/lo A-fragments (c-frag -> a-frag pairing)
        uint32_t ph[4][4], pl[4][4];
        #pragma unroll
        for (int kf = 0; kf < 4; kf++) {
            int nj0 = 2 * kf, nj1 = 2 * kf + 1;
            float h00 = bf16f(s[nj0][0]), h01 = bf16f(s[nj0][1]);
            float h02 = bf16f(s[nj0][2]), h03 = bf16f(s[nj0][3]);
            float h10 = bf16f(s[nj1][0]), h11 = bf16f(s[nj1][1]);
            float h12 = bf16f(s[nj1][2]), h13 = bf16f(s[nj1][3]);
            ph[kf][0] = pack2(h00, h01);
            ph[kf][1] = pack2(h02, h03);
            ph[kf][2] = pack2(h10, h11);
            ph[kf][3] = pack2(h12, h13);
            pl[kf][0] = pack2(s[nj0][0] - h00, s[nj0][1] - h01);
            pl[kf][1] = pack2(s[nj0][2] - h02, s[nj0][3] - h03);
            pl[kf][2] = pack2(s[nj1][0] - h10, s[nj1][1] - h11);
            pl[kf][3] = pack2(s[nj1][2] - h12, s[nj1][3] - h13);
        }

        // O += P V (bf16x3); V B-frags from [d][t] layout
        #pragma unroll
        for (int nj = 0; nj < 8; nj++) {
            int cb = (nj * 8 + lr) * FST;
            #pragma unroll
            for (int kf = 0; kf < 4; kf++) {
                uint32_t vh_[2] = { VH[cb + kf * 8 + lc], VH[cb + kf * 8 + lc + 4] };
                uint32_t vl_[2] = { VL[cb + kf * 8 + lc], VL[cb + kf * 8 + lc + 4] };
                mma16(o[nj], ph[kf], vh_);
                mma16(o[nj], pl[kf], vh_);
                mma16(o[nj], ph[kf], vl_);
            }
        }

        __syncthreads();
        if (tt + 2 < NTT) fill(tt + 2, st);
    }

    // epilogue: normalize and write ctx hi/lo
    float i0 = 1.0f / l0, i1 = 1.0f / l1;
    int r0 = s0 + w * 16 + lr, r1 = r0 + 8;
    #pragma unroll
    for (int nj = 0; nj < 8; nj++) {
        int col = h * CHD + nj * 8 + 2 * lc;
        if (r0 < CS) {
            float v0 = o[nj][0] * i0, v1 = o[nj][1] * i0;
            float h0 = bf16f(v0), h1 = bf16f(v1);
            size_t off = ((size_t)b * CS + r0) * CD + col;
            *(uint32_t*)(ctxh + off) = pack2(h0, h1);
            *(uint32_t*)(ctxl + off) = pack2(v0 - h0, v1 - h1);
        }
        if (r1 < CS) {
            float v0 = o[nj][2] * i1, v1 = o[nj][3] * i1;
            float h0 = bf16f(v0), h1 = bf16f(v1);
            size_t off = ((size_t)b * CS + r1) * CD + col;
            *(uint32_t*)(ctxh + off) = pack2(h0, h1);
            *(uint32_t*)(ctxl + off) = pack2(v0 - h0, v1 - h1);
        }
    }
}

// ---------------------------------------------------------------------------
// Orchestration
// ---------------------------------------------------------------------------
extern "C" void kernel_launch(void* const* d_in, const int* in_sizes, int n_in,
                              void* d_out, int out_size)
{
    (void)in_sizes; (void)n_in; (void)out_size;

    const float* x     = (const float*)d_in[0];
    const float* ln1_s = (const float*)d_in[1];
    const float* ln1_b = (const float*)d_in[2];
    const float* wq    = (const float*)d_in[3];
    const float* bq    = (const float*)d_in[4];
    const float* wk    = (const float*)d_in[5];
    const float* bk    = (const float*)d_in[6];
    const float* wv    = (const float*)d_in[7];
    const float* bv    = (const float*)d_in[8];
    const float* wo    = (const float*)d_in[9];
    const float* bo    = (const float*)d_in[10];
    const float* ln2_s = (const float*)d_in[11];
    const float* ln2_b = (const float*)d_in[12];
    const float* w1    = (const float*)d_in[13];
    const float* b1    = (const float*)d_in[14];
    const float* w2    = (const float*)d_in[15];
    const float* b2    = (const float*)d_in[16];
    const float* lnf_s = (const float*)d_in[17];
    const float* lnf_b = (const float*)d_in[18];

    float *h, *v;
    cudaGetSymbolAddress((void**)&h, g_h);
    cudaGetSymbolAddress((void**)&v, g_v);

    __nv_bfloat16 *yh, *yl, *qh, *ql, *kh, *kl, *vth, *vtl, *ctxh, *ctxl, *mlph, *mlpl;
    cudaGetSymbolAddress((void**)&yh,   g_yh);
    cudaGetSymbolAddress((void**)&yl,   g_yl);
    cudaGetSymbolAddress((void**)&qh,   g_qh);
    cudaGetSymbolAddress((void**)&ql,   g_ql);
    cudaGetSymbolAddress((void**)&kh,   g_kh);
    cudaGetSymbolAddress((void**)&kl,   g_kl);
    cudaGetSymbolAddress((void**)&vth,  g_vth);
    cudaGetSymbolAddress((void**)&vtl,  g_vtl);
    cudaGetSymbolAddress((void**)&ctxh, g_ctxh);
    cudaGetSymbolAddress((void**)&ctxl, g_ctxl);
    cudaGetSymbolAddress((void**)&mlph, g_mlph);
    cudaGetSymbolAddress((void**)&mlpl, g_mlpl);

    __nv_bfloat16 *wqth, *wqtl, *wkth, *wktl, *wvth_, *wvtl_, *woth, *wotl;
    __nv_bfloat16 *w1th, *w1tl, *w2th, *w2tl;
    cudaGetSymbolAddress((void**)&wqth, g_wqth);
    cudaGetSymbolAddress((void**)&wqtl, g_wqtl);
    cudaGetSymbolAddress((void**)&wkth, g_wkth);
    cudaGetSymbolAddress((void**)&wktl, g_wktl);
    cudaGetSymbolAddress((void**)&wvth_, g_wvth);
    cudaGetSymbolAddress((void**)&wvtl_, g_wvtl);
    cudaGetSymbolAddress((void**)&woth, g_woth);
    cudaGetSymbolAddress((void**)&wotl, g_wotl);
    cudaGetSymbolAddress((void**)&w1th, g_w1th);
    cudaGetSymbolAddress((void**)&w1tl, g_w1tl);
    cudaGetSymbolAddress((void**)&w2th, g_w2th);
    cudaGetSymbolAddress((void**)&w2tl, g_w2tl);

    cudaFuncSetAttribute(gemm_bf16p<0,0,0>, cudaFuncAttributeMaxDynamicSharedMemorySize, GSMEM);
    cudaFuncSetAttribute(gemm_bf16p<0,0,1>, cudaFuncAttributeMaxDynamicSharedMemorySize, GSMEM);
    cudaFuncSetAttribute(gemm_bf16p<0,1,0>, cudaFuncAttributeMaxDynamicSharedMemorySize, GSMEM);
    cudaFuncSetAttribute(gemm_bf16p<1,0,1>, cudaFuncAttributeMaxDynamicSharedMemorySize, GSMEM);
    cudaFuncSetAttribute(flash_attn, cudaFuncAttributeMaxDynamicSharedMemorySize, FSMEM);

    dim3 blk(256), blk128(128);

    // weight prep
    splitT_kernel<<<dim3(CD/32, CD/32, CL), blk>>>(wq, wqth, wqtl, CD, CD);
    splitT_kernel<<<dim3(CD/32, CD/32, CL), blk>>>(wk, wkth, wktl, CD, CD);
    splitT_kernel<<<dim3(CD/32, CD/32, CL), blk>>>(wv, wvth_, wvtl_, CD, CD);
    splitT_kernel<<<dim3(CD/32, CD/32, CL), blk>>>(wo, woth, wotl, CD, CD);
    splitT_kernel<<<dim3(CF/32, CD/32, CL), blk>>>(w1, w1th, w1tl, CD, CF);
    splitT_kernel<<<dim3(CD/32, CF/32, CL), blk>>>(w2, w2th, w2tl, CF, CD);

    cudaMemcpyAsync(h, x, (size_t)CBS * CD * sizeof(float),
                    cudaMemcpyDeviceToDevice);

    dim3 gp768(CD / 128, CBS / 128);    // (6, 49)
    dim3 gp3072(CF / 128, CBS / 128);   // (24, 49)
    dim3 gfa(NTT, CB * CH);             // (13, 96)
    dim3 gvt(NTT, CB * CH);

    for (int l = 0; l < CL; l++) {
        size_t wo768 = (size_t)l * CD * CD;
        size_t woF   = (size_t)l * CD * CF;
        ln_split_kernel<<<CBS, blk>>>(h, yh, yl, ln1_s + l * CD, ln1_b + l * CD);
        gemm_bf16p<0,0,1><<<gp768, blk, GSMEM>>>(
            yh, yl, wqth + wo768, wqtl + wo768, bq + l * CD, nullptr,
            nullptr, qh, ql, CD, CD);
        gemm_bf16p<0,0,1><<<gp768, blk, GSMEM>>>(
            yh, yl, wkth + wo768, wktl + wo768, bk + l * CD, nullptr,
            nullptr, kh, kl, CD, CD);
        gemm_bf16p<0,0,0><<<gp768, blk, GSMEM>>>(
            yh, yl, wvth_ + wo768, wvtl_ + wo768, bv + l * CD, nullptr,
            v, nullptr, nullptr, CD, CD);
        vsplitT_kernel<<<gvt, blk>>>(v, vth, vtl);
        flash_attn<<<gfa, blk128, FSMEM>>>(qh, ql, kh, kl, vth, vtl, ctxh, ctxl);
        gemm_bf16p<0,1,0><<<gp768, blk, GSMEM>>>(
            ctxh, ctxl, woth + wo768, wotl + wo768, bo + l * CD, h,
            h, nullptr, nullptr, CD, CD);
        ln_split_kernel<<<CBS, blk>>>(h, yh, yl, ln2_s + l * CD, ln2_b + l * CD);
        gemm_bf16p<1,0,1><<<gp3072, blk, GSMEM>>>(
            yh, yl, w1th + woF, w1tl + woF, b1 + l * CF, nullptr,
            nullptr, mlph, mlpl, CF, CD);
        gemm_bf16p<0,1,0><<<gp768, blk, GSMEM>>>(
            mlph, mlpl, w2th + woF, w2tl + woF, b2 + l * CD, h,
            h, nullptr, nullptr, CD, CF);
    }
    ln_kernel<<<CBS, blk>>>(h, (float*)d_out, lnf_s, lnf_b);
}

// round 9
// speedup vs baseline: 4.3161x; 1.6043x over previous
#include <cuda_runtime.h>
#include <cuda_fp16.h>
#include <math.h>
#include <stdint.h>

// Problem constants
#define CL   12
#define CD   768
#define CH   12
#define CF   3072
#define CB   8
#define CS   784
#define CHD  64
#define CBS  (CB*CS)          // 6272 rows
#define CEPS 1e-6f
#define TPAD 832              // t-dim padded to 13*64

// ---------------------------------------------------------------------------
// Scratch (device globals; no allocations allowed)
// ---------------------------------------------------------------------------
__device__ float g_h [CBS*CD];
__device__ float g_v [CBS*CD];

__device__ __half g_yh  [CBS*CD];
__device__ __half g_yl  [CBS*CD];
__device__ __half g_qh  [CBS*CD];
__device__ __half g_ql  [CBS*CD];
__device__ __half g_kh  [CBS*CD];
__device__ __half g_vth [CB*CH*CHD*TPAD];
__device__ __half g_ctxh[CBS*CD];
__device__ __half g_ctxl[CBS*CD];
__device__ __half g_mlph[(size_t)CBS*CF];
__device__ __half g_mlpl[(size_t)CBS*CF];

// transposed fp16 weights (hi only): [L][N][K]
__device__ __half g_wqt[CL*CD*CD];
__device__ __half g_wkt[CL*CD*CD];
__device__ __half g_wvt[CL*CD*CD];
__device__ __half g_wot[CL*CD*CD];
__device__ __half g_w1t[(size_t)CL*CD*CF];
__device__ __half g_w2t[(size_t)CL*CD*CF];

// ---------------------------------------------------------------------------
// helpers
// ---------------------------------------------------------------------------
__device__ __forceinline__ uint32_t smem_u32(const void* p) {
    return (uint32_t)__cvta_generic_to_shared(p);
}
__device__ __forceinline__ uint32_t pack2h(float a, float b) {
    __half2 t = __floats2half2_rn(a, b);
    return *reinterpret_cast<uint32_t*>(&t);
}
__device__ __forceinline__ float f16f(float a) {
    return __half2float(__float2half_rn(a));
}

__device__ __forceinline__ void mma16f(float* c, const uint32_t* a, const uint32_t* b) {
    asm("mma.sync.aligned.m16n8k16.row.col.f32.f16.f16.f32 "
        "{%0,%1,%2,%3},{%4,%5,%6,%7},{%8,%9},{%0,%1,%2,%3};"
        : "+f"(c[0]), "+f"(c[1]), "+f"(c[2]), "+f"(c[3])
        : "r"(a[0]), "r"(a[1]), "r"(a[2]), "r"(a[3]), "r"(b[0]), "r"(b[1]));
}

#define CP16(dst, src) \
    asm volatile("cp.async.cg.shared.global [%0], [%1], 16;" \
                 :: "r"(dst), "l"(src) : "memory")

#define LDMX4(r, addr) \
    asm volatile("ldmatrix.sync.aligned.m8n8.x4.shared.b16 {%0,%1,%2,%3}, [%4];" \
                 : "=r"((r)[0]), "=r"((r)[1]), "=r"((r)[2]), "=r"((r)[3]) \
                 : "r"(addr))

// ---------------------------------------------------------------------------
// Block reduction (256 threads)
// ---------------------------------------------------------------------------
__device__ __forceinline__ float bsum(float v) {
    __shared__ float red[32];
    #pragma unroll
    for (int o = 16; o; o >>= 1) v += __shfl_xor_sync(0xffffffffu, v, o);
    if ((threadIdx.x & 31) == 0) red[threadIdx.x >> 5] = v;
    __syncthreads();
    float t = (threadIdx.x < (blockDim.x >> 5)) ? red[threadIdx.x] : 0.0f;
    if (threadIdx.x < 32) {
        #pragma unroll
        for (int o = 16; o; o >>= 1) t += __shfl_xor_sync(0xffffffffu, t, o);
        if (threadIdx.x == 0) red[0] = t;
    }
    __syncthreads();
    float r = red[0];
    __syncthreads();
    return r;
}

// ---------------------------------------------------------------------------
// Weight prep: transpose + fp16 convert. W:[L][K][N] -> T:[L][N][K]
// ---------------------------------------------------------------------------
__global__ void __launch_bounds__(256) splitT_kernel(
    const float* __restrict__ W, __half* __restrict__ Th, int K, int N)
{
    __shared__ float t[32][33];
    size_t lb = (size_t)blockIdx.z * K * N;
    const float* Wl = W + lb;
    __half* Thl = Th + lb;
    int n0 = blockIdx.x * 32, k0 = blockIdx.y * 32;
    int tx = threadIdx.x & 31, ty = threadIdx.x >> 5;
    #pragma unroll
    for (int r = 0; r < 32; r += 8)
        t[ty + r][tx] = Wl[(size_t)(k0 + ty + r) * N + n0 + tx];
    __syncthreads();
    #pragma unroll
    for (int r = 0; r < 32; r += 8)
        Thl[(size_t)(n0 + ty + r) * K + k0 + tx] = __float2half_rn(t[tx][ty + r]);
}

// ---------------------------------------------------------------------------
// V transpose: v fp32 [b,t,h,d] -> vth fp16 [b*h][d][TPAD]
// ---------------------------------------------------------------------------
__global__ void __launch_bounds__(256) vsplitT_kernel(
    const float* __restrict__ v, __half* __restrict__ vth)
{
    __shared__ float t[64][65];
    int bh = blockIdx.y, b = bh / CH, h = bh % CH;
    int t0 = blockIdx.x * 64;
    int tid = threadIdx.x;
    #pragma unroll
    for (int i = 0; i < 16; i++) {
        int idx = tid + 256 * i;
        int row = idx >> 6, d = idx & 63;
        int tr = t0 + row;
        t[row][d] = (tr < CS)
            ? v[((size_t)b * CS + tr) * CD + h * CHD + d] : 0.0f;
    }
    __syncthreads();
    #pragma unroll
    for (int pass = 0; pass < 4; pass++) {
        int d = (tid >> 4) + pass * 16;
        int tw = (tid & 15) * 4;
        size_t ob = ((size_t)bh * CHD + d) * TPAD + t0 + tw;
        *(uint32_t*)(vth + ob)     = pack2h(t[tw + 0][d], t[tw + 1][d]);
        *(uint32_t*)(vth + ob + 2) = pack2h(t[tw + 2][d], t[tw + 3][d]);
    }
}

// ---------------------------------------------------------------------------
// LayerNorm -> fp32 out (final)
// ---------------------------------------------------------------------------
__global__ void __launch_bounds__(256) ln_kernel(
    const float* __restrict__ in, float* __restrict__ out,
    const float* __restrict__ gs, const float* __restrict__ gb)
{
    int tid = threadIdx.x;
    const float* x = in  + (size_t)blockIdx.x * CD;
    float*       o = out + (size_t)blockIdx.x * CD;
    float v0 = x[tid], v1 = x[tid + 256], v2 = x[tid + 512];
    float mean = bsum(v0 + v1 + v2) * (1.0f / CD);
    float c0 = v0 - mean, c1 = v1 - mean, c2 = v2 - mean;
    float var = bsum(c0*c0 + c1*c1 + c2*c2) * (1.0f / CD);
    float r = rsqrtf(var + CEPS);
    o[tid]       = c0 * r * gs[tid]       + gb[tid];
    o[tid + 256] = c1 * r * gs[tid + 256] + gb[tid + 256];
    o[tid + 512] = c2 * r * gs[tid + 512] + gb[tid + 512];
}

// LayerNorm -> fp16 hi/lo
__global__ void __launch_bounds__(256) ln_split_kernel(
    const float* __restrict__ in,
    __half* __restrict__ oh, __half* __restrict__ ol,
    const float* __restrict__ gs, const float* __restrict__ gb)
{
    int tid = threadIdx.x;
    const float* x = in + (size_t)blockIdx.x * CD;
    size_t ob = (size_t)blockIdx.x * CD;
    float v0 = x[tid], v1 = x[tid + 256], v2 = x[tid + 512];
    float mean = bsum(v0 + v1 + v2) * (1.0f / CD);
    float c0 = v0 - mean, c1 = v1 - mean, c2 = v2 - mean;
    float var = bsum(c0*c0 + c1*c1 + c2*c2) * (1.0f / CD);
    float r = rsqrtf(var + CEPS);
    float y0 = c0 * r * gs[tid]       + gb[tid];
    float y1 = c1 * r * gs[tid + 256] + gb[tid + 256];
    float y2 = c2 * r * gs[tid + 512] + gb[tid + 512];
    float h0 = f16f(y0), h1 = f16f(y1), h2 = f16f(y2);
    oh[ob + tid]       = __float2half_rn(y0);
    oh[ob + tid + 256] = __float2half_rn(y1);
    oh[ob + tid + 512] = __float2half_rn(y2);
    ol[ob + tid]       = __float2half_rn(y0 - h0);
    ol[ob + tid + 256] = __float2half_rn(y1 - h1);
    ol[ob + tid + 512] = __float2half_rn(y2 - h2);
}

// ---------------------------------------------------------------------------
// fp16x2 GEMM: C = A @ B^T (+bias/gelu/res). A{h,l}[M][K], B[N][K] fp16.
// 128x128 CTA tile, KT=32, 8 warps (64x32 warp tile), 3-stage cp.async,
// single __syncthreads per k-tile, ldmatrix fragment loads, 2 CTAs/SM.
// Stage: 3 arrays (Ah, Al, B) x 128 rows x 80B (64 data + 16 pad).
// acc += Ah*B + Al*B (B-side fp16 residual dropped; ~1.4e-4 rel per dot).
// OUTM_: 0 = fp32 C, 1 = fp16 hi/lo (Ch,Cl), 2 = fp16 hi only (Ch)
// ---------------------------------------------------------------------------
#define GST    30720
#define GSMEM3 (3*GST)

template<int GELU_, int RES_, int OUTM_>
__global__ void __launch_bounds__(256, 2) gemm_fp16x2(
    const __half* __restrict__ Ah, const __half* __restrict__ Al,
    const __half* __restrict__ Bh,
    const float* __restrict__ bias, const float* __restrict__ R,
    float* __restrict__ C, __half* __restrict__ Ch, __half* __restrict__ Cl,
    int N, int K)
{
    extern __shared__ char smem[];
    const int tid = threadIdx.x, lane = tid & 31, wid = tid >> 5;
    const int bm = blockIdx.y * 128, bn = blockIdx.x * 128;
    const int wm = (wid >> 2) * 64, wn = (wid & 3) * 32;
    const int lr = lane >> 2, lc = lane & 3;
    const uint32_t sb = smem_u32(smem);

    // ldmatrix lane-address offsets (within stage)
    const uint32_t a_off = (uint32_t)((wm + (lane & 15)) * 80 + (lane >> 4) * 16);
    const uint32_t b_off = (uint32_t)(2 * 10240 +
        (wn + ((lane >> 4) & 1) * 8 + (lane & 7)) * 80 + ((lane >> 3) & 1) * 16);

    auto fill = [&](int kt, int s) {
        int k0 = kt << 5;
        uint32_t stg = sb + s * GST;
        #pragma unroll
        for (int i = 0; i < 6; i++) {
            int idx = tid + 256 * i;              // 0..1535
            int arr = idx >> 9;                   // 0:Ah 1:Al 2:B
            int c = idx & 511;
            int row = c >> 2, ch = c & 3;
            const __half* g = (arr == 0) ? Ah : (arr == 1) ? Al : Bh;
            int rb = (arr < 2) ? bm : bn;
            const __half* src = g + (size_t)(rb + row) * K + k0 + ch * 8;
            uint32_t dst = stg + arr * 10240 + row * 80 + ch * 16;
            CP16(dst, src);
        }
        asm volatile("cp.async.commit_group;" ::: "memory");
    };

    float acc[4][4][4];
    #pragma unroll
    for (int mi = 0; mi < 4; mi++)
        #pragma unroll
        for (int ni = 0; ni < 4; ni++)
            #pragma unroll
            for (int e = 0; e < 4; e++) acc[mi][ni][e] = 0.0f;

    int NT = K >> 5;
    fill(0, 0);
    fill(1, 1);

    for (int kt = 0; kt < NT; kt++) {
        int s = kt % 3;
        asm volatile("cp.async.wait_group 1;" ::: "memory");
        __syncthreads();
        uint32_t stg = sb + s * GST;

        #pragma unroll
        for (int ks = 0; ks < 2; ks++) {
            uint32_t kb = ks * 32;
            uint32_t ah[4][4], al[4][4], bb[2][4];
            #pragma unroll
            for (int mi = 0; mi < 4; mi++) {
                LDMX4(ah[mi], stg + a_off + mi * (16 * 80) + kb);
                LDMX4(al[mi], stg + 10240 + a_off + mi * (16 * 80) + kb);
            }
            #pragma unroll
            for (int nj = 0; nj < 2; nj++)
                LDMX4(bb[nj], stg + b_off + nj * (16 * 80) + kb);
            #pragma unroll
            for (int mi = 0; mi < 4; mi++)
                #pragma unroll
                for (int ni = 0; ni < 4; ni++) {
                    const uint32_t* bf = &bb[ni >> 1][(ni & 1) * 2];
                    mma16f(acc[mi][ni], ah[mi], bf);
                    mma16f(acc[mi][ni], al[mi], bf);
                }
        }
        if (kt + 2 < NT) fill(kt + 2, (kt + 2) % 3);
        else asm volatile("cp.async.commit_group;" ::: "memory");
    }

    // epilogue
    #pragma unroll
    for (int mi = 0; mi < 4; mi++) {
        int row0 = bm + wm + mi * 16 + lr;
        #pragma unroll
        for (int ni = 0; ni < 4; ni++) {
            int col0 = bn + wn + ni * 8 + (lc << 1);
            float b0 = bias[col0], b1 = bias[col0 + 1];
            #pragma unroll
            for (int half = 0; half < 2; half++) {
                int row = row0 + half * 8;
                float v0 = acc[mi][ni][half * 2 + 0] + b0;
                float v1 = acc[mi][ni][half * 2 + 1] + b1;
                if (GELU_) {
                    v0 = 0.5f * v0 * (1.0f + erff(v0 * 0.70710678118654752f));
                    v1 = 0.5f * v1 * (1.0f + erff(v1 * 0.70710678118654752f));
                }
                if (RES_) {
                    float2 r2 = *(const float2*)(R + (size_t)row * N + col0);
                    v0 += r2.x; v1 += r2.y;
                }
                size_t off = (size_t)row * N + col0;
                if (OUTM_ == 1) {
                    float h0 = f16f(v0), h1 = f16f(v1);
                    *(uint32_t*)(Ch + off) = pack2h(v0, v1);
                    *(uint32_t*)(Cl + off) = pack2h(v0 - h0, v1 - h1);
                } else if (OUTM_ == 2) {
                    *(uint32_t*)(Ch + off) = pack2h(v0, v1);
                } else {
                    *(float2*)(C + off) = make_float2(v0, v1);
                }
            }
        }
    }
}

// ---------------------------------------------------------------------------
// Fused flash attention, fp16x2 (online softmax).
// Grid (13, 96), 128 threads = 4 warps; warp w owns q-rows s0+16w..+15.
// Stage: 2 arrays (Kh, Vh) x 64 rows x 144B; 3 stages, single sync/tile.
// S = qh*Kh + ql*Kh ; O += ph*Vh + pl*Vh.
// ---------------------------------------------------------------------------
#define FST    36
#define FARR   (64*FST)
#define FSTAGE (2*FARR*4)          // 18432
#define FSMEM  (3*FSTAGE)          // 55296
#define NTT    ((CS + 63) / 64)    // 13

__global__ void __launch_bounds__(128, 2) flash_attn(
    const __half* __restrict__ qh, const __half* __restrict__ ql,
    const __half* __restrict__ kh, const __half* __restrict__ vth,
    __half* __restrict__ ctxh, __half* __restrict__ ctxl)
{
    extern __shared__ uint32_t fs[];
    int tid = threadIdx.x, lane = tid & 31, w = tid >> 5;
    int lr = lane >> 2, lc = lane & 3;
    int bh = blockIdx.y, b = bh / CH, h = bh % CH;
    int s0 = blockIdx.x * 64;
    uint32_t sb = smem_u32(fs);

    // Q A-fragments in registers
    uint32_t qfh[4][4], qfl[4][4];
    {
        int r0 = min(s0 + w * 16 + lr, CS - 1);
        int r1 = min(s0 + w * 16 + lr + 8, CS - 1);
        const __half* qh0 = qh + ((size_t)b * CS + r0) * CD + h * CHD + 2 * lc;
        const __half* qh1 = qh + ((size_t)b * CS + r1) * CD + h * CHD + 2 * lc;
        const __half* ql0 = ql + ((size_t)b * CS + r0) * CD + h * CHD + 2 * lc;
        const __half* ql1 = ql + ((size_t)b * CS + r1) * CD + h * CHD + 2 * lc;
        #pragma unroll
        for (int kf = 0; kf < 4; kf++) {
            qfh[kf][0] = *(const uint32_t*)(qh0 + kf * 16);
            qfh[kf][1] = *(const uint32_t*)(qh1 + kf * 16);
            qfh[kf][2] = *(const uint32_t*)(qh0 + kf * 16 + 8);
            qfh[kf][3] = *(const uint32_t*)(qh1 + kf * 16 + 8);
            qfl[kf][0] = *(const uint32_t*)(ql0 + kf * 16);
            qfl[kf][1] = *(const uint32_t*)(ql1 + kf * 16);
            qfl[kf][2] = *(const uint32_t*)(ql0 + kf * 16 + 8);
            qfl[kf][3] = *(const uint32_t*)(ql1 + kf * 16 + 8);
        }
    }

    auto fill = [&](int tt, int st) {
        int t0 = tt * 64;
        uint32_t base = sb + st * FSTAGE;
        #pragma unroll
        for (int i = 0; i < 8; i++) {
            int idx = tid + 128 * i;              // 0..1023
            int arr = idx >> 9;                   // 0:Kh 1:Vh
            int c = idx & 511;
            int row = c >> 3, ch = c & 7;
            const __half* src;
            if (arr == 0) {
                int t = min(t0 + row, CS - 1);
                src = kh + ((size_t)b * CS + t) * CD + h * CHD + ch * 8;
            } else {
                src = vth + ((size_t)bh * CHD + row) * TPAD + t0 + ch * 8;
            }
            uint32_t dst = base + arr * (FARR * 4) + row * (FST * 4) + ch * 16;
            CP16(dst, src);
        }
        asm volatile("cp.async.commit_group;" ::: "memory");
    };

    float m0 = -1e30f, m1 = -1e30f, l0 = 0.0f, l1 = 0.0f;
    float o[8][4];
    #pragma unroll
    for (int nj = 0; nj < 8; nj++)
        #pragma unroll
        for (int e = 0; e < 4; e++) o[nj][e] = 0.0f;

    fill(0, 0);
    fill(1, 1);

    for (int tt = 0; tt < NTT; tt++) {
        int st = tt % 3;
        asm volatile("cp.async.wait_group 1;" ::: "memory");
        __syncthreads();

        const uint32_t* KH = fs + st * (FSTAGE / 4);
        const uint32_t* VH = KH + FARR;

        // S = Q K^T
        float s[8][4];
        #pragma unroll
        for (int nj = 0; nj < 8; nj++) {
            s[nj][0] = s[nj][1] = s[nj][2] = s[nj][3] = 0.0f;
            int cb = (nj * 8 + lr) * FST;
            #pragma unroll
            for (int kf = 0; kf < 4; kf++) {
                uint32_t bh_[2] = { KH[cb + kf * 8 + lc], KH[cb + kf * 8 + lc + 4] };
                mma16f(s[nj], qfh[kf], bh_);
                mma16f(s[nj], qfl[kf], bh_);
            }
        }

        // scale + mask
        bool last = (tt == NTT - 1);
        #pragma unroll
        for (int nj = 0; nj < 8; nj++) {
            if (last && nj >= 2) {
                s[nj][0] = s[nj][1] = s[nj][2] = s[nj][3] = -1e30f;
            } else {
                s[nj][0] *= 0.125f; s[nj][1] *= 0.125f;
                s[nj][2] *= 0.125f; s[nj][3] *= 0.125f;
            }
        }

        // online softmax
        float tm0 = -1e30f, tm1 = -1e30f;
        #pragma unroll
        for (int nj = 0; nj < 8; nj++) {
            tm0 = fmaxf(tm0, fmaxf(s[nj][0], s[nj][1]));
            tm1 = fmaxf(tm1, fmaxf(s[nj][2], s[nj][3]));
        }
        tm0 = fmaxf(tm0, __shfl_xor_sync(0xffffffffu, tm0, 1));
        tm0 = fmaxf(tm0, __shfl_xor_sync(0xffffffffu, tm0, 2));
        tm1 = fmaxf(tm1, __shfl_xor_sync(0xffffffffu, tm1, 1));
        tm1 = fmaxf(tm1, __shfl_xor_sync(0xffffffffu, tm1, 2));
        float mn0 = fmaxf(m0, tm0), mn1 = fmaxf(m1, tm1);
        float a0 = __expf(m0 - mn0), a1 = __expf(m1 - mn1);
        m0 = mn0; m1 = mn1;

        float rs0 = 0.0f, rs1 = 0.0f;
        #pragma unroll
        for (int nj = 0; nj < 8; nj++) {
            s[nj][0] = __expf(s[nj][0] - mn0);
            s[nj][1] = __expf(s[nj][1] - mn0);
            s[nj][2] = __expf(s[nj][2] - mn1);
            s[nj][3] = __expf(s[nj][3] - mn1);
            rs0 += s[nj][0] + s[nj][1];
            rs1 += s[nj][2] + s[nj][3];
        }
        rs0 += __shfl_xor_sync(0xffffffffu, rs0, 1);
        rs0 += __shfl_xor_sync(0xffffffffu, rs0, 2);
        rs1 += __shfl_xor_sync(0xffffffffu, rs1, 1);
        rs1 += __shfl_xor_sync(0xffffffffu, rs1, 2);
        l0 = l0 * a0 + rs0;
        l1 = l1 * a1 + rs1;

        #pragma unroll
        for (int nj = 0; nj < 8; nj++) {
            o[nj][0] *= a0; o[nj][1] *= a0;
            o[nj][2] *= a1; o[nj][3] *= a1;
        }

        // pack P -> fp16 hi/lo A-fragments
        uint32_t ph[4][4], pl[4][4];
        #pragma unroll
        for (int kf = 0; kf < 4; kf++) {
            int nj0 = 2 * kf, nj1 = 2 * kf + 1;
            float h00 = f16f(s[nj0][0]), h01 = f16f(s[nj0][1]);
            float h02 = f16f(s[nj0][2]), h03 = f16f(s[nj0][3]);
            float h10 = f16f(s[nj1][0]), h11 = f16f(s[nj1][1]);
            float h12 = f16f(s[nj1][2]), h13 = f16f(s[nj1][3]);
            ph[kf][0] = pack2h(s[nj0][0], s[nj0][1]);
            ph[kf][1] = pack2h(s[nj0][2], s[nj0][3]);
            ph[kf][2] = pack2h(s[nj1][0], s[nj1][1]);
            ph[kf][3] = pack2h(s[nj1][2], s[nj1][3]);
            pl[kf][0] = pack2h(s[nj0][0] - h00, s[nj0][1] - h01);
            pl[kf][1] = pack2h(s[nj0][2] - h02, s[nj0][3] - h03);
            pl[kf][2] = pack2h(s[nj1][0] - h10, s[nj1][1] - h11);
            pl[kf][3] = pack2h(s[nj1][2] - h12, s[nj1][3] - h13);
        }

        // O += P V
        #pragma unroll
        for (int nj = 0; nj < 8; nj++) {
            int cb = (nj * 8 + lr) * FST;
            #pragma unroll
            for (int kf = 0; kf < 4; kf++) {
                uint32_t vh_[2] = { VH[cb + kf * 8 + lc], VH[cb + kf * 8 + lc + 4] };
                mma16f(o[nj], ph[kf], vh_);
                mma16f(o[nj], pl[kf], vh_);
            }
        }

        if (tt + 2 < NTT) fill(tt + 2, (tt + 2) % 3);
        else asm volatile("cp.async.commit_group;" ::: "memory");
    }

    // epilogue: normalize, write ctx fp16 hi/lo
    float i0 = 1.0f / l0, i1 = 1.0f / l1;
    int r0 = s0 + w * 16 + lr, r1 = r0 + 8;
    #pragma unroll
    for (int nj = 0; nj < 8; nj++) {
        int col = h * CHD + nj * 8 + 2 * lc;
        if (r0 < CS) {
            float v0 = o[nj][0] * i0, v1 = o[nj][1] * i0;
            float h0 = f16f(v0), h1 = f16f(v1);
            size_t off = ((size_t)b * CS + r0) * CD + col;
            *(uint32_t*)(ctxh + off) = pack2h(v0, v1);
            *(uint32_t*)(ctxl + off) = pack2h(v0 - h0, v1 - h1);
        }
        if (r1 < CS) {
            float v0 = o[nj][2] * i1, v1 = o[nj][3] * i1;
            float h0 = f16f(v0), h1 = f16f(v1);
            size_t off = ((size_t)b * CS + r1) * CD + col;
            *(uint32_t*)(ctxh + off) = pack2h(v0, v1);
            *(uint32_t*)(ctxl + off) = pack2h(v0 - h0, v1 - h1);
        }
    }
}

// ---------------------------------------------------------------------------
// Orchestration
// ---------------------------------------------------------------------------
extern "C" void kernel_launch(void* const* d_in, const int* in_sizes, int n_in,
                              void* d_out, int out_size)
{
    (void)in_sizes; (void)n_in; (void)out_size;

    const float* x     = (const float*)d_in[0];
    const float* ln1_s = (const float*)d_in[1];
    const float* ln1_b = (const float*)d_in[2];
    const float* wq    = (const float*)d_in[3];
    const float* bq    = (const float*)d_in[4];
    const float* wk    = (const float*)d_in[5];
    const float* bk    = (const float*)d_in[6];
    const float* wv    = (const float*)d_in[7];
    const float* bv    = (const float*)d_in[8];
    const float* wo    = (const float*)d_in[9];
    const float* bo    = (const float*)d_in[10];
    const float* ln2_s = (const float*)d_in[11];
    const float* ln2_b = (const float*)d_in[12];
    const float* w1    = (const float*)d_in[13];
    const float* b1    = (const float*)d_in[14];
    const float* w2    = (const float*)d_in[15];
    const float* b2    = (const float*)d_in[16];
    const float* lnf_s = (const float*)d_in[17];
    const float* lnf_b = (const float*)d_in[18];

    float *h, *v;
    cudaGetSymbolAddress((void**)&h, g_h);
    cudaGetSymbolAddress((void**)&v, g_v);

    __half *yh, *yl, *qh, *ql, *kh, *vth, *ctxh, *ctxl, *mlph, *mlpl;
    cudaGetSymbolAddress((void**)&yh,   g_yh);
    cudaGetSymbolAddress((void**)&yl,   g_yl);
    cudaGetSymbolAddress((void**)&qh,   g_qh);
    cudaGetSymbolAddress((void**)&ql,   g_ql);
    cudaGetSymbolAddress((void**)&kh,   g_kh);
    cudaGetSymbolAddress((void**)&vth,  g_vth);
    cudaGetSymbolAddress((void**)&ctxh, g_ctxh);
    cudaGetSymbolAddress((void**)&ctxl, g_ctxl);
    cudaGetSymbolAddress((void**)&mlph, g_mlph);
    cudaGetSymbolAddress((void**)&mlpl, g_mlpl);

    __half *wqt, *wkt, *wvt, *wot, *w1t, *w2t;
    cudaGetSymbolAddress((void**)&wqt, g_wqt);
    cudaGetSymbolAddress((void**)&wkt, g_wkt);
    cudaGetSymbolAddress((void**)&wvt, g_wvt);
    cudaGetSymbolAddress((void**)&wot, g_wot);
    cudaGetSymbolAddress((void**)&w1t, g_w1t);
    cudaGetSymbolAddress((void**)&w2t, g_w2t);

    cudaFuncSetAttribute(gemm_fp16x2<0,0,0>, cudaFuncAttributeMaxDynamicSharedMemorySize, GSMEM3);
    cudaFuncSetAttribute(gemm_fp16x2<0,0,1>, cudaFuncAttributeMaxDynamicSharedMemorySize, GSMEM3);
    cudaFuncSetAttribute(gemm_fp16x2<0,0,2>, cudaFuncAttributeMaxDynamicSharedMemorySize, GSMEM3);
    cudaFuncSetAttribute(gemm_fp16x2<0,1,0>, cudaFuncAttributeMaxDynamicSharedMemorySize, GSMEM3);
    cudaFuncSetAttribute(gemm_fp16x2<1,0,1>, cudaFuncAttributeMaxDynamicSharedMemorySize, GSMEM3);
    cudaFuncSetAttribute(flash_attn, cudaFuncAttributeMaxDynamicSharedMemorySize, FSMEM);

    dim3 blk(256), blk128(128);

    // weight prep
    splitT_kernel<<<dim3(CD/32, CD/32, CL), blk>>>(wq, wqt, CD, CD);
    splitT_kernel<<<dim3(CD/32, CD/32, CL), blk>>>(wk, wkt, CD, CD);
    splitT_kernel<<<dim3(CD/32, CD/32, CL), blk>>>(wv, wvt, CD, CD);
    splitT_kernel<<<dim3(CD/32, CD/32, CL), blk>>>(wo, wot, CD, CD);
    splitT_kernel<<<dim3(CF/32, CD/32, CL), blk>>>(w1, w1t, CD, CF);
    splitT_kernel<<<dim3(CD/32, CF/32, CL), blk>>>(w2, w2t, CF, CD);

    cudaMemcpyAsync(h, x, (size_t)CBS * CD * sizeof(float),
                    cudaMemcpyDeviceToDevice);

    dim3 gp768(CD / 128, CBS / 128);    // (6, 49)
    dim3 gp3072(CF / 128, CBS / 128);   // (24, 49)
    dim3 gfa(NTT, CB * CH);             // (13, 96)

    for (int l = 0; l < CL; l++) {
        size_t wo768 = (size_t)l * CD * CD;
        size_t woF   = (size_t)l * CD * CF;
        ln_split_kernel<<<CBS, blk>>>(h, yh, yl, ln1_s + l * CD, ln1_b + l * CD);
        gemm_fp16x2<0,0,1><<<gp768, blk, GSMEM3>>>(
            yh, yl, wqt + wo768, bq + l * CD, nullptr,
            nullptr, qh, ql, CD, CD);
        gemm_fp16x2<0,0,2><<<gp768, blk, GSMEM3>>>(
            yh, yl, wkt + wo768, bk + l * CD, nullptr,
            nullptr, kh, nullptr, CD, CD);
        gemm_fp16x2<0,0,0><<<gp768, blk, GSMEM3>>>(
            yh, yl, wvt + wo768, bv + l * CD, nullptr,
            v, nullptr, nullptr, CD, CD);
        vsplitT_kernel<<<gfa, blk>>>(v, vth);
        flash_attn<<<gfa, blk128, FSMEM>>>(qh, ql, kh, vth, ctxh, ctxl);
        gemm_fp16x2<0,1,0><<<gp768, blk, GSMEM3>>>(
            ctxh, ctxl, wot + wo768, bo + l * CD, h,
            h, nullptr, nullptr, CD, CD);
        ln_split_kernel<<<CBS, blk>>>(h, yh, yl, ln2_s + l * CD, ln2_b + l * CD);
        gemm_fp16x2<1,0,1><<<gp3072, blk, GSMEM3>>>(
            yh, yl, w1t + woF, b1 + l * CF, nullptr,
            nullptr, mlph, mlpl, CF, CD);
        gemm_fp16x2<0,1,0><<<gp768, blk, GSMEM3>>>(
            mlph, mlpl, w2t + woF, b2 + l * CD, h,
            h, nullptr, nullptr, CD, CF);
    }
    ln_kernel<<<CBS, blk>>>(h, (float*)d_out, lnf_s, lnf_b);
}

// round 10
// speedup vs baseline: 7.0651x; 1.6369x over previous
#include <cuda_runtime.h>
#include <cuda_fp16.h>
#include <math.h>
#include <stdint.h>

// Problem constants
#define CL   12
#define CD   768
#define CH   12
#define CF   3072
#define CB   8
#define CS   784
#define CHD  64
#define CBS  (CB*CS)          // 6272 rows
#define CEPS 1e-6f
#define TPAD 832              // t-dim padded to 13*64

// ---------------------------------------------------------------------------
// Scratch (device globals; no allocations allowed)
// ---------------------------------------------------------------------------
__device__ float g_h [CBS*CD];

__device__ __half g_yh  [CBS*CD];
__device__ __half g_qh  [CBS*CD];
__device__ __half g_kh  [CBS*CD];
__device__ __half g_vh  [CBS*CD];
__device__ __half g_vth [CB*CH*CHD*TPAD];
__device__ __half g_ctxh[CBS*CD];
__device__ __half g_mlph[(size_t)CBS*CF];

// transposed fp16 weights: [L][N][K]
__device__ __half g_wqt[CL*CD*CD];
__device__ __half g_wkt[CL*CD*CD];
__device__ __half g_wvt[CL*CD*CD];
__device__ __half g_wot[CL*CD*CD];
__device__ __half g_w1t[(size_t)CL*CD*CF];
__device__ __half g_w2t[(size_t)CL*CD*CF];

// ---------------------------------------------------------------------------
// helpers
// ---------------------------------------------------------------------------
__device__ __forceinline__ uint32_t smem_u32(const void* p) {
    return (uint32_t)__cvta_generic_to_shared(p);
}
__device__ __forceinline__ uint32_t pack2h(float a, float b) {
    __half2 t = __floats2half2_rn(a, b);
    return *reinterpret_cast<uint32_t*>(&t);
}

__device__ __forceinline__ void mma16f(float* c, const uint32_t* a, const uint32_t* b) {
    asm("mma.sync.aligned.m16n8k16.row.col.f32.f16.f16.f32 "
        "{%0,%1,%2,%3},{%4,%5,%6,%7},{%8,%9},{%0,%1,%2,%3};"
        : "+f"(c[0]), "+f"(c[1]), "+f"(c[2]), "+f"(c[3])
        : "r"(a[0]), "r"(a[1]), "r"(a[2]), "r"(a[3]), "r"(b[0]), "r"(b[1]));
}

#define CP16(dst, src) \
    asm volatile("cp.async.cg.shared.global [%0], [%1], 16;" \
                 :: "r"(dst), "l"(src) : "memory")

#define LDMX4(r, addr) \
    asm volatile("ldmatrix.sync.aligned.m8n8.x4.shared.b16 {%0,%1,%2,%3}, [%4];" \
                 : "=r"((r)[0]), "=r"((r)[1]), "=r"((r)[2]), "=r"((r)[3]) \
                 : "r"(addr))

// ---------------------------------------------------------------------------
// Block reduction (256 threads)
// ---------------------------------------------------------------------------
__device__ __forceinline__ float bsum(float v) {
    __shared__ float red[32];
    #pragma unroll
    for (int o = 16; o; o >>= 1) v += __shfl_xor_sync(0xffffffffu, v, o);
    if ((threadIdx.x & 31) == 0) red[threadIdx.x >> 5] = v;
    __syncthreads();
    float t = (threadIdx.x < (blockDim.x >> 5)) ? red[threadIdx.x] : 0.0f;
    if (threadIdx.x < 32) {
        #pragma unroll
        for (int o = 16; o; o >>= 1) t += __shfl_xor_sync(0xffffffffu, t, o);
        if (threadIdx.x == 0) red[0] = t;
    }
    __syncthreads();
    float r = red[0];
    __syncthreads();
    return r;
}

// ---------------------------------------------------------------------------
// Weight prep: transpose + fp16 convert. W:[L][K][N] -> T:[L][N][K]
// ---------------------------------------------------------------------------
__global__ void __launch_bounds__(256) splitT_kernel(
    const float* __restrict__ W, __half* __restrict__ Th, int K, int N)
{
    __shared__ float t[32][33];
    size_t lb = (size_t)blockIdx.z * K * N;
    const float* Wl = W + lb;
    __half* Thl = Th + lb;
    int n0 = blockIdx.x * 32, k0 = blockIdx.y * 32;
    int tx = threadIdx.x & 31, ty = threadIdx.x >> 5;
    #pragma unroll
    for (int r = 0; r < 32; r += 8)
        t[ty + r][tx] = Wl[(size_t)(k0 + ty + r) * N + n0 + tx];
    __syncthreads();
    #pragma unroll
    for (int r = 0; r < 32; r += 8)
        Thl[(size_t)(n0 + ty + r) * K + k0 + tx] = __float2half_rn(t[tx][ty + r]);
}

// ---------------------------------------------------------------------------
// V transpose: vh fp16 [b,t,h,d] -> vth fp16 [b*h][d][TPAD]
// ---------------------------------------------------------------------------
__global__ void __launch_bounds__(256) vsplitT_kernel(
    const __half* __restrict__ vh, __half* __restrict__ vth)
{
    __shared__ __half t[64][72];
    int bh = blockIdx.y, b = bh / CH, h = bh % CH;
    int t0 = blockIdx.x * 64;
    int tid = threadIdx.x;
    #pragma unroll
    for (int i = 0; i < 4; i++) {
        int idx = tid + 256 * i;          // 0..1023
        int row = idx >> 4, d4 = (idx & 15) << 2;
        int tr = t0 + row;
        if (tr < CS) {
            uint2 v2 = *(const uint2*)(vh + ((size_t)b * CS + tr) * CD + h * CHD + d4);
            *(uint2*)&t[row][d4] = v2;
        } else {
            *(uint2*)&t[row][d4] = make_uint2(0u, 0u);
        }
    }
    __syncthreads();
    #pragma unroll
    for (int pass = 0; pass < 4; pass++) {
        int d = (tid >> 4) + pass * 16;
        int tw = (tid & 15) * 4;
        size_t ob = ((size_t)bh * CHD + d) * TPAD + t0 + tw;
        __half v0 = t[tw + 0][d], v1 = t[tw + 1][d];
        __half v2 = t[tw + 2][d], v3 = t[tw + 3][d];
        __half2 p0 = __halves2half2(v0, v1), p1 = __halves2half2(v2, v3);
        *(uint32_t*)(vth + ob)     = *(uint32_t*)&p0;
        *(uint32_t*)(vth + ob + 2) = *(uint32_t*)&p1;
    }
}

// ---------------------------------------------------------------------------
// LayerNorm -> fp32 out (final)
// ---------------------------------------------------------------------------
__global__ void __launch_bounds__(256) ln_kernel(
    const float* __restrict__ in, float* __restrict__ out,
    const float* __restrict__ gs, const float* __restrict__ gb)
{
    int tid = threadIdx.x;
    const float* x = in  + (size_t)blockIdx.x * CD;
    float*       o = out + (size_t)blockIdx.x * CD;
    float v0 = x[tid], v1 = x[tid + 256], v2 = x[tid + 512];
    float mean = bsum(v0 + v1 + v2) * (1.0f / CD);
    float c0 = v0 - mean, c1 = v1 - mean, c2 = v2 - mean;
    float var = bsum(c0*c0 + c1*c1 + c2*c2) * (1.0f / CD);
    float r = rsqrtf(var + CEPS);
    o[tid]       = c0 * r * gs[tid]       + gb[tid];
    o[tid + 256] = c1 * r * gs[tid + 256] + gb[tid + 256];
    o[tid + 512] = c2 * r * gs[tid + 512] + gb[tid + 512];
}

// LayerNorm -> fp16
__global__ void __launch_bounds__(256) ln_h_kernel(
    const float* __restrict__ in, __half* __restrict__ oh,
    const float* __restrict__ gs, const float* __restrict__ gb)
{
    int tid = threadIdx.x;
    const float* x = in + (size_t)blockIdx.x * CD;
    size_t ob = (size_t)blockIdx.x * CD;
    float v0 = x[tid], v1 = x[tid + 256], v2 = x[tid + 512];
    float mean = bsum(v0 + v1 + v2) * (1.0f / CD);
    float c0 = v0 - mean, c1 = v1 - mean, c2 = v2 - mean;
    float var = bsum(c0*c0 + c1*c1 + c2*c2) * (1.0f / CD);
    float r = rsqrtf(var + CEPS);
    oh[ob + tid]       = __float2half_rn(c0 * r * gs[tid]       + gb[tid]);
    oh[ob + tid + 256] = __float2half_rn(c1 * r * gs[tid + 256] + gb[tid + 256]);
    oh[ob + tid + 512] = __float2half_rn(c2 * r * gs[tid + 512] + gb[tid + 512]);
}

// ---------------------------------------------------------------------------
// fp16 GEMM: C = A @ B^T (+bias/gelu/res). A[M][K], B[N][K] fp16.
// 128x128 CTA tile, KT=32, 8 warps (64x32 warp tile), 3-stage cp.async,
// single __syncthreads per k-tile, ldmatrix fragment loads, 2 CTAs/SM.
// Stage: 2 arrays (A, B) x 128 rows x 80B (64 data + 16 pad).
// OUTM_: 0 = fp32 C, 2 = fp16 Ch
// ---------------------------------------------------------------------------
#define GST    20480
#define GSMEM3 (3*GST)

template<int GELU_, int RES_, int OUTM_>
__global__ void __launch_bounds__(256, 2) gemm_fp16(
    const __half* __restrict__ Ah, const __half* __restrict__ Bh,
    const float* __restrict__ bias, const float* __restrict__ R,
    float* __restrict__ C, __half* __restrict__ Ch,
    int N, int K)
{
    extern __shared__ char smem[];
    const int tid = threadIdx.x, lane = tid & 31, wid = tid >> 5;
    const int bm = blockIdx.y * 128, bn = blockIdx.x * 128;
    const int wm = (wid >> 2) * 64, wn = (wid & 3) * 32;
    const int lr = lane >> 2, lc = lane & 3;
    const uint32_t sb = smem_u32(smem);

    const uint32_t a_off = (uint32_t)((wm + (lane & 15)) * 80 + (lane >> 4) * 16);
    const uint32_t b_off = (uint32_t)(10240 +
        (wn + ((lane >> 4) & 1) * 8 + (lane & 7)) * 80 + ((lane >> 3) & 1) * 16);

    auto fill = [&](int kt, int s) {
        int k0 = kt << 5;
        uint32_t stg = sb + s * GST;
        #pragma unroll
        for (int i = 0; i < 4; i++) {
            int idx = tid + 256 * i;              // 0..1023
            int arr = idx >> 9;                   // 0:A 1:B
            int c = idx & 511;
            int row = c >> 2, ch = c & 3;
            const __half* g = (arr == 0) ? Ah : Bh;
            int rb = (arr == 0) ? bm : bn;
            const __half* src = g + (size_t)(rb + row) * K + k0 + ch * 8;
            uint32_t dst = stg + arr * 10240 + row * 80 + ch * 16;
            CP16(dst, src);
        }
        asm volatile("cp.async.commit_group;" ::: "memory");
    };

    float acc[4][4][4];
    #pragma unroll
    for (int mi = 0; mi < 4; mi++)
        #pragma unroll
        for (int ni = 0; ni < 4; ni++)
            #pragma unroll
            for (int e = 0; e < 4; e++) acc[mi][ni][e] = 0.0f;

    int NT = K >> 5;
    fill(0, 0);
    fill(1, 1);

    for (int kt = 0; kt < NT; kt++) {
        int s = kt % 3;
        asm volatile("cp.async.wait_group 1;" ::: "memory");
        __syncthreads();
        uint32_t stg = sb + s * GST;

        #pragma unroll
        for (int ks = 0; ks < 2; ks++) {
            uint32_t kb = ks * 32;
            uint32_t ah[4][4], bb[2][4];
            #pragma unroll
            for (int mi = 0; mi < 4; mi++)
                LDMX4(ah[mi], stg + a_off + mi * (16 * 80) + kb);
            #pragma unroll
            for (int nj = 0; nj < 2; nj++)
                LDMX4(bb[nj], stg + b_off + nj * (16 * 80) + kb);
            #pragma unroll
            for (int mi = 0; mi < 4; mi++)
                #pragma unroll
                for (int ni = 0; ni < 4; ni++)
                    mma16f(acc[mi][ni], ah[mi], &bb[ni >> 1][(ni & 1) * 2]);
        }
        if (kt + 2 < NT) fill(kt + 2, (kt + 2) % 3);
        else asm volatile("cp.async.commit_group;" ::: "memory");
    }

    // epilogue
    #pragma unroll
    for (int mi = 0; mi < 4; mi++) {
        int row0 = bm + wm + mi * 16 + lr;
        #pragma unroll
        for (int ni = 0; ni < 4; ni++) {
            int col0 = bn + wn + ni * 8 + (lc << 1);
            float b0 = bias[col0], b1 = bias[col0 + 1];
            #pragma unroll
            for (int half = 0; half < 2; half++) {
                int row = row0 + half * 8;
                float v0 = acc[mi][ni][half * 2 + 0] + b0;
                float v1 = acc[mi][ni][half * 2 + 1] + b1;
                if (GELU_) {
                    v0 = 0.5f * v0 * (1.0f + erff(v0 * 0.70710678118654752f));
                    v1 = 0.5f * v1 * (1.0f + erff(v1 * 0.70710678118654752f));
                }
                if (RES_) {
                    float2 r2 = *(const float2*)(R + (size_t)row * N + col0);
                    v0 += r2.x; v1 += r2.y;
                }
                size_t off = (size_t)row * N + col0;
                if (OUTM_ == 2) {
                    *(uint32_t*)(Ch + off) = pack2h(v0, v1);
                } else {
                    *(float2*)(C + off) = make_float2(v0, v1);
                }
            }
        }
    }
}

// ---------------------------------------------------------------------------
// Fused flash attention, pure fp16 MMA (online softmax).
// Grid (13, 96), 128 threads = 4 warps; warp w owns q-rows s0+16w..+15.
// Stage: 2 arrays (Kh, Vh) x 64 rows x 144B; 3 stages, single sync/tile.
// ---------------------------------------------------------------------------
#define FST    36
#define FARR   (64*FST)
#define FSTAGE (2*FARR*4)          // 18432
#define FSMEM  (3*FSTAGE)          // 55296
#define NTT    ((CS + 63) / 64)    // 13

__global__ void __launch_bounds__(128, 2) flash_attn(
    const __half* __restrict__ qh, const __half* __restrict__ kh,
    const __half* __restrict__ vth, __half* __restrict__ ctxh)
{
    extern __shared__ uint32_t fs[];
    int tid = threadIdx.x, lane = tid & 31, w = tid >> 5;
    int lr = lane >> 2, lc = lane & 3;
    int bh = blockIdx.y, b = bh / CH, h = bh % CH;
    int s0 = blockIdx.x * 64;
    uint32_t sb = smem_u32(fs);

    // Q A-fragments in registers
    uint32_t qf[4][4];
    {
        int r0 = min(s0 + w * 16 + lr, CS - 1);
        int r1 = min(s0 + w * 16 + lr + 8, CS - 1);
        const __half* q0 = qh + ((size_t)b * CS + r0) * CD + h * CHD + 2 * lc;
        const __half* q1 = qh + ((size_t)b * CS + r1) * CD + h * CHD + 2 * lc;
        #pragma unroll
        for (int kf = 0; kf < 4; kf++) {
            qf[kf][0] = *(const uint32_t*)(q0 + kf * 16);
            qf[kf][1] = *(const uint32_t*)(q1 + kf * 16);
            qf[kf][2] = *(const uint32_t*)(q0 + kf * 16 + 8);
            qf[kf][3] = *(const uint32_t*)(q1 + kf * 16 + 8);
        }
    }

    auto fill = [&](int tt, int st) {
        int t0 = tt * 64;
        uint32_t base = sb + st * FSTAGE;
        #pragma unroll
        for (int i = 0; i < 8; i++) {
            int idx = tid + 128 * i;
            int arr = idx >> 9;                   // 0:Kh 1:Vh
            int c = idx & 511;
            int row = c >> 3, ch = c & 7;
            const __half* src;
            if (arr == 0) {
                int t = min(t0 + row, CS - 1);
                src = kh + ((size_t)b * CS + t) * CD + h * CHD + ch * 8;
            } else {
                src = vth + ((size_t)bh * CHD + row) * TPAD + t0 + ch * 8;
            }
            uint32_t dst = base + arr * (FARR * 4) + row * (FST * 4) + ch * 16;
            CP16(dst, src);
        }
        asm volatile("cp.async.commit_group;" ::: "memory");
    };

    float m0 = -1e30f, m1 = -1e30f, l0 = 0.0f, l1 = 0.0f;
    float o[8][4];
    #pragma unroll
    for (int nj = 0; nj < 8; nj++)
        #pragma unroll
        for (int e = 0; e < 4; e++) o[nj][e] = 0.0f;

    fill(0, 0);
    fill(1, 1);

    for (int tt = 0; tt < NTT; tt++) {
        int st = tt % 3;
        asm volatile("cp.async.wait_group 1;" ::: "memory");
        __syncthreads();

        const uint32_t* KH = fs + st * (FSTAGE / 4);
        const uint32_t* VH = KH + FARR;

        // S = Q K^T
        float s[8][4];
        #pragma unroll
        for (int nj = 0; nj < 8; nj++) {
            s[nj][0] = s[nj][1] = s[nj][2] = s[nj][3] = 0.0f;
            int cb = (nj * 8 + lr) * FST;
            #pragma unroll
            for (int kf = 0; kf < 4; kf++) {
                uint32_t bh_[2] = { KH[cb + kf * 8 + lc], KH[cb + kf * 8 + lc + 4] };
                mma16f(s[nj], qf[kf], bh_);
            }
        }

        // scale + mask
        bool last = (tt == NTT - 1);
        #pragma unroll
        for (int nj = 0; nj < 8; nj++) {
            if (last && nj >= 2) {
                s[nj][0] = s[nj][1] = s[nj][2] = s[nj][3] = -1e30f;
            } else {
                s[nj][0] *= 0.125f; s[nj][1] *= 0.125f;
                s[nj][2] *= 0.125f; s[nj][3] *= 0.125f;
            }
        }

        // online softmax
        float tm0 = -1e30f, tm1 = -1e30f;
        #pragma unroll
        for (int nj = 0; nj < 8; nj++) {
            tm0 = fmaxf(tm0, fmaxf(s[nj][0], s[nj][1]));
            tm1 = fmaxf(tm1, fmaxf(s[nj][2], s[nj][3]));
        }
        tm0 = fmaxf(tm0, __shfl_xor_sync(0xffffffffu, tm0, 1));
        tm0 = fmaxf(tm0, __shfl_xor_sync(0xffffffffu, tm0, 2));
        tm1 = fmaxf(tm1, __shfl_xor_sync(0xffffffffu, tm1, 1));
        tm1 = fmaxf(tm1, __shfl_xor_sync(0xffffffffu, tm1, 2));
        float mn0 = fmaxf(m0, tm0), mn1 = fmaxf(m1, tm1);
        float a0 = __expf(m0 - mn0), a1 = __expf(m1 - mn1);
        m0 = mn0; m1 = mn1;

        float rs0 = 0.0f, rs1 = 0.0f;
        #pragma unroll
        for (int nj = 0; nj < 8; nj++) {
            s[nj][0] = __expf(s[nj][0] - mn0);
            s[nj][1] = __expf(s[nj][1] - mn0);
            s[nj][2] = __expf(s[nj][2] - mn1);
            s[nj][3] = __expf(s[nj][3] - mn1);
            rs0 += s[nj][0] + s[nj][1];
            rs1 += s[nj][2] + s[nj][3];
        }
        rs0 += __shfl_xor_sync(0xffffffffu, rs0, 1);
        rs0 += __shfl_xor_sync(0xffffffffu, rs0, 2);
        rs1 += __shfl_xor_sync(0xffffffffu, rs1, 1);
        rs1 += __shfl_xor_sync(0xffffffffu, rs1, 2);
        l0 = l0 * a0 + rs0;
        l1 = l1 * a1 + rs1;

        #pragma unroll
        for (int nj = 0; nj < 8; nj++) {
            o[nj][0] *= a0; o[nj][1] *= a0;
            o[nj][2] *= a1; o[nj][3] *= a1;
        }

        // pack P -> fp16 A-fragments
        uint32_t ph[4][4];
        #pragma unroll
        for (int kf = 0; kf < 4; kf++) {
            int nj0 = 2 * kf, nj1 = 2 * kf + 1;
            ph[kf][0] = pack2h(s[nj0][0], s[nj0][1]);
            ph[kf][1] = pack2h(s[nj0][2], s[nj0][3]);
            ph[kf][2] = pack2h(s[nj1][0], s[nj1][1]);
            ph[kf][3] = pack2h(s[nj1][2], s[nj1][3]);
        }

        // O += P V
        #pragma unroll
        for (int nj = 0; nj < 8; nj++) {
            int cb = (nj * 8 + lr) * FST;
            #pragma unroll
            for (int kf = 0; kf < 4; kf++) {
                uint32_t vh_[2] = { VH[cb + kf * 8 + lc], VH[cb + kf * 8 + lc + 4] };
                mma16f(o[nj], ph[kf], vh_);
            }
        }

        if (tt + 2 < NTT) fill(tt + 2, (tt + 2) % 3);
        else asm volatile("cp.async.commit_group;" ::: "memory");
    }

    // epilogue: normalize, write ctx fp16
    float i0 = 1.0f / l0, i1 = 1.0f / l1;
    int r0 = s0 + w * 16 + lr, r1 = r0 + 8;
    #pragma unroll
    for (int nj = 0; nj < 8; nj++) {
        int col = h * CHD + nj * 8 + 2 * lc;
        if (r0 < CS) {
            size_t off = ((size_t)b * CS + r0) * CD + col;
            *(uint32_t*)(ctxh + off) = pack2h(o[nj][0] * i0, o[nj][1] * i0);
        }
        if (r1 < CS) {
            size_t off = ((size_t)b * CS + r1) * CD + col;
            *(uint32_t*)(ctxh + off) = pack2h(o[nj][2] * i1, o[nj][3] * i1);
        }
    }
}

// ---------------------------------------------------------------------------
// Orchestration
// ---------------------------------------------------------------------------
extern "C" void kernel_launch(void* const* d_in, const int* in_sizes, int n_in,
                              void* d_out, int out_size)
{
    (void)in_sizes; (void)n_in; (void)out_size;

    const float* x     = (const float*)d_in[0];
    const float* ln1_s = (const float*)d_in[1];
    const float* ln1_b = (const float*)d_in[2];
    const float* wq    = (const float*)d_in[3];
    const float* bq    = (const float*)d_in[4];
    const float* wk    = (const float*)d_in[5];
    const float* bk    = (const float*)d_in[6];
    const float* wv    = (const float*)d_in[7];
    const float* bv    = (const float*)d_in[8];
    const float* wo    = (const float*)d_in[9];
    const float* bo    = (const float*)d_in[10];
    const float* ln2_s = (const float*)d_in[11];
    const float* ln2_b = (const float*)d_in[12];
    const float* w1    = (const float*)d_in[13];
    const float* b1    = (const float*)d_in[14];
    const float* w2    = (const float*)d_in[15];
    const float* b2    = (const float*)d_in[16];
    const float* lnf_s = (const float*)d_in[17];
    const float* lnf_b = (const float*)d_in[18];

    float* h;
    cudaGetSymbolAddress((void**)&h, g_h);

    __half *yh, *qh, *kh, *vh, *vth, *ctxh, *mlph;
    cudaGetSymbolAddress((void**)&yh,   g_yh);
    cudaGetSymbolAddress((void**)&qh,   g_qh);
    cudaGetSymbolAddress((void**)&kh,   g_kh);
    cudaGetSymbolAddress((void**)&vh,   g_vh);
    cudaGetSymbolAddress((void**)&vth,  g_vth);
    cudaGetSymbolAddress((void**)&ctxh, g_ctxh);
    cudaGetSymbolAddress((void**)&mlph, g_mlph);

    __half *wqt, *wkt, *wvt, *wot, *w1t, *w2t;
    cudaGetSymbolAddress((void**)&wqt, g_wqt);
    cudaGetSymbolAddress((void**)&wkt, g_wkt);
    cudaGetSymbolAddress((void**)&wvt, g_wvt);
    cudaGetSymbolAddress((void**)&wot, g_wot);
    cudaGetSymbolAddress((void**)&w1t, g_w1t);
    cudaGetSymbolAddress((void**)&w2t, g_w2t);

    cudaFuncSetAttribute(gemm_fp16<0,0,0>, cudaFuncAttributeMaxDynamicSharedMemorySize, GSMEM3);
    cudaFuncSetAttribute(gemm_fp16<0,0,2>, cudaFuncAttributeMaxDynamicSharedMemorySize, GSMEM3);
    cudaFuncSetAttribute(gemm_fp16<0,1,0>, cudaFuncAttributeMaxDynamicSharedMemorySize, GSMEM3);
    cudaFuncSetAttribute(gemm_fp16<1,0,2>, cudaFuncAttributeMaxDynamicSharedMemorySize, GSMEM3);
    cudaFuncSetAttribute(flash_attn, cudaFuncAttributeMaxDynamicSharedMemorySize, FSMEM);

    dim3 blk(256), blk128(128);

    // weight prep
    splitT_kernel<<<dim3(CD/32, CD/32, CL), blk>>>(wq, wqt, CD, CD);
    splitT_kernel<<<dim3(CD/32, CD/32, CL), blk>>>(wk, wkt, CD, CD);
    splitT_kernel<<<dim3(CD/32, CD/32, CL), blk>>>(wv, wvt, CD, CD);
    splitT_kernel<<<dim3(CD/32, CD/32, CL), blk>>>(wo, wot, CD, CD);
    splitT_kernel<<<dim3(CF/32, CD/32, CL), blk>>>(w1, w1t, CD, CF);
    splitT_kernel<<<dim3(CD/32, CF/32, CL), blk>>>(w2, w2t, CF, CD);

    cudaMemcpyAsync(h, x, (size_t)CBS * CD * sizeof(float),
                    cudaMemcpyDeviceToDevice);

    dim3 gp768(CD / 128, CBS / 128);    // (6, 49)
    dim3 gp3072(CF / 128, CBS / 128);   // (24, 49)
    dim3 gfa(NTT, CB * CH);             // (13, 96)

    for (int l = 0; l < CL; l++) {
        size_t wo768 = (size_t)l * CD * CD;
        size_t woF   = (size_t)l * CD * CF;
        ln_h_kernel<<<CBS, blk>>>(h, yh, ln1_s + l * CD, ln1_b + l * CD);
        gemm_fp16<0,0,2><<<gp768, blk, GSMEM3>>>(
            yh, wqt + wo768, bq + l * CD, nullptr, nullptr, qh, CD, CD);
        gemm_fp16<0,0,2><<<gp768, blk, GSMEM3>>>(
            yh, wkt + wo768, bk + l * CD, nullptr, nullptr, kh, CD, CD);
        gemm_fp16<0,0,2><<<gp768, blk, GSMEM3>>>(
            yh, wvt + wo768, bv + l * CD, nullptr, nullptr, vh, CD, CD);
        vsplitT_kernel<<<gfa, blk>>>(vh, vth);
        flash_attn<<<gfa, blk128, FSMEM>>>(qh, kh, vth, ctxh);
        gemm_fp16<0,1,0><<<gp768, blk, GSMEM3>>>(
            ctxh, wot + wo768, bo + l * CD, h, h, nullptr, CD, CD);
        ln_h_kernel<<<CBS, blk>>>(h, yh, ln2_s + l * CD, ln2_b + l * CD);
        gemm_fp16<1,0,2><<<gp3072, blk, GSMEM3>>>(
            yh, w1t + woF, b1 + l * CF, nullptr, nullptr, mlph, CF, CD);
        gemm_fp16<0,1,0><<<gp768, blk, GSMEM3>>>(
            mlph, w2t + woF, b2 + l * CD, h, h, nullptr, CD, CF);
    }
    ln_kernel<<<CBS, blk>>>(h, (float*)d_out, lnf_s, lnf_b);
}

// round 11
// speedup vs baseline: 7.6599x; 1.0842x over previous
#include <cuda_runtime.h>
#include <cuda_fp16.h>
#include <math.h>
#include <stdint.h>

// Problem constants
#define CL   12
#define CD   768
#define CH   12
#define CF   3072
#define CB   8
#define CS   784
#define CHD  64
#define CBS  (CB*CS)          // 6272 rows
#define CEPS 1e-6f
#define QKVD 2304             // packed q|k|v row width

// ---------------------------------------------------------------------------
// Scratch (device globals; no allocations allowed)
// ---------------------------------------------------------------------------
__device__ float g_h [CBS*CD];

__device__ __half g_yh  [CBS*CD];
__device__ __half g_qkv [(size_t)CBS*QKVD];
__device__ __half g_ctxh[CBS*CD];
__device__ __half g_mlph[(size_t)CBS*CF];

// transposed fp16 weights: qkv packed [L][2304][768]; others [L][N][K]
__device__ __half g_wqkvt[(size_t)CL*QKVD*CD];
__device__ __half g_wot[CL*CD*CD];
__device__ __half g_w1t[(size_t)CL*CD*CF];
__device__ __half g_w2t[(size_t)CL*CD*CF];
__device__ float  g_bqkv[CL*QKVD];

// ---------------------------------------------------------------------------
// helpers
// ---------------------------------------------------------------------------
__device__ __forceinline__ uint32_t smem_u32(const void* p) {
    return (uint32_t)__cvta_generic_to_shared(p);
}
__device__ __forceinline__ uint32_t pack2h(float a, float b) {
    __half2 t = __floats2half2_rn(a, b);
    return *reinterpret_cast<uint32_t*>(&t);
}

__device__ __forceinline__ void mma16f(float* c, const uint32_t* a, const uint32_t* b) {
    asm("mma.sync.aligned.m16n8k16.row.col.f32.f16.f16.f32 "
        "{%0,%1,%2,%3},{%4,%5,%6,%7},{%8,%9},{%0,%1,%2,%3};"
        : "+f"(c[0]), "+f"(c[1]), "+f"(c[2]), "+f"(c[3])
        : "r"(a[0]), "r"(a[1]), "r"(a[2]), "r"(a[3]), "r"(b[0]), "r"(b[1]));
}

#define CP16(dst, src) \
    asm volatile("cp.async.cg.shared.global [%0], [%1], 16;" \
                 :: "r"(dst), "l"(src) : "memory")

#define LDMX4(r, addr) \
    asm volatile("ldmatrix.sync.aligned.m8n8.x4.shared.b16 {%0,%1,%2,%3}, [%4];" \
                 : "=r"((r)[0]), "=r"((r)[1]), "=r"((r)[2]), "=r"((r)[3]) \
                 : "r"(addr))

#define LDMX4T(r, addr) \
    asm volatile("ldmatrix.sync.aligned.m8n8.x4.trans.shared.b16 {%0,%1,%2,%3}, [%4];" \
                 : "=r"((r)[0]), "=r"((r)[1]), "=r"((r)[2]), "=r"((r)[3]) \
                 : "r"(addr))

// ---------------------------------------------------------------------------
// Block reduction (256 threads)
// ---------------------------------------------------------------------------
__device__ __forceinline__ float bsum(float v) {
    __shared__ float red[32];
    #pragma unroll
    for (int o = 16; o; o >>= 1) v += __shfl_xor_sync(0xffffffffu, v, o);
    if ((threadIdx.x & 31) == 0) red[threadIdx.x >> 5] = v;
    __syncthreads();
    float t = (threadIdx.x < (blockDim.x >> 5)) ? red[threadIdx.x] : 0.0f;
    if (threadIdx.x < 32) {
        #pragma unroll
        for (int o = 16; o; o >>= 1) t += __shfl_xor_sync(0xffffffffu, t, o);
        if (threadIdx.x == 0) red[0] = t;
    }
    __syncthreads();
    float r = red[0];
    __syncthreads();
    return r;
}

// ---------------------------------------------------------------------------
// Weight prep: transpose + fp16. W:[L][K][N] -> T:[L*ls_out + n*K + k]
// ---------------------------------------------------------------------------
__global__ void __launch_bounds__(256) splitT_kernel(
    const float* __restrict__ W, __half* __restrict__ Th,
    int K, int N, size_t ls_out)
{
    __shared__ float t[32][33];
    const float* Wl = W + (size_t)blockIdx.z * K * N;
    __half* Thl = Th + (size_t)blockIdx.z * ls_out;
    int n0 = blockIdx.x * 32, k0 = blockIdx.y * 32;
    int tx = threadIdx.x & 31, ty = threadIdx.x >> 5;
    #pragma unroll
    for (int r = 0; r < 32; r += 8)
        t[ty + r][tx] = Wl[(size_t)(k0 + ty + r) * N + n0 + tx];
    __syncthreads();
    #pragma unroll
    for (int r = 0; r < 32; r += 8)
        Thl[(size_t)(n0 + ty + r) * K + k0 + tx] = __float2half_rn(t[tx][ty + r]);
}

// pack qkv biases: [L][2304] = bq | bk | bv
__global__ void __launch_bounds__(256) pack_bias_kernel(
    const float* __restrict__ bq, const float* __restrict__ bk,
    const float* __restrict__ bv, float* __restrict__ out)
{
    int l = blockIdx.x;
    for (int i = threadIdx.x; i < QKVD; i += 256) {
        float v = (i < CD) ? bq[l * CD + i]
                : (i < 2 * CD) ? bk[l * CD + i - CD]
                : bv[l * CD + i - 2 * CD];
        out[l * QKVD + i] = v;
    }
}

// ---------------------------------------------------------------------------
// LayerNorm -> fp32 out (final)
// ---------------------------------------------------------------------------
__global__ void __launch_bounds__(256) ln_kernel(
    const float* __restrict__ in, float* __restrict__ out,
    const float* __restrict__ gs, const float* __restrict__ gb)
{
    int tid = threadIdx.x;
    const float* x = in  + (size_t)blockIdx.x * CD;
    float*       o = out + (size_t)blockIdx.x * CD;
    float v0 = x[tid], v1 = x[tid + 256], v2 = x[tid + 512];
    float mean = bsum(v0 + v1 + v2) * (1.0f / CD);
    float c0 = v0 - mean, c1 = v1 - mean, c2 = v2 - mean;
    float var = bsum(c0*c0 + c1*c1 + c2*c2) * (1.0f / CD);
    float r = rsqrtf(var + CEPS);
    o[tid]       = c0 * r * gs[tid]       + gb[tid];
    o[tid + 256] = c1 * r * gs[tid + 256] + gb[tid + 256];
    o[tid + 512] = c2 * r * gs[tid + 512] + gb[tid + 512];
}

// LayerNorm -> fp16
__global__ void __launch_bounds__(256) ln_h_kernel(
    const float* __restrict__ in, __half* __restrict__ oh,
    const float* __restrict__ gs, const float* __restrict__ gb)
{
    int tid = threadIdx.x;
    const float* x = in + (size_t)blockIdx.x * CD;
    size_t ob = (size_t)blockIdx.x * CD;
    float v0 = x[tid], v1 = x[tid + 256], v2 = x[tid + 512];
    float mean = bsum(v0 + v1 + v2) * (1.0f / CD);
    float c0 = v0 - mean, c1 = v1 - mean, c2 = v2 - mean;
    float var = bsum(c0*c0 + c1*c1 + c2*c2) * (1.0f / CD);
    float r = rsqrtf(var + CEPS);
    oh[ob + tid]       = __float2half_rn(c0 * r * gs[tid]       + gb[tid]);
    oh[ob + tid + 256] = __float2half_rn(c1 * r * gs[tid + 256] + gb[tid + 256]);
    oh[ob + tid + 512] = __float2half_rn(c2 * r * gs[tid + 512] + gb[tid + 512]);
}

// ---------------------------------------------------------------------------
// fp16 GEMM: C = A @ B^T (+bias/gelu/res). A[M][K], B[N][K] fp16.
// 128x128 CTA tile, KT=64, 8 warps (64x32 warp tile), 3-stage cp.async,
// single __syncthreads per k-tile, ldmatrix fragments, 2 CTAs/SM.
// Stage: 2 arrays (A, B) x 128 rows x 144B (128 data + 16 pad) = 36,864B.
// OUTM_: 0 = fp32 C, 2 = fp16 Ch
// ---------------------------------------------------------------------------
#define GST    36864
#define GSMEM3 (3*GST)

template<int GELU_, int RES_, int OUTM_>
__global__ void __launch_bounds__(256, 2) gemm_fp16(
    const __half* __restrict__ Ah, const __half* __restrict__ Bh,
    const float* __restrict__ bias, const float* __restrict__ R,
    float* __restrict__ C, __half* __restrict__ Ch,
    int N, int K)
{
    extern __shared__ char smem[];
    const int tid = threadIdx.x, lane = tid & 31, wid = tid >> 5;
    const int bm = blockIdx.y * 128, bn = blockIdx.x * 128;
    const int wm = (wid >> 2) * 64, wn = (wid & 3) * 32;
    const int lr = lane >> 2, lc = lane & 3;
    const uint32_t sb = smem_u32(smem);

    const uint32_t a_off = (uint32_t)((wm + (lane & 15)) * 144 + (lane >> 4) * 16);
    const uint32_t b_off = (uint32_t)(18432 +
        (wn + ((lane >> 4) & 1) * 8 + (lane & 7)) * 144 + ((lane >> 3) & 1) * 16);

    auto fill = [&](int kt, int s) {
        int k0 = kt << 6;
        uint32_t stg = sb + s * GST;
        #pragma unroll
        for (int i = 0; i < 8; i++) {
            int idx = tid + 256 * i;              // 0..2047
            int arr = idx >> 10;                  // 0:A 1:B
            int c = idx & 1023;
            int row = c >> 3, ch = c & 7;
            const __half* g = (arr == 0) ? Ah : Bh;
            int rb = (arr == 0) ? bm : bn;
            const __half* src = g + (size_t)(rb + row) * K + k0 + ch * 8;
            uint32_t dst = stg + arr * 18432 + row * 144 + ch * 16;
            CP16(dst, src);
        }
        asm volatile("cp.async.commit_group;" ::: "memory");
    };

    float acc[4][4][4];
    #pragma unroll
    for (int mi = 0; mi < 4; mi++)
        #pragma unroll
        for (int ni = 0; ni < 4; ni++)
            #pragma unroll
            for (int e = 0; e < 4; e++) acc[mi][ni][e] = 0.0f;

    int NT = K >> 6;
    fill(0, 0);
    fill(1, 1);

    for (int kt = 0; kt < NT; kt++) {
        int s = kt % 3;
        asm volatile("cp.async.wait_group 1;" ::: "memory");
        __syncthreads();
        uint32_t stg = sb + s * GST;

        #pragma unroll
        for (int ks = 0; ks < 4; ks++) {
            uint32_t kb = ks * 32;                // 16 fp16 = 32B per step
            uint32_t ah[4][4], bb[2][4];
            #pragma unroll
            for (int mi = 0; mi < 4; mi++)
                LDMX4(ah[mi], stg + a_off + mi * (16 * 144) + kb);
            #pragma unroll
            for (int nj = 0; nj < 2; nj++)
                LDMX4(bb[nj], stg + b_off + nj * (16 * 144) + kb);
            #pragma unroll
            for (int mi = 0; mi < 4; mi++)
                #pragma unroll
                for (int ni = 0; ni < 4; ni++)
                    mma16f(acc[mi][ni], ah[mi], &bb[ni >> 1][(ni & 1) * 2]);
        }
        if (kt + 2 < NT) fill(kt + 2, (kt + 2) % 3);
        else asm volatile("cp.async.commit_group;" ::: "memory");
    }

    // epilogue
    #pragma unroll
    for (int mi = 0; mi < 4; mi++) {
        int row0 = bm + wm + mi * 16 + lr;
        #pragma unroll
        for (int ni = 0; ni < 4; ni++) {
            int col0 = bn + wn + ni * 8 + (lc << 1);
            float b0 = bias[col0], b1 = bias[col0 + 1];
            #pragma unroll
            for (int half = 0; half < 2; half++) {
                int row = row0 + half * 8;
                float v0 = acc[mi][ni][half * 2 + 0] + b0;
                float v1 = acc[mi][ni][half * 2 + 1] + b1;
                if (GELU_) {
                    v0 = 0.5f * v0 * (1.0f + erff(v0 * 0.70710678118654752f));
                    v1 = 0.5f * v1 * (1.0f + erff(v1 * 0.70710678118654752f));
                }
                if (RES_) {
                    float2 r2 = *(const float2*)(R + (size_t)row * N + col0);
                    v0 += r2.x; v1 += r2.y;
                }
                size_t off = (size_t)row * N + col0;
                if (OUTM_ == 2) {
                    *(uint32_t*)(Ch + off) = pack2h(v0, v1);
                } else {
                    *(float2*)(C + off) = make_float2(v0, v1);
                }
            }
        }
    }
}

// ---------------------------------------------------------------------------
// Fused flash attention, pure fp16 MMA, packed QKV input.
// Grid (13, 96), 128 threads = 4 warps; warp w owns q-rows s0+16w..+15.
// K and V both stored [t][d] in smem (64 rows x 144B); V B-fragments via
// ldmatrix.x4.trans. 3 stages, single sync per tile.
// ---------------------------------------------------------------------------
#define FST    36
#define FARR   (64*FST)
#define FSTAGE (2*FARR*4)          // 18432
#define FSMEM  (3*FSTAGE)          // 55296
#define NTT    ((CS + 63) / 64)    // 13

__global__ void __launch_bounds__(128, 2) flash_attn(
    const __half* __restrict__ qkv, __half* __restrict__ ctxh)
{
    extern __shared__ uint32_t fs[];
    int tid = threadIdx.x, lane = tid & 31, w = tid >> 5;
    int lr = lane >> 2, lc = lane & 3;
    int bh = blockIdx.y, b = bh / CH, h = bh % CH;
    int s0 = blockIdx.x * 64;
    uint32_t sb = smem_u32(fs);

    // Q A-fragments in registers (from packed qkv, q section)
    uint32_t qf[4][4];
    {
        int r0 = min(s0 + w * 16 + lr, CS - 1);
        int r1 = min(s0 + w * 16 + lr + 8, CS - 1);
        const __half* q0 = qkv + ((size_t)b * CS + r0) * QKVD + h * CHD + 2 * lc;
        const __half* q1 = qkv + ((size_t)b * CS + r1) * QKVD + h * CHD + 2 * lc;
        #pragma unroll
        for (int kf = 0; kf < 4; kf++) {
            qf[kf][0] = *(const uint32_t*)(q0 + kf * 16);
            qf[kf][1] = *(const uint32_t*)(q1 + kf * 16);
            qf[kf][2] = *(const uint32_t*)(q0 + kf * 16 + 8);
            qf[kf][3] = *(const uint32_t*)(q1 + kf * 16 + 8);
        }
    }

    auto fill = [&](int tt, int st) {
        int t0 = tt * 64;
        uint32_t base = sb + st * FSTAGE;
        #pragma unroll
        for (int i = 0; i < 8; i++) {
            int idx = tid + 128 * i;
            int arr = idx >> 9;                   // 0:K 1:V
            int c = idx & 511;
            int row = c >> 3, ch = c & 7;
            int t = min(t0 + row, CS - 1);
            const __half* src = qkv + ((size_t)b * CS + t) * QKVD
                              + (arr == 0 ? CD : 2 * CD) + h * CHD + ch * 8;
            uint32_t dst = base + arr * (FARR * 4) + row * (FST * 4) + ch * 16;
            CP16(dst, src);
        }
        asm volatile("cp.async.commit_group;" ::: "memory");
    };

    float m0 = -1e30f, m1 = -1e30f, l0 = 0.0f, l1 = 0.0f;
    float o[8][4];
    #pragma unroll
    for (int nj = 0; nj < 8; nj++)
        #pragma unroll
        for (int e = 0; e < 4; e++) o[nj][e] = 0.0f;

    fill(0, 0);
    fill(1, 1);

    for (int tt = 0; tt < NTT; tt++) {
        int st = tt % 3;
        asm volatile("cp.async.wait_group 1;" ::: "memory");
        __syncthreads();

        const uint32_t* KH = fs + st * (FSTAGE / 4);
        const uint32_t  VB = sb + st * FSTAGE + FARR * 4;   // V array byte base

        // S = Q K^T (K smem [t][d]; direct B-frag loads)
        float s[8][4];
        #pragma unroll
        for (int nj = 0; nj < 8; nj++) {
            s[nj][0] = s[nj][1] = s[nj][2] = s[nj][3] = 0.0f;
            int cb = (nj * 8 + lr) * FST;
            #pragma unroll
            for (int kf = 0; kf < 4; kf++) {
                uint32_t bh_[2] = { KH[cb + kf * 8 + lc], KH[cb + kf * 8 + lc + 4] };
                mma16f(s[nj], qf[kf], bh_);
            }
        }

        // scale + mask
        bool last = (tt == NTT - 1);
        #pragma unroll
        for (int nj = 0; nj < 8; nj++) {
            if (last && nj >= 2) {
                s[nj][0] = s[nj][1] = s[nj][2] = s[nj][3] = -1e30f;
            } else {
                s[nj][0] *= 0.125f; s[nj][1] *= 0.125f;
                s[nj][2] *= 0.125f; s[nj][3] *= 0.125f;
            }
        }

        // online softmax
        float tm0 = -1e30f, tm1 = -1e30f;
        #pragma unroll
        for (int nj = 0; nj < 8; nj++) {
            tm0 = fmaxf(tm0, fmaxf(s[nj][0], s[nj][1]));
            tm1 = fmaxf(tm1, fmaxf(s[nj][2], s[nj][3]));
        }
        tm0 = fmaxf(tm0, __shfl_xor_sync(0xffffffffu, tm0, 1));
        tm0 = fmaxf(tm0, __shfl_xor_sync(0xffffffffu, tm0, 2));
        tm1 = fmaxf(tm1, __shfl_xor_sync(0xffffffffu, tm1, 1));
        tm1 = fmaxf(tm1, __shfl_xor_sync(0xffffffffu, tm1, 2));
        float mn0 = fmaxf(m0, tm0), mn1 = fmaxf(m1, tm1);
        float a0 = __expf(m0 - mn0), a1 = __expf(m1 - mn1);
        m0 = mn0; m1 = mn1;

        float rs0 = 0.0f, rs1 = 0.0f;
        #pragma unroll
        for (int nj = 0; nj < 8; nj++) {
            s[nj][0] = __expf(s[nj][0] - mn0);
            s[nj][1] = __expf(s[nj][1] - mn0);
            s[nj][2] = __expf(s[nj][2] - mn1);
            s[nj][3] = __expf(s[nj][3] - mn1);
            rs0 += s[nj][0] + s[nj][1];
            rs1 += s[nj][2] + s[nj][3];
        }
        rs0 += __shfl_xor_sync(0xffffffffu, rs0, 1);
        rs0 += __shfl_xor_sync(0xffffffffu, rs0, 2);
        rs1 += __shfl_xor_sync(0xffffffffu, rs1, 1);
        rs1 += __shfl_xor_sync(0xffffffffu, rs1, 2);
        l0 = l0 * a0 + rs0;
        l1 = l1 * a1 + rs1;

        #pragma unroll
        for (int nj = 0; nj < 8; nj++) {
            o[nj][0] *= a0; o[nj][1] *= a0;
            o[nj][2] *= a1; o[nj][3] *= a1;
        }

        // pack P -> fp16 A-fragments
        uint32_t ph[4][4];
        #pragma unroll
        for (int kf = 0; kf < 4; kf++) {
            int nj0 = 2 * kf, nj1 = 2 * kf + 1;
            ph[kf][0] = pack2h(s[nj0][0], s[nj0][1]);
            ph[kf][1] = pack2h(s[nj0][2], s[nj0][3]);
            ph[kf][2] = pack2h(s[nj1][0], s[nj1][1]);
            ph[kf][3] = pack2h(s[nj1][2], s[nj1][3]);
        }

        // O += P V : V smem [t][d], B-frags via ldmatrix.trans
        // addr(lane) = VB + (kf*16 + (lane&15))*144 + (njp*16 + (lane>>4)*8)*2
        #pragma unroll
        for (int kf = 0; kf < 4; kf++) {
            uint32_t vr[4][4];
            uint32_t rowa = VB + (kf * 16 + (lane & 15)) * 144 + (lane >> 4) * 16;
            #pragma unroll
            for (int njp = 0; njp < 4; njp++)
                LDMX4T(vr[njp], rowa + njp * 32);
            #pragma unroll
            for (int njp = 0; njp < 4; njp++) {
                mma16f(o[2 * njp],     ph[kf], &vr[njp][0]);
                mma16f(o[2 * njp + 1], ph[kf], &vr[njp][2]);
            }
        }

        if (tt + 2 < NTT) fill(tt + 2, (tt + 2) % 3);
        else asm volatile("cp.async.commit_group;" ::: "memory");
    }

    // epilogue: normalize, write ctx fp16
    float i0 = 1.0f / l0, i1 = 1.0f / l1;
    int r0 = s0 + w * 16 + lr, r1 = r0 + 8;
    #pragma unroll
    for (int nj = 0; nj < 8; nj++) {
        int col = h * CHD + nj * 8 + 2 * lc;
        if (r0 < CS) {
            size_t off = ((size_t)b * CS + r0) * CD + col;
            *(uint32_t*)(ctxh + off) = pack2h(o[nj][0] * i0, o[nj][1] * i0);
        }
        if (r1 < CS) {
            size_t off = ((size_t)b * CS + r1) * CD + col;
            *(uint32_t*)(ctxh + off) = pack2h(o[nj][2] * i1, o[nj][3] * i1);
        }
    }
}

// ---------------------------------------------------------------------------
// Orchestration
// ---------------------------------------------------------------------------
extern "C" void kernel_launch(void* const* d_in, const int* in_sizes, int n_in,
                              void* d_out, int out_size)
{
    (void)in_sizes; (void)n_in; (void)out_size;

    const float* x     = (const float*)d_in[0];
    const float* ln1_s = (const float*)d_in[1];
    const float* ln1_b = (const float*)d_in[2];
    const float* wq    = (const float*)d_in[3];
    const float* bq    = (const float*)d_in[4];
    const float* wk    = (const float*)d_in[5];
    const float* bk    = (const float*)d_in[6];
    const float* wv    = (const float*)d_in[7];
    const float* bv    = (const float*)d_in[8];
    const float* wo    = (const float*)d_in[9];
    const float* bo    = (const float*)d_in[10];
    const float* ln2_s = (const float*)d_in[11];
    const float* ln2_b = (const float*)d_in[12];
    const float* w1    = (const float*)d_in[13];
    const float* b1    = (const float*)d_in[14];
    const float* w2    = (const float*)d_in[15];
    const float* b2    = (const float*)d_in[16];
    const float* lnf_s = (const float*)d_in[17];
    const float* lnf_b = (const float*)d_in[18];

    float *h, *bqkv;
    cudaGetSymbolAddress((void**)&h,    g_h);
    cudaGetSymbolAddress((void**)&bqkv, g_bqkv);

    __half *yh, *qkv, *ctxh, *mlph;
    cudaGetSymbolAddress((void**)&yh,   g_yh);
    cudaGetSymbolAddress((void**)&qkv,  g_qkv);
    cudaGetSymbolAddress((void**)&ctxh, g_ctxh);
    cudaGetSymbolAddress((void**)&mlph, g_mlph);

    __half *wqkvt, *wot, *w1t, *w2t;
    cudaGetSymbolAddress((void**)&wqkvt, g_wqkvt);
    cudaGetSymbolAddress((void**)&wot,  g_wot);
    cudaGetSymbolAddress((void**)&w1t,  g_w1t);
    cudaGetSymbolAddress((void**)&w2t,  g_w2t);

    cudaFuncSetAttribute(gemm_fp16<0,0,0>, cudaFuncAttributeMaxDynamicSharedMemorySize, GSMEM3);
    cudaFuncSetAttribute(gemm_fp16<0,0,2>, cudaFuncAttributeMaxDynamicSharedMemorySize, GSMEM3);
    cudaFuncSetAttribute(gemm_fp16<0,1,0>, cudaFuncAttributeMaxDynamicSharedMemorySize, GSMEM3);
    cudaFuncSetAttribute(gemm_fp16<1,0,2>, cudaFuncAttributeMaxDynamicSharedMemorySize, GSMEM3);
    cudaFuncSetAttribute(flash_attn, cudaFuncAttributeMaxDynamicSharedMemorySize, FSMEM);

    dim3 blk(256), blk128(128);

    // weight prep: q|k|v packed into [L][2304][768]
    splitT_kernel<<<dim3(CD/32, CD/32, CL), blk>>>(
        wq, wqkvt,                     CD, CD, (size_t)QKVD * CD);
    splitT_kernel<<<dim3(CD/32, CD/32, CL), blk>>>(
        wk, wqkvt + (size_t)CD * CD,   CD, CD, (size_t)QKVD * CD);
    splitT_kernel<<<dim3(CD/32, CD/32, CL), blk>>>(
        wv, wqkvt + (size_t)2 * CD * CD, CD, CD, (size_t)QKVD * CD);
    splitT_kernel<<<dim3(CD/32, CD/32, CL), blk>>>(
        wo, wot, CD, CD, (size_t)CD * CD);
    splitT_kernel<<<dim3(CF/32, CD/32, CL), blk>>>(
        w1, w1t, CD, CF, (size_t)CD * CF);
    splitT_kernel<<<dim3(CD/32, CF/32, CL), blk>>>(
        w2, w2t, CF, CD, (size_t)CD * CF);
    pack_bias_kernel<<<CL, blk>>>(bq, bk, bv, bqkv);

    cudaMemcpyAsync(h, x, (size_t)CBS * CD * sizeof(float),
                    cudaMemcpyDeviceToDevice);

    dim3 gqkv(QKVD / 128, CBS / 128);   // (18, 49)
    dim3 gp768(CD / 128, CBS / 128);    // (6, 49)
    dim3 gp3072(CF / 128, CBS / 128);   // (24, 49)
    dim3 gfa(NTT, CB * CH);             // (13, 96)

    for (int l = 0; l < CL; l++) {
        size_t woQ  = (size_t)l * QKVD * CD;
        size_t wo768 = (size_t)l * CD * CD;
        size_t woF   = (size_t)l * CD * CF;
        ln_h_kernel<<<CBS, blk>>>(h, yh, ln1_s + l * CD, ln1_b + l * CD);
        gemm_fp16<0,0,2><<<gqkv, blk, GSMEM3>>>(
            yh, wqkvt + woQ, bqkv + l * QKVD, nullptr, nullptr, qkv, QKVD, CD);
        flash_attn<<<gfa, blk128, FSMEM>>>(qkv, ctxh);
        gemm_fp16<0,1,0><<<gp768, blk, GSMEM3>>>(
            ctxh, wot + wo768, bo + l * CD, h, h, nullptr, CD, CD);
        ln_h_kernel<<<CBS, blk>>>(h, yh, ln2_s + l * CD, ln2_b + l * CD);
        gemm_fp16<1,0,2><<<gp3072, blk, GSMEM3>>>(
            yh, w1t + woF, b1 + l * CF, nullptr, nullptr, mlph, CF, CD);
        gemm_fp16<0,1,0><<<gp768, blk, GSMEM3>>>(
            mlph, w2t + woF, b2 + l * CD, h, h, nullptr, CD, CF);
    }
    ln_kernel<<<CBS, blk>>>(h, (float*)d_out, lnf_s, lnf_b);
}

// round 12
// speedup vs baseline: 7.6813x; 1.0028x over previous
#include <cuda_runtime.h>
#include <cuda_fp16.h>
#include <math.h>
#include <stdint.h>

// Problem constants
#define CL   12
#define CD   768
#define CH   12
#define CF   3072
#define CB   8
#define CS   784
#define CHD  64
#define CBS  (CB*CS)          // 6272 rows
#define CEPS 1e-6f
#define QKVD 2304             // packed q|k|v row width

// ---------------------------------------------------------------------------
// Scratch (device globals; no allocations allowed)
// ---------------------------------------------------------------------------
__device__ float g_h [CBS*CD];

__device__ __half g_yh  [CBS*CD];
__device__ __half g_qkv [(size_t)CBS*QKVD];
__device__ __half g_ctxh[CBS*CD];
__device__ __half g_mlph[(size_t)CBS*CF];

// transposed fp16 weights: qkv packed [L][2304][768]; others [L][N][K]
__device__ __half g_wqkvt[(size_t)CL*QKVD*CD];
__device__ __half g_wot[CL*CD*CD];
__device__ __half g_w1t[(size_t)CL*CD*CF];
__device__ __half g_w2t[(size_t)CL*CD*CF];
__device__ float  g_bqkv[CL*QKVD];

// ---------------------------------------------------------------------------
// helpers
// ---------------------------------------------------------------------------
__device__ __forceinline__ uint32_t smem_u32(const void* p) {
    return (uint32_t)__cvta_generic_to_shared(p);
}
__device__ __forceinline__ uint32_t pack2h(float a, float b) {
    __half2 t = __floats2half2_rn(a, b);
    return *reinterpret_cast<uint32_t*>(&t);
}

__device__ __forceinline__ void mma16f(float* c, const uint32_t* a, const uint32_t* b) {
    asm("mma.sync.aligned.m16n8k16.row.col.f32.f16.f16.f32 "
        "{%0,%1,%2,%3},{%4,%5,%6,%7},{%8,%9},{%0,%1,%2,%3};"
        : "+f"(c[0]), "+f"(c[1]), "+f"(c[2]), "+f"(c[3])
        : "r"(a[0]), "r"(a[1]), "r"(a[2]), "r"(a[3]), "r"(b[0]), "r"(b[1]));
}

#define CP16(dst, src) \
    asm volatile("cp.async.cg.shared.global [%0], [%1], 16;" \
                 :: "r"(dst), "l"(src) : "memory")

#define LDMX4(r, addr) \
    asm volatile("ldmatrix.sync.aligned.m8n8.x4.shared.b16 {%0,%1,%2,%3}, [%4];" \
                 : "=r"((r)[0]), "=r"((r)[1]), "=r"((r)[2]), "=r"((r)[3]) \
                 : "r"(addr))

#define LDMX4T(r, addr) \
    asm volatile("ldmatrix.sync.aligned.m8n8.x4.trans.shared.b16 {%0,%1,%2,%3}, [%4];" \
                 : "=r"((r)[0]), "=r"((r)[1]), "=r"((r)[2]), "=r"((r)[3]) \
                 : "r"(addr))

#define EX2H2(out, in) \
    asm("ex2.approx.f16x2 %0, %1;" : "=r"(out) : "r"(in))

// ---------------------------------------------------------------------------
// Block reduction (256 threads)
// ---------------------------------------------------------------------------
__device__ __forceinline__ float bsum(float v) {
    __shared__ float red[32];
    #pragma unroll
    for (int o = 16; o; o >>= 1) v += __shfl_xor_sync(0xffffffffu, v, o);
    if ((threadIdx.x & 31) == 0) red[threadIdx.x >> 5] = v;
    __syncthreads();
    float t = (threadIdx.x < (blockDim.x >> 5)) ? red[threadIdx.x] : 0.0f;
    if (threadIdx.x < 32) {
        #pragma unroll
        for (int o = 16; o; o >>= 1) t += __shfl_xor_sync(0xffffffffu, t, o);
        if (threadIdx.x == 0) red[0] = t;
    }
    __syncthreads();
    float r = red[0];
    __syncthreads();
    return r;
}

// ---------------------------------------------------------------------------
// Weight prep: transpose + fp16. W:[L][K][N] -> T:[L*ls_out + n*K + k]
// 64(k) x 32(n) tiles; half2 coalesced stores (128B per warp).
// ---------------------------------------------------------------------------
__global__ void __launch_bounds__(256) splitT_kernel(
    const float* __restrict__ W, __half* __restrict__ Th,
    int K, int N, size_t ls_out)
{
    __shared__ float t[64][33];
    const float* Wl = W + (size_t)blockIdx.z * K * N;
    __half* Thl = Th + (size_t)blockIdx.z * ls_out;
    int n0 = blockIdx.x * 32, k0 = blockIdx.y * 64;
    int tid = threadIdx.x, lane = tid & 31, w = tid >> 5;

    #pragma unroll
    for (int i = 0; i < 2; i++) {
        int idx = tid + 256 * i;          // 0..511
        int row = idx >> 3;               // k row 0..63
        int c4  = (idx & 7) << 2;         // n 0..28
        float4 v = *(const float4*)(Wl + (size_t)(k0 + row) * N + n0 + c4);
        t[row][c4 + 0] = v.x; t[row][c4 + 1] = v.y;
        t[row][c4 + 2] = v.z; t[row][c4 + 3] = v.w;
    }
    __syncthreads();

    #pragma unroll
    for (int pass = 0; pass < 4; pass++) {
        int n = w + pass * 8;             // 0..31
        uint32_t p = pack2h(t[2 * lane][n], t[2 * lane + 1][n]);
        *(uint32_t*)(Thl + (size_t)(n0 + n) * K + k0 + 2 * lane) = p;
    }
}

// pack qkv biases: [L][2304] = bq | bk | bv
__global__ void __launch_bounds__(256) pack_bias_kernel(
    const float* __restrict__ bq, const float* __restrict__ bk,
    const float* __restrict__ bv, float* __restrict__ out)
{
    int l = blockIdx.x;
    for (int i = threadIdx.x; i < QKVD; i += 256) {
        float v = (i < CD) ? bq[l * CD + i]
                : (i < 2 * CD) ? bk[l * CD + i - CD]
                : bv[l * CD + i - 2 * CD];
        out[l * QKVD + i] = v;
    }
}

// ---------------------------------------------------------------------------
// LayerNorm -> fp32 out (final)
// ---------------------------------------------------------------------------
__global__ void __launch_bounds__(256) ln_kernel(
    const float* __restrict__ in, float* __restrict__ out,
    const float* __restrict__ gs, const float* __restrict__ gb)
{
    int tid = threadIdx.x;
    const float* x = in  + (size_t)blockIdx.x * CD;
    float*       o = out + (size_t)blockIdx.x * CD;
    float v0 = x[tid], v1 = x[tid + 256], v2 = x[tid + 512];
    float mean = bsum(v0 + v1 + v2) * (1.0f / CD);
    float c0 = v0 - mean, c1 = v1 - mean, c2 = v2 - mean;
    float var = bsum(c0*c0 + c1*c1 + c2*c2) * (1.0f / CD);
    float r = rsqrtf(var + CEPS);
    o[tid]       = c0 * r * gs[tid]       + gb[tid];
    o[tid + 256] = c1 * r * gs[tid + 256] + gb[tid + 256];
    o[tid + 512] = c2 * r * gs[tid + 512] + gb[tid + 512];
}

// LayerNorm -> fp16
__global__ void __launch_bounds__(256) ln_h_kernel(
    const float* __restrict__ in, __half* __restrict__ oh,
    const float* __restrict__ gs, const float* __restrict__ gb)
{
    int tid = threadIdx.x;
    const float* x = in + (size_t)blockIdx.x * CD;
    size_t ob = (size_t)blockIdx.x * CD;
    float v0 = x[tid], v1 = x[tid + 256], v2 = x[tid + 512];
    float mean = bsum(v0 + v1 + v2) * (1.0f / CD);
    float c0 = v0 - mean, c1 = v1 - mean, c2 = v2 - mean;
    float var = bsum(c0*c0 + c1*c1 + c2*c2) * (1.0f / CD);
    float r = rsqrtf(var + CEPS);
    oh[ob + tid]       = __float2half_rn(c0 * r * gs[tid]       + gb[tid]);
    oh[ob + tid + 256] = __float2half_rn(c1 * r * gs[tid + 256] + gb[tid + 256]);
    oh[ob + tid + 512] = __float2half_rn(c2 * r * gs[tid + 512] + gb[tid + 512]);
}

// ---------------------------------------------------------------------------
// fp16 GEMM (unchanged from R11): C = A @ B^T (+bias/gelu/res).
// 128x128 CTA tile, KT=64, 8 warps, 3-stage cp.async, 2 CTAs/SM.
// ---------------------------------------------------------------------------
#define GST    36864
#define GSMEM3 (3*GST)

template<int GELU_, int RES_, int OUTM_>
__global__ void __launch_bounds__(256, 2) gemm_fp16(
    const __half* __restrict__ Ah, const __half* __restrict__ Bh,
    const float* __restrict__ bias, const float* __restrict__ R,
    float* __restrict__ C, __half* __restrict__ Ch,
    int N, int K)
{
    extern __shared__ char smem[];
    const int tid = threadIdx.x, lane = tid & 31, wid = tid >> 5;
    const int bm = blockIdx.y * 128, bn = blockIdx.x * 128;
    const int wm = (wid >> 2) * 64, wn = (wid & 3) * 32;
    const int lr = lane >> 2, lc = lane & 3;
    const uint32_t sb = smem_u32(smem);

    const uint32_t a_off = (uint32_t)((wm + (lane & 15)) * 144 + (lane >> 4) * 16);
    const uint32_t b_off = (uint32_t)(18432 +
        (wn + ((lane >> 4) & 1) * 8 + (lane & 7)) * 144 + ((lane >> 3) & 1) * 16);

    auto fill = [&](int kt, int s) {
        int k0 = kt << 6;
        uint32_t stg = sb + s * GST;
        #pragma unroll
        for (int i = 0; i < 8; i++) {
            int idx = tid + 256 * i;
            int arr = idx >> 10;
            int c = idx & 1023;
            int row = c >> 3, ch = c & 7;
            const __half* g = (arr == 0) ? Ah : Bh;
            int rb = (arr == 0) ? bm : bn;
            const __half* src = g + (size_t)(rb + row) * K + k0 + ch * 8;
            uint32_t dst = stg + arr * 18432 + row * 144 + ch * 16;
            CP16(dst, src);
        }
        asm volatile("cp.async.commit_group;" ::: "memory");
    };

    float acc[4][4][4];
    #pragma unroll
    for (int mi = 0; mi < 4; mi++)
        #pragma unroll
        for (int ni = 0; ni < 4; ni++)
            #pragma unroll
            for (int e = 0; e < 4; e++) acc[mi][ni][e] = 0.0f;

    int NT = K >> 6;
    fill(0, 0);
    fill(1, 1);

    for (int kt = 0; kt < NT; kt++) {
        int s = kt % 3;
        asm volatile("cp.async.wait_group 1;" ::: "memory");
        __syncthreads();
        uint32_t stg = sb + s * GST;

        #pragma unroll
        for (int ks = 0; ks < 4; ks++) {
            uint32_t kb = ks * 32;
            uint32_t ah[4][4], bb[2][4];
            #pragma unroll
            for (int mi = 0; mi < 4; mi++)
                LDMX4(ah[mi], stg + a_off + mi * (16 * 144) + kb);
            #pragma unroll
            for (int nj = 0; nj < 2; nj++)
                LDMX4(bb[nj], stg + b_off + nj * (16 * 144) + kb);
            #pragma unroll
            for (int mi = 0; mi < 4; mi++)
                #pragma unroll
                for (int ni = 0; ni < 4; ni++)
                    mma16f(acc[mi][ni], ah[mi], &bb[ni >> 1][(ni & 1) * 2]);
        }
        if (kt + 2 < NT) fill(kt + 2, (kt + 2) % 3);
        else asm volatile("cp.async.commit_group;" ::: "memory");
    }

    #pragma unroll
    for (int mi = 0; mi < 4; mi++) {
        int row0 = bm + wm + mi * 16 + lr;
        #pragma unroll
        for (int ni = 0; ni < 4; ni++) {
            int col0 = bn + wn + ni * 8 + (lc << 1);
            float b0 = bias[col0], b1 = bias[col0 + 1];
            #pragma unroll
            for (int half = 0; half < 2; half++) {
                int row = row0 + half * 8;
                float v0 = acc[mi][ni][half * 2 + 0] + b0;
                float v1 = acc[mi][ni][half * 2 + 1] + b1;
                if (GELU_) {
                    v0 = 0.5f * v0 * (1.0f + erff(v0 * 0.70710678118654752f));
                    v1 = 0.5f * v1 * (1.0f + erff(v1 * 0.70710678118654752f));
                }
                if (RES_) {
                    float2 r2 = *(const float2*)(R + (size_t)row * N + col0);
                    v0 += r2.x; v1 += r2.y;
                }
                size_t off = (size_t)row * N + col0;
                if (OUTM_ == 2) {
                    *(uint32_t*)(Ch + off) = pack2h(v0, v1);
                } else {
                    *(float2*)(C + off) = make_float2(v0, v1);
                }
            }
        }
    }
}

// ---------------------------------------------------------------------------
// Fused flash attention, fp16 MMA, ex2.f16x2 softmax, packed QKV input.
// Grid (7, 96), 256 threads = 8 warps; 128 q-rows per CTA, warp w owns
// q-rows s0+16w..+15. K/V tiles 64x64 [t][d]; V B-frags via ldmatrix.trans.
// 3 stages, single sync per tile.
// ---------------------------------------------------------------------------
#define FST    36
#define FARR   (64*FST)
#define FSTAGE (2*FARR*4)          // 18432
#define FSMEM  (3*FSTAGE)          // 55296
#define NTT    ((CS + 63) / 64)    // 13
#define NQB    ((CS + 127) / 128)  // 7

__global__ void __launch_bounds__(256, 2) flash_attn(
    const __half* __restrict__ qkv, __half* __restrict__ ctxh)
{
    extern __shared__ uint32_t fs[];
    int tid = threadIdx.x, lane = tid & 31, w = tid >> 5;
    int lr = lane >> 2, lc = lane & 3;
    int bh = blockIdx.y, b = bh / CH, h = bh % CH;
    int s0 = blockIdx.x * 128;
    uint32_t sb = smem_u32(fs);
    const float L2E = 1.4426950408889634f;

    // Q A-fragments in registers (q section of packed qkv)
    uint32_t qf[4][4];
    {
        int r0 = min(s0 + w * 16 + lr, CS - 1);
        int r1 = min(s0 + w * 16 + lr + 8, CS - 1);
        const __half* q0 = qkv + ((size_t)b * CS + r0) * QKVD + h * CHD + 2 * lc;
        const __half* q1 = qkv + ((size_t)b * CS + r1) * QKVD + h * CHD + 2 * lc;
        #pragma unroll
        for (int kf = 0; kf < 4; kf++) {
            qf[kf][0] = *(const uint32_t*)(q0 + kf * 16);
            qf[kf][1] = *(const uint32_t*)(q1 + kf * 16);
            qf[kf][2] = *(const uint32_t*)(q0 + kf * 16 + 8);
            qf[kf][3] = *(const uint32_t*)(q1 + kf * 16 + 8);
        }
    }

    auto fill = [&](int tt, int st) {
        int t0 = tt * 64;
        uint32_t base = sb + st * FSTAGE;
        #pragma unroll
        for (int i = 0; i < 4; i++) {
            int idx = tid + 256 * i;              // 0..1023
            int arr = idx >> 9;                   // 0:K 1:V
            int c = idx & 511;
            int row = c >> 3, ch = c & 7;
            int t = min(t0 + row, CS - 1);
            const __half* src = qkv + ((size_t)b * CS + t) * QKVD
                              + (arr == 0 ? CD : 2 * CD) + h * CHD + ch * 8;
            uint32_t dst = base + arr * (FARR * 4) + row * (FST * 4) + ch * 16;
            CP16(dst, src);
        }
        asm volatile("cp.async.commit_group;" ::: "memory");
    };

    float m0 = -1e30f, m1 = -1e30f, l0 = 0.0f, l1 = 0.0f;
    float o[8][4];
    #pragma unroll
    for (int nj = 0; nj < 8; nj++)
        #pragma unroll
        for (int e = 0; e < 4; e++) o[nj][e] = 0.0f;

    fill(0, 0);
    fill(1, 1);

    for (int tt = 0; tt < NTT; tt++) {
        int st = tt % 3;
        asm volatile("cp.async.wait_group 1;" ::: "memory");
        __syncthreads();

        const uint32_t* KH = fs + st * (FSTAGE / 4);
        const uint32_t  VB = sb + st * FSTAGE + FARR * 4;

        // S = Q K^T
        float s[8][4];
        #pragma unroll
        for (int nj = 0; nj < 8; nj++) {
            s[nj][0] = s[nj][1] = s[nj][2] = s[nj][3] = 0.0f;
            int cb = (nj * 8 + lr) * FST;
            #pragma unroll
            for (int kf = 0; kf < 4; kf++) {
                uint32_t bh_[2] = { KH[cb + kf * 8 + lc], KH[cb + kf * 8 + lc + 4] };
                mma16f(s[nj], qf[kf], bh_);
            }
        }

        // scale + mask
        bool last = (tt == NTT - 1);
        #pragma unroll
        for (int nj = 0; nj < 8; nj++) {
            if (last && nj >= 2) {
                s[nj][0] = s[nj][1] = s[nj][2] = s[nj][3] = -1e30f;
            } else {
                s[nj][0] *= 0.125f; s[nj][1] *= 0.125f;
                s[nj][2] *= 0.125f; s[nj][3] *= 0.125f;
            }
        }

        // online softmax maxes
        float tm0 = -1e30f, tm1 = -1e30f;
        #pragma unroll
        for (int nj = 0; nj < 8; nj++) {
            tm0 = fmaxf(tm0, fmaxf(s[nj][0], s[nj][1]));
            tm1 = fmaxf(tm1, fmaxf(s[nj][2], s[nj][3]));
        }
        tm0 = fmaxf(tm0, __shfl_xor_sync(0xffffffffu, tm0, 1));
        tm0 = fmaxf(tm0, __shfl_xor_sync(0xffffffffu, tm0, 2));
        tm1 = fmaxf(tm1, __shfl_xor_sync(0xffffffffu, tm1, 1));
        tm1 = fmaxf(tm1, __shfl_xor_sync(0xffffffffu, tm1, 2));
        float mn0 = fmaxf(m0, tm0), mn1 = fmaxf(m1, tm1);
        float a0 = __expf(m0 - mn0), a1 = __expf(m1 - mn1);
        m0 = mn0; m1 = mn1;

        // P = exp(S - m) via ex2.f16x2 -> fp16 A-fragments directly,
        // row sums from the same fp16 values (exactly consistent with PV).
        uint32_t ph[4][4];
        float rs0 = 0.0f, rs1 = 0.0f;
        #pragma unroll
        for (int kf = 0; kf < 4; kf++) {
            int nj0 = 2 * kf, nj1 = 2 * kf + 1;
            uint32_t u;
            u = pack2h((s[nj0][0] - mn0) * L2E, (s[nj0][1] - mn0) * L2E);
            EX2H2(ph[kf][0], u);
            u = pack2h((s[nj0][2] - mn1) * L2E, (s[nj0][3] - mn1) * L2E);
            EX2H2(ph[kf][1], u);
            u = pack2h((s[nj1][0] - mn0) * L2E, (s[nj1][1] - mn0) * L2E);
            EX2H2(ph[kf][2], u);
            u = pack2h((s[nj1][2] - mn1) * L2E, (s[nj1][3] - mn1) * L2E);
            EX2H2(ph[kf][3], u);
            float2 f;
            f = __half22float2(*(__half2*)&ph[kf][0]); rs0 += f.x + f.y;
            f = __half22float2(*(__half2*)&ph[kf][1]); rs1 += f.x + f.y;
            f = __half22float2(*(__half2*)&ph[kf][2]); rs0 += f.x + f.y;
            f = __half22float2(*(__half2*)&ph[kf][3]); rs1 += f.x + f.y;
        }
        rs0 += __shfl_xor_sync(0xffffffffu, rs0, 1);
        rs0 += __shfl_xor_sync(0xffffffffu, rs0, 2);
        rs1 += __shfl_xor_sync(0xffffffffu, rs1, 1);
        rs1 += __shfl_xor_sync(0xffffffffu, rs1, 2);
        l0 = l0 * a0 + rs0;
        l1 = l1 * a1 + rs1;

        #pragma unroll
        for (int nj = 0; nj < 8; nj++) {
            o[nj][0] *= a0; o[nj][1] *= a0;
            o[nj][2] *= a1; o[nj][3] *= a1;
        }

        // O += P V : V smem [t][d], B-frags via ldmatrix.trans
        #pragma unroll
        for (int kf = 0; kf < 4; kf++) {
            uint32_t vr[4][4];
            uint32_t rowa = VB + (kf * 16 + (lane & 15)) * 144 + (lane >> 4) * 16;
            #pragma unroll
            for (int njp = 0; njp < 4; njp++)
                LDMX4T(vr[njp], rowa + njp * 32);
            #pragma unroll
            for (int njp = 0; njp < 4; njp++) {
                mma16f(o[2 * njp],     ph[kf], &vr[njp][0]);
                mma16f(o[2 * njp + 1], ph[kf], &vr[njp][2]);
            }
        }

        if (tt + 2 < NTT) fill(tt + 2, (tt + 2) % 3);
        else asm volatile("cp.async.commit_group;" ::: "memory");
    }

    // epilogue: normalize, write ctx fp16
    float i0 = 1.0f / l0, i1 = 1.0f / l1;
    int r0 = s0 + w * 16 + lr, r1 = r0 + 8;
    #pragma unroll
    for (int nj = 0; nj < 8; nj++) {
        int col = h * CHD + nj * 8 + 2 * lc;
        if (r0 < CS) {
            size_t off = ((size_t)b * CS + r0) * CD + col;
            *(uint32_t*)(ctxh + off) = pack2h(o[nj][0] * i0, o[nj][1] * i0);
        }
        if (r1 < CS) {
            size_t off = ((size_t)b * CS + r1) * CD + col;
            *(uint32_t*)(ctxh + off) = pack2h(o[nj][2] * i1, o[nj][3] * i1);
        }
    }
}

// ---------------------------------------------------------------------------
// Orchestration
// ---------------------------------------------------------------------------
extern "C" void kernel_launch(void* const* d_in, const int* in_sizes, int n_in,
                              void* d_out, int out_size)
{
    (void)in_sizes; (void)n_in; (void)out_size;

    const float* x     = (const float*)d_in[0];
    const float* ln1_s = (const float*)d_in[1];
    const float* ln1_b = (const float*)d_in[2];
    const float* wq    = (const float*)d_in[3];
    const float* bq    = (const float*)d_in[4];
    const float* wk    = (const float*)d_in[5];
    const float* bk    = (const float*)d_in[6];
    const float* wv    = (const float*)d_in[7];
    const float* bv    = (const float*)d_in[8];
    const float* wo    = (const float*)d_in[9];
    const float* bo    = (const float*)d_in[10];
    const float* ln2_s = (const float*)d_in[11];
    const float* ln2_b = (const float*)d_in[12];
    const float* w1    = (const float*)d_in[13];
    const float* b1    = (const float*)d_in[14];
    const float* w2    = (const float*)d_in[15];
    const float* b2    = (const float*)d_in[16];
    const float* lnf_s = (const float*)d_in[17];
    const float* lnf_b = (const float*)d_in[18];

    float *h, *bqkv;
    cudaGetSymbolAddress((void**)&h,    g_h);
    cudaGetSymbolAddress((void**)&bqkv, g_bqkv);

    __half *yh, *qkv, *ctxh, *mlph;
    cudaGetSymbolAddress((void**)&yh,   g_yh);
    cudaGetSymbolAddress((void**)&qkv,  g_qkv);
    cudaGetSymbolAddress((void**)&ctxh, g_ctxh);
    cudaGetSymbolAddress((void**)&mlph, g_mlph);

    __half *wqkvt, *wot, *w1t, *w2t;
    cudaGetSymbolAddress((void**)&wqkvt, g_wqkvt);
    cudaGetSymbolAddress((void**)&wot,  g_wot);
    cudaGetSymbolAddress((void**)&w1t,  g_w1t);
    cudaGetSymbolAddress((void**)&w2t,  g_w2t);

    cudaFuncSetAttribute(gemm_fp16<0,0,0>, cudaFuncAttributeMaxDynamicSharedMemorySize, GSMEM3);
    cudaFuncSetAttribute(gemm_fp16<0,0,2>, cudaFuncAttributeMaxDynamicSharedMemorySize, GSMEM3);
    cudaFuncSetAttribute(gemm_fp16<0,1,0>, cudaFuncAttributeMaxDynamicSharedMemorySize, GSMEM3);
    cudaFuncSetAttribute(gemm_fp16<1,0,2>, cudaFuncAttributeMaxDynamicSharedMemorySize, GSMEM3);
    cudaFuncSetAttribute(flash_attn, cudaFuncAttributeMaxDynamicSharedMemorySize, FSMEM);

    dim3 blk(256);

    // weight prep: q|k|v packed into [L][2304][768]
    splitT_kernel<<<dim3(CD/32, CD/64, CL), blk>>>(
        wq, wqkvt,                       CD, CD, (size_t)QKVD * CD);
    splitT_kernel<<<dim3(CD/32, CD/64, CL), blk>>>(
        wk, wqkvt + (size_t)CD * CD,     CD, CD, (size_t)QKVD * CD);
    splitT_kernel<<<dim3(CD/32, CD/64, CL), blk>>>(
        wv, wqkvt + (size_t)2 * CD * CD, CD, CD, (size_t)QKVD * CD);
    splitT_kernel<<<dim3(CD/32, CD/64, CL), blk>>>(
        wo, wot, CD, CD, (size_t)CD * CD);
    splitT_kernel<<<dim3(CF/32, CD/64, CL), blk>>>(
        w1, w1t, CD, CF, (size_t)CD * CF);
    splitT_kernel<<<dim3(CD/32, CF/64, CL), blk>>>(
        w2, w2t, CF, CD, (size_t)CD * CF);
    pack_bias_kernel<<<CL, blk>>>(bq, bk, bv, bqkv);

    cudaMemcpyAsync(h, x, (size_t)CBS * CD * sizeof(float),
                    cudaMemcpyDeviceToDevice);

    dim3 gqkv(QKVD / 128, CBS / 128);   // (18, 49)
    dim3 gp768(CD / 128, CBS / 128);    // (6, 49)
    dim3 gp3072(CF / 128, CBS / 128);   // (24, 49)
    dim3 gfa(NQB, CB * CH);             // (7, 96)

    for (int l = 0; l < CL; l++) {
        size_t woQ   = (size_t)l * QKVD * CD;
        size_t wo768 = (size_t)l * CD * CD;
        size_t woF   = (size_t)l * CD * CF;
        ln_h_kernel<<<CBS, blk>>>(h, yh, ln1_s + l * CD, ln1_b + l * CD);
        gemm_fp16<0,0,2><<<gqkv, blk, GSMEM3>>>(
            yh, wqkvt + woQ, bqkv + l * QKVD, nullptr, nullptr, qkv, QKVD, CD);
        flash_attn<<<gfa, blk, FSMEM>>>(qkv, ctxh);
        gemm_fp16<0,1,0><<<gp768, blk, GSMEM3>>>(
            ctxh, wot + wo768, bo + l * CD, h, h, nullptr, CD, CD);
        ln_h_kernel<<<CBS, blk>>>(h, yh, ln2_s + l * CD, ln2_b + l * CD);
        gemm_fp16<1,0,2><<<gp3072, blk, GSMEM3>>>(
            yh, w1t + woF, b1 + l * CF, nullptr, nullptr, mlph, CF, CD);
        gemm_fp16<0,1,0><<<gp768, blk, GSMEM3>>>(
            mlph, w2t + woF, b2 + l * CD, h, h, nullptr, CD, CF);
    }
    ln_kernel<<<CBS, blk>>>(h, (float*)d_out, lnf_s, lnf_b);
}

// round 13
// speedup vs baseline: 7.7143x; 1.0043x over previous
#include <cuda_runtime.h>
#include <cuda_fp16.h>
#include <math.h>
#include <stdint.h>

// Problem constants
#define CL   12
#define CD   768
#define CH   12
#define CF   3072
#define CB   8
#define CS   784
#define CHD  64
#define CBS  (CB*CS)          // 6272 rows
#define CEPS 1e-6f
#define QKVD 2304             // packed q|k|v row width

// ---------------------------------------------------------------------------
// Scratch (device globals; no allocations allowed)
// ---------------------------------------------------------------------------
__device__ float g_h [CBS*CD];

__device__ __half g_yh  [CBS*CD];
__device__ __half g_qkv [(size_t)CBS*QKVD];
__device__ __half g_ctxh[CBS*CD];
__device__ __half g_mlph[(size_t)CBS*CF];

// transposed fp16 weights: qkv packed [L][2304][768]; others [L][N][K]
__device__ __half g_wqkvt[(size_t)CL*QKVD*CD];
__device__ __half g_wot[CL*CD*CD];
__device__ __half g_w1t[(size_t)CL*CD*CF];
__device__ __half g_w2t[(size_t)CL*CD*CF];
__device__ float  g_bqkv[CL*QKVD];

// ---------------------------------------------------------------------------
// helpers
// ---------------------------------------------------------------------------
__device__ __forceinline__ uint32_t smem_u32(const void* p) {
    return (uint32_t)__cvta_generic_to_shared(p);
}
__device__ __forceinline__ uint32_t pack2h(float a, float b) {
    __half2 t = __floats2half2_rn(a, b);
    return *reinterpret_cast<uint32_t*>(&t);
}

__device__ __forceinline__ void mma16f(float* c, const uint32_t* a, const uint32_t* b) {
    asm("mma.sync.aligned.m16n8k16.row.col.f32.f16.f16.f32 "
        "{%0,%1,%2,%3},{%4,%5,%6,%7},{%8,%9},{%0,%1,%2,%3};"
        : "+f"(c[0]), "+f"(c[1]), "+f"(c[2]), "+f"(c[3])
        : "r"(a[0]), "r"(a[1]), "r"(a[2]), "r"(a[3]), "r"(b[0]), "r"(b[1]));
}

#define CP16(dst, src) \
    asm volatile("cp.async.cg.shared.global [%0], [%1], 16;" \
                 :: "r"(dst), "l"(src) : "memory")

#define LDMX4(r, addr) \
    asm volatile("ldmatrix.sync.aligned.m8n8.x4.shared.b16 {%0,%1,%2,%3}, [%4];" \
                 : "=r"((r)[0]), "=r"((r)[1]), "=r"((r)[2]), "=r"((r)[3]) \
                 : "r"(addr))

#define LDMX4T(r, addr) \
    asm volatile("ldmatrix.sync.aligned.m8n8.x4.trans.shared.b16 {%0,%1,%2,%3}, [%4];" \
                 : "=r"((r)[0]), "=r"((r)[1]), "=r"((r)[2]), "=r"((r)[3]) \
                 : "r"(addr))

#define EX2H2(out, in) \
    asm("ex2.approx.f16x2 %0, %1;" : "=r"(out) : "r"(in))

// ---------------------------------------------------------------------------
// Block reduction (256 threads)
// ---------------------------------------------------------------------------
__device__ __forceinline__ float bsum(float v) {
    __shared__ float red[32];
    #pragma unroll
    for (int o = 16; o; o >>= 1) v += __shfl_xor_sync(0xffffffffu, v, o);
    if ((threadIdx.x & 31) == 0) red[threadIdx.x >> 5] = v;
    __syncthreads();
    float t = (threadIdx.x < (blockDim.x >> 5)) ? red[threadIdx.x] : 0.0f;
    if (threadIdx.x < 32) {
        #pragma unroll
        for (int o = 16; o; o >>= 1) t += __shfl_xor_sync(0xffffffffu, t, o);
        if (threadIdx.x == 0) red[0] = t;
    }
    __syncthreads();
    float r = red[0];
    __syncthreads();
    return r;
}

// ---------------------------------------------------------------------------
// Merged weight prep: one launch transposes+converts ALL weights.
// grid = (3456 tiles, 12 layers); tile = 64(k) x 32(n).
// Segments: [0,288) wq | [288,576) wk | [576,864) wv | [864,1152) wo
//           [1152,2304) w1 | [2304,3456) w2
// ---------------------------------------------------------------------------
__global__ void __launch_bounds__(256) prep_kernel(
    const float* __restrict__ wq, const float* __restrict__ wk,
    const float* __restrict__ wv, const float* __restrict__ wo,
    const float* __restrict__ w1, const float* __restrict__ w2,
    __half* __restrict__ wqkvt, __half* __restrict__ wot,
    __half* __restrict__ w1t,   __half* __restrict__ w2t)
{
    __shared__ float t[64][33];
    int l = blockIdx.y, tile = blockIdx.x;
    const float* W;
    __half* T;
    int K, N, n0, k0;

    if (tile < 1152) {                       // wq/wk/wv/wo: 768x768, 288 tiles each
        int seg = tile / 288, tt = tile % 288;
        K = CD; N = CD;
        n0 = (tt % 24) * 32; k0 = (tt / 24) * 64;
        if (seg < 3) {
            W = (seg == 0) ? wq : (seg == 1) ? wk : wv;
            W += (size_t)l * CD * CD;
            T = wqkvt + (size_t)l * QKVD * CD + (size_t)(seg * CD + n0) * CD + k0;
        } else {
            W = wo + (size_t)l * CD * CD;
            T = wot + (size_t)l * CD * CD + (size_t)n0 * CD + k0;
        }
    } else if (tile < 2304) {                // w1: K=768, N=3072
        int tt = tile - 1152;
        K = CD; N = CF;
        n0 = (tt % 96) * 32; k0 = (tt / 96) * 64;
        W = w1 + (size_t)l * CD * CF;
        T = w1t + (size_t)l * CD * CF + (size_t)n0 * CD + k0;
    } else {                                 // w2: K=3072, N=768
        int tt = tile - 2304;
        K = CF; N = CD;
        n0 = (tt % 24) * 32; k0 = (tt / 24) * 64;
        W = w2 + (size_t)l * CD * CF;
        T = w2t + (size_t)l * CD * CF + (size_t)n0 * CF + k0;
    }

    int tid = threadIdx.x, lane = tid & 31, w = tid >> 5;
    #pragma unroll
    for (int i = 0; i < 2; i++) {
        int idx = tid + 256 * i;
        int row = idx >> 3;                  // k row 0..63
        int c4  = (idx & 7) << 2;            // n 0..28
        float4 v = *(const float4*)(W + (size_t)(k0 + row) * N + n0 + c4);
        t[row][c4 + 0] = v.x; t[row][c4 + 1] = v.y;
        t[row][c4 + 2] = v.z; t[row][c4 + 3] = v.w;
    }
    __syncthreads();
    #pragma unroll
    for (int pass = 0; pass < 4; pass++) {
        int n = w + pass * 8;
        uint32_t p = pack2h(t[2 * lane][n], t[2 * lane + 1][n]);
        *(uint32_t*)(T + (size_t)n * K + 2 * lane) = p;
    }
}

// pack qkv biases: [L][2304] = bq | bk | bv
__global__ void __launch_bounds__(256) pack_bias_kernel(
    const float* __restrict__ bq, const float* __restrict__ bk,
    const float* __restrict__ bv, float* __restrict__ out)
{
    int l = blockIdx.x;
    for (int i = threadIdx.x; i < QKVD; i += 256) {
        float v = (i < CD) ? bq[l * CD + i]
                : (i < 2 * CD) ? bk[l * CD + i - CD]
                : bv[l * CD + i - 2 * CD];
        out[l * QKVD + i] = v;
    }
}

// ---------------------------------------------------------------------------
// LayerNorm -> fp32 out (final) — vectorized
// ---------------------------------------------------------------------------
__global__ void __launch_bounds__(256) ln_kernel(
    const float* __restrict__ in, float* __restrict__ out,
    const float* __restrict__ gs, const float* __restrict__ gb)
{
    int tid = threadIdx.x;
    const float4* x4 = (const float4*)(in + (size_t)blockIdx.x * CD);
    float4 v = make_float4(0.f, 0.f, 0.f, 0.f);
    if (tid < 192) v = x4[tid];
    float mean = bsum(v.x + v.y + v.z + v.w) * (1.0f / CD);
    float c0 = v.x - mean, c1 = v.y - mean, c2 = v.z - mean, c3 = v.w - mean;
    float sq = (tid < 192) ? (c0*c0 + c1*c1 + c2*c2 + c3*c3) : 0.0f;
    float var = bsum(sq) * (1.0f / CD);
    float r = rsqrtf(var + CEPS);
    if (tid < 192) {
        float4 g4 = ((const float4*)gs)[tid];
        float4 b4 = ((const float4*)gb)[tid];
        float4 o4 = make_float4(c0 * r * g4.x + b4.x, c1 * r * g4.y + b4.y,
                                c2 * r * g4.z + b4.z, c3 * r * g4.w + b4.w);
        ((float4*)(out + (size_t)blockIdx.x * CD))[tid] = o4;
    }
}

// LayerNorm -> fp16 — vectorized
__global__ void __launch_bounds__(256) ln_h_kernel(
    const float* __restrict__ in, __half* __restrict__ oh,
    const float* __restrict__ gs, const float* __restrict__ gb)
{
    int tid = threadIdx.x;
    const float4* x4 = (const float4*)(in + (size_t)blockIdx.x * CD);
    float4 v = make_float4(0.f, 0.f, 0.f, 0.f);
    if (tid < 192) v = x4[tid];
    float mean = bsum(v.x + v.y + v.z + v.w) * (1.0f / CD);
    float c0 = v.x - mean, c1 = v.y - mean, c2 = v.z - mean, c3 = v.w - mean;
    float sq = (tid < 192) ? (c0*c0 + c1*c1 + c2*c2 + c3*c3) : 0.0f;
    float var = bsum(sq) * (1.0f / CD);
    float r = rsqrtf(var + CEPS);
    if (tid < 192) {
        float4 g4 = ((const float4*)gs)[tid];
        float4 b4 = ((const float4*)gb)[tid];
        uint2 o2;
        o2.x = pack2h(c0 * r * g4.x + b4.x, c1 * r * g4.y + b4.y);
        o2.y = pack2h(c2 * r * g4.z + b4.z, c3 * r * g4.w + b4.w);
        ((uint2*)(oh + (size_t)blockIdx.x * CD))[tid] = o2;
    }
}

// ---------------------------------------------------------------------------
// fp16 GEMM (unchanged): C = A @ B^T (+bias/gelu/res).
// 128x128 CTA tile, KT=64, 8 warps, 3-stage cp.async, 2 CTAs/SM.
// ---------------------------------------------------------------------------
#define GST    36864
#define GSMEM3 (3*GST)

template<int GELU_, int RES_, int OUTM_>
__global__ void __launch_bounds__(256, 2) gemm_fp16(
    const __half* __restrict__ Ah, const __half* __restrict__ Bh,
    const float* __restrict__ bias, const float* __restrict__ R,
    float* __restrict__ C, __half* __restrict__ Ch,
    int N, int K)
{
    extern __shared__ char smem[];
    const int tid = threadIdx.x, lane = tid & 31, wid = tid >> 5;
    const int bm = blockIdx.y * 128, bn = blockIdx.x * 128;
    const int wm = (wid >> 2) * 64, wn = (wid & 3) * 32;
    const int lr = lane >> 2, lc = lane & 3;
    const uint32_t sb = smem_u32(smem);

    const uint32_t a_off = (uint32_t)((wm + (lane & 15)) * 144 + (lane >> 4) * 16);
    const uint32_t b_off = (uint32_t)(18432 +
        (wn + ((lane >> 4) & 1) * 8 + (lane & 7)) * 144 + ((lane >> 3) & 1) * 16);

    auto fill = [&](int kt, int s) {
        int k0 = kt << 6;
        uint32_t stg = sb + s * GST;
        #pragma unroll
        for (int i = 0; i < 8; i++) {
            int idx = tid + 256 * i;
            int arr = idx >> 10;
            int c = idx & 1023;
            int row = c >> 3, ch = c & 7;
            const __half* g = (arr == 0) ? Ah : Bh;
            int rb = (arr == 0) ? bm : bn;
            const __half* src = g + (size_t)(rb + row) * K + k0 + ch * 8;
            uint32_t dst = stg + arr * 18432 + row * 144 + ch * 16;
            CP16(dst, src);
        }
        asm volatile("cp.async.commit_group;" ::: "memory");
    };

    float acc[4][4][4];
    #pragma unroll
    for (int mi = 0; mi < 4; mi++)
        #pragma unroll
        for (int ni = 0; ni < 4; ni++)
            #pragma unroll
            for (int e = 0; e < 4; e++) acc[mi][ni][e] = 0.0f;

    int NT = K >> 6;
    fill(0, 0);
    fill(1, 1);

    for (int kt = 0; kt < NT; kt++) {
        int s = kt % 3;
        asm volatile("cp.async.wait_group 1;" ::: "memory");
        __syncthreads();
        uint32_t stg = sb + s * GST;

        #pragma unroll
        for (int ks = 0; ks < 4; ks++) {
            uint32_t kb = ks * 32;
            uint32_t ah[4][4], bb[2][4];
            #pragma unroll
            for (int mi = 0; mi < 4; mi++)
                LDMX4(ah[mi], stg + a_off + mi * (16 * 144) + kb);
            #pragma unroll
            for (int nj = 0; nj < 2; nj++)
                LDMX4(bb[nj], stg + b_off + nj * (16 * 144) + kb);
            #pragma unroll
            for (int mi = 0; mi < 4; mi++)
                #pragma unroll
                for (int ni = 0; ni < 4; ni++)
                    mma16f(acc[mi][ni], ah[mi], &bb[ni >> 1][(ni & 1) * 2]);
        }
        if (kt + 2 < NT) fill(kt + 2, (kt + 2) % 3);
        else asm volatile("cp.async.commit_group;" ::: "memory");
    }

    #pragma unroll
    for (int mi = 0; mi < 4; mi++) {
        int row0 = bm + wm + mi * 16 + lr;
        #pragma unroll
        for (int ni = 0; ni < 4; ni++) {
            int col0 = bn + wn + ni * 8 + (lc << 1);
            float b0 = bias[col0], b1 = bias[col0 + 1];
            #pragma unroll
            for (int half = 0; half < 2; half++) {
                int row = row0 + half * 8;
                float v0 = acc[mi][ni][half * 2 + 0] + b0;
                float v1 = acc[mi][ni][half * 2 + 1] + b1;
                if (GELU_) {
                    v0 = 0.5f * v0 * (1.0f + erff(v0 * 0.70710678118654752f));
                    v1 = 0.5f * v1 * (1.0f + erff(v1 * 0.70710678118654752f));
                }
                if (RES_) {
                    float2 r2 = *(const float2*)(R + (size_t)row * N + col0);
                    v0 += r2.x; v1 += r2.y;
                }
                size_t off = (size_t)row * N + col0;
                if (OUTM_ == 2) {
                    *(uint32_t*)(Ch + off) = pack2h(v0, v1);
                } else {
                    *(float2*)(C + off) = make_float2(v0, v1);
                }
            }
        }
    }
}

// ---------------------------------------------------------------------------
// Fused flash attention (unchanged from R12).
// ---------------------------------------------------------------------------
#define FST    36
#define FARR   (64*FST)
#define FSTAGE (2*FARR*4)          // 18432
#define FSMEM  (3*FSTAGE)          // 55296
#define NTT    ((CS + 63) / 64)    // 13
#define NQB    ((CS + 127) / 128)  // 7

__global__ void __launch_bounds__(256, 2) flash_attn(
    const __half* __restrict__ qkv, __half* __restrict__ ctxh)
{
    extern __shared__ uint32_t fs[];
    int tid = threadIdx.x, lane = tid & 31, w = tid >> 5;
    int lr = lane >> 2, lc = lane & 3;
    int bh = blockIdx.y, b = bh / CH, h = bh % CH;
    int s0 = blockIdx.x * 128;
    uint32_t sb = smem_u32(fs);
    const float L2E = 1.4426950408889634f;

    uint32_t qf[4][4];
    {
        int r0 = min(s0 + w * 16 + lr, CS - 1);
        int r1 = min(s0 + w * 16 + lr + 8, CS - 1);
        const __half* q0 = qkv + ((size_t)b * CS + r0) * QKVD + h * CHD + 2 * lc;
        const __half* q1 = qkv + ((size_t)b * CS + r1) * QKVD + h * CHD + 2 * lc;
        #pragma unroll
        for (int kf = 0; kf < 4; kf++) {
            qf[kf][0] = *(const uint32_t*)(q0 + kf * 16);
            qf[kf][1] = *(const uint32_t*)(q1 + kf * 16);
            qf[kf][2] = *(const uint32_t*)(q0 + kf * 16 + 8);
            qf[kf][3] = *(const uint32_t*)(q1 + kf * 16 + 8);
        }
    }

    auto fill = [&](int tt, int st) {
        int t0 = tt * 64;
        uint32_t base = sb + st * FSTAGE;
        #pragma unroll
        for (int i = 0; i < 4; i++) {
            int idx = tid + 256 * i;
            int arr = idx >> 9;
            int c = idx & 511;
            int row = c >> 3, ch = c & 7;
            int t = min(t0 + row, CS - 1);
            const __half* src = qkv + ((size_t)b * CS + t) * QKVD
                              + (arr == 0 ? CD : 2 * CD) + h * CHD + ch * 8;
            uint32_t dst = base + arr * (FARR * 4) + row * (FST * 4) + ch * 16;
            CP16(dst, src);
        }
        asm volatile("cp.async.commit_group;" ::: "memory");
    };

    float m0 = -1e30f, m1 = -1e30f, l0 = 0.0f, l1 = 0.0f;
    float o[8][4];
    #pragma unroll
    for (int nj = 0; nj < 8; nj++)
        #pragma unroll
        for (int e = 0; e < 4; e++) o[nj][e] = 0.0f;

    fill(0, 0);
    fill(1, 1);

    for (int tt = 0; tt < NTT; tt++) {
        int st = tt % 3;
        asm volatile("cp.async.wait_group 1;" ::: "memory");
        __syncthreads();

        const uint32_t* KH = fs + st * (FSTAGE / 4);
        const uint32_t  VB = sb + st * FSTAGE + FARR * 4;

        float s[8][4];
        #pragma unroll
        for (int nj = 0; nj < 8; nj++) {
            s[nj][0] = s[nj][1] = s[nj][2] = s[nj][3] = 0.0f;
            int cb = (nj * 8 + lr) * FST;
            #pragma unroll
            for (int kf = 0; kf < 4; kf++) {
                uint32_t bh_[2] = { KH[cb + kf * 8 + lc], KH[cb + kf * 8 + lc + 4] };
                mma16f(s[nj], qf[kf], bh_);
            }
        }

        bool last = (tt == NTT - 1);
        #pragma unroll
        for (int nj = 0; nj < 8; nj++) {
            if (last && nj >= 2) {
                s[nj][0] = s[nj][1] = s[nj][2] = s[nj][3] = -1e30f;
            } else {
                s[nj][0] *= 0.125f; s[nj][1] *= 0.125f;
                s[nj][2] *= 0.125f; s[nj][3] *= 0.125f;
            }
        }

        float tm0 = -1e30f, tm1 = -1e30f;
        #pragma unroll
        for (int nj = 0; nj < 8; nj++) {
            tm0 = fmaxf(tm0, fmaxf(s[nj][0], s[nj][1]));
            tm1 = fmaxf(tm1, fmaxf(s[nj][2], s[nj][3]));
        }
        tm0 = fmaxf(tm0, __shfl_xor_sync(0xffffffffu, tm0, 1));
        tm0 = fmaxf(tm0, __shfl_xor_sync(0xffffffffu, tm0, 2));
        tm1 = fmaxf(tm1, __shfl_xor_sync(0xffffffffu, tm1, 1));
        tm1 = fmaxf(tm1, __shfl_xor_sync(0xffffffffu, tm1, 2));
        float mn0 = fmaxf(m0, tm0), mn1 = fmaxf(m1, tm1);
        float a0 = __expf(m0 - mn0), a1 = __expf(m1 - mn1);
        m0 = mn0; m1 = mn1;

        uint32_t ph[4][4];
        float rs0 = 0.0f, rs1 = 0.0f;
        #pragma unroll
        for (int kf = 0; kf < 4; kf++) {
            int nj0 = 2 * kf, nj1 = 2 * kf + 1;
            uint32_t u;
            u = pack2h((s[nj0][0] - mn0) * L2E, (s[nj0][1] - mn0) * L2E);
            EX2H2(ph[kf][0], u);
            u = pack2h((s[nj0][2] - mn1) * L2E, (s[nj0][3] - mn1) * L2E);
            EX2H2(ph[kf][1], u);
            u = pack2h((s[nj1][0] - mn0) * L2E, (s[nj1][1] - mn0) * L2E);
            EX2H2(ph[kf][2], u);
            u = pack2h((s[nj1][2] - mn1) * L2E, (s[nj1][3] - mn1) * L2E);
            EX2H2(ph[kf][3], u);
            float2 f;
            f = __half22float2(*(__half2*)&ph[kf][0]); rs0 += f.x + f.y;
            f = __half22float2(*(__half2*)&ph[kf][1]); rs1 += f.x + f.y;
            f = __half22float2(*(__half2*)&ph[kf][2]); rs0 += f.x + f.y;
            f = __half22float2(*(__half2*)&ph[kf][3]); rs1 += f.x + f.y;
        }
        rs0 += __shfl_xor_sync(0xffffffffu, rs0, 1);
        rs0 += __shfl_xor_sync(0xffffffffu, rs0, 2);
        rs1 += __shfl_xor_sync(0xffffffffu, rs1, 1);
        rs1 += __shfl_xor_sync(0xffffffffu, rs1, 2);
        l0 = l0 * a0 + rs0;
        l1 = l1 * a1 + rs1;

        #pragma unroll
        for (int nj = 0; nj < 8; nj++) {
            o[nj][0] *= a0; o[nj][1] *= a0;
            o[nj][2] *= a1; o[nj][3] *= a1;
        }

        #pragma unroll
        for (int kf = 0; kf < 4; kf++) {
            uint32_t vr[4][4];
            uint32_t rowa = VB + (kf * 16 + (lane & 15)) * 144 + (lane >> 4) * 16;
            #pragma unroll
            for (int njp = 0; njp < 4; njp++)
                LDMX4T(vr[njp], rowa + njp * 32);
            #pragma unroll
            for (int njp = 0; njp < 4; njp++) {
                mma16f(o[2 * njp],     ph[kf], &vr[njp][0]);
                mma16f(o[2 * njp + 1], ph[kf], &vr[njp][2]);
            }
        }

        if (tt + 2 < NTT) fill(tt + 2, (tt + 2) % 3);
        else asm volatile("cp.async.commit_group;" ::: "memory");
    }

    float i0 = 1.0f / l0, i1 = 1.0f / l1;
    int r0 = s0 + w * 16 + lr, r1 = r0 + 8;
    #pragma unroll
    for (int nj = 0; nj < 8; nj++) {
        int col = h * CHD + nj * 8 + 2 * lc;
        if (r0 < CS) {
            size_t off = ((size_t)b * CS + r0) * CD + col;
            *(uint32_t*)(ctxh + off) = pack2h(o[nj][0] * i0, o[nj][1] * i0);
        }
        if (r1 < CS) {
            size_t off = ((size_t)b * CS + r1) * CD + col;
            *(uint32_t*)(ctxh + off) = pack2h(o[nj][2] * i1, o[nj][3] * i1);
        }
    }
}

// ---------------------------------------------------------------------------
// Orchestration
// ---------------------------------------------------------------------------
extern "C" void kernel_launch(void* const* d_in, const int* in_sizes, int n_in,
                              void* d_out, int out_size)
{
    (void)in_sizes; (void)n_in; (void)out_size;

    const float* x     = (const float*)d_in[0];
    const float* ln1_s = (const float*)d_in[1];
    const float* ln1_b = (const float*)d_in[2];
    const float* wq    = (const float*)d_in[3];
    const float* bq    = (const float*)d_in[4];
    const float* wk    = (const float*)d_in[5];
    const float* bk    = (const float*)d_in[6];
    const float* wv    = (const float*)d_in[7];
    const float* bv    = (const float*)d_in[8];
    const float* wo    = (const float*)d_in[9];
    const float* bo    = (const float*)d_in[10];
    const float* ln2_s = (const float*)d_in[11];
    const float* ln2_b = (const float*)d_in[12];
    const float* w1    = (const float*)d_in[13];
    const float* b1    = (const float*)d_in[14];
    const float* w2    = (const float*)d_in[15];
    const float* b2    = (const float*)d_in[16];
    const float* lnf_s = (const float*)d_in[17];
    const float* lnf_b = (const float*)d_in[18];

    float *h, *bqkv;
    cudaGetSymbolAddress((void**)&h,    g_h);
    cudaGetSymbolAddress((void**)&bqkv, g_bqkv);

    __half *yh, *qkv, *ctxh, *mlph;
    cudaGetSymbolAddress((void**)&yh,   g_yh);
    cudaGetSymbolAddress((void**)&qkv,  g_qkv);
    cudaGetSymbolAddress((void**)&ctxh, g_ctxh);
    cudaGetSymbolAddress((void**)&mlph, g_mlph);

    __half *wqkvt, *wot, *w1t, *w2t;
    cudaGetSymbolAddress((void**)&wqkvt, g_wqkvt);
    cudaGetSymbolAddress((void**)&wot,  g_wot);
    cudaGetSymbolAddress((void**)&w1t,  g_w1t);
    cudaGetSymbolAddress((void**)&w2t,  g_w2t);

    cudaFuncSetAttribute(gemm_fp16<0,0,0>, cudaFuncAttributeMaxDynamicSharedMemorySize, GSMEM3);
    cudaFuncSetAttribute(gemm_fp16<0,0,2>, cudaFuncAttributeMaxDynamicSharedMemorySize, GSMEM3);
    cudaFuncSetAttribute(gemm_fp16<0,1,0>, cudaFuncAttributeMaxDynamicSharedMemorySize, GSMEM3);
    cudaFuncSetAttribute(gemm_fp16<1,0,2>, cudaFuncAttributeMaxDynamicSharedMemorySize, GSMEM3);
    cudaFuncSetAttribute(flash_attn, cudaFuncAttributeMaxDynamicSharedMemorySize, FSMEM);

    dim3 blk(256);

    // single merged weight-prep launch + bias pack
    prep_kernel<<<dim3(3456, CL), blk>>>(wq, wk, wv, wo, w1, w2,
                                         wqkvt, wot, w1t, w2t);
    pack_bias_kernel<<<CL, blk>>>(bq, bk, bv, bqkv);

    cudaMemcpyAsync(h, x, (size_t)CBS * CD * sizeof(float),
                    cudaMemcpyDeviceToDevice);

    dim3 gqkv(QKVD / 128, CBS / 128);   // (18, 49)
    dim3 gp768(CD / 128, CBS / 128);    // (6, 49)
    dim3 gp3072(CF / 128, CBS / 128);   // (24, 49)
    dim3 gfa(NQB, CB * CH);             // (7, 96)

    for (int l = 0; l < CL; l++) {
        size_t woQ   = (size_t)l * QKVD * CD;
        size_t wo768 = (size_t)l * CD * CD;
        size_t woF   = (size_t)l * CD * CF;
        ln_h_kernel<<<CBS, blk>>>(h, yh, ln1_s + l * CD, ln1_b + l * CD);
        gemm_fp16<0,0,2><<<gqkv, blk, GSMEM3>>>(
            yh, wqkvt + woQ, bqkv + l * QKVD, nullptr, nullptr, qkv, QKVD, CD);
        flash_attn<<<gfa, blk, FSMEM>>>(qkv, ctxh);
        gemm_fp16<0,1,0><<<gp768, blk, GSMEM3>>>(
            ctxh, wot + wo768, bo + l * CD, h, h, nullptr, CD, CD);
        ln_h_kernel<<<CBS, blk>>>(h, yh, ln2_s + l * CD, ln2_b + l * CD);
        gemm_fp16<1,0,2><<<gp3072, blk, GSMEM3>>>(
            yh, w1t + woF, b1 + l * CF, nullptr, nullptr, mlph, CF, CD);
        gemm_fp16<0,1,0><<<gp768, blk, GSMEM3>>>(
            mlph, w2t + woF, b2 + l * CD, h, h, nullptr, CD, CF);
    }
    ln_kernel<<<CBS, blk>>>(h, (float*)d_out, lnf_s, lnf_b);
}